// round 9
// baseline (speedup 1.0000x reference)
#include <cuda_runtime.h>
#include <cuda_bf16.h>
#include <math.h>
#include <stdint.h>

// ---------------- problem constants ----------------
#define NNODES 5120
#define NEDGES 20000
#define BGR    128
#define MAXN   45
#define LPROT  512
#define DPROT  1280
#define NPROT  229
#define TROWS  (BGR*LPROT)   // 65536

typedef unsigned long long u64;

// ---------------- device scratch ----------------
__device__ float g_deg[NNODES];
__device__ float g_coef[NEDGES];
__device__ float g_xw[NNODES*256];
__device__ float g_hA[NNODES*128];
__device__ float g_hB[NNODES*128];
__device__ float g_h3[NNODES*256];
__device__ int   g_counts[BGR];
__device__ int   g_starts[BGR];
__device__ float g_dense[BGR*MAXN*256];
__device__ float g_fc1[BGR*MAXN*1024];
__device__ float g_hd[BGR*MAXN*128];
__device__ int   g_rowmap[TROWS];
__device__ float g_t1[TROWS*128];
__device__ float g_t[TROWS*128];
__device__ float g_tbw[(long)TROWS*256];   // [tb | WptT | pad]
__device__ float g_wcomb[128*256];
__device__ float g_cp[BGR*256];
__device__ float g_f1[BGR*1024];
__device__ float g_f2[BGR*512];
__device__ int g_Mdyn[1];
__device__ int g_bslot[BGR];

// ---------------- warp-MMA helpers (baseline PTX, sm_80+) ----------------
__device__ __forceinline__ unsigned su32(const void* p) {
    unsigned r;
    asm("{ .reg .u64 t; cvta.to.shared.u64 t, %1; cvt.u32.u64 %0, t; }" : "=r"(r) : "l"(p));
    return r;
}
__device__ __forceinline__ void ldsm4(unsigned* r, unsigned addr) {
    asm volatile("ldmatrix.sync.aligned.m8n8.x4.shared.b16 {%0,%1,%2,%3}, [%4];"
        : "=r"(r[0]), "=r"(r[1]), "=r"(r[2]), "=r"(r[3]) : "r"(addr));
}
__device__ __forceinline__ void ldsm2(unsigned* r, unsigned addr) {
    asm volatile("ldmatrix.sync.aligned.m8n8.x2.shared.b16 {%0,%1}, [%2];"
        : "=r"(r[0]), "=r"(r[1]) : "r"(addr));
}
__device__ __forceinline__ void mma16816(float* d, const unsigned* a, const unsigned* b) {
    asm volatile("mma.sync.aligned.m16n8k16.row.col.f32.bf16.bf16.f32 "
        "{%0,%1,%2,%3}, {%4,%5,%6,%7}, {%8,%9}, {%0,%1,%2,%3};"
        : "+f"(d[0]), "+f"(d[1]), "+f"(d[2]), "+f"(d[3])
        : "r"(a[0]), "r"(a[1]), "r"(a[2]), "r"(a[3]), "r"(b[0]), "r"(b[1]));
}
__device__ __forceinline__ unsigned bfpack(float a, float b) {
    __nv_bfloat162 h = __floats2bfloat162_rn(a, b);
    return *(unsigned*)&h;
}

// =================================================================
// bf16-split warp-MMA GEMM: C[M,N] = act(pre(gather(A))[M,K] @ B[K,N] + bias)
// Tile 128x128 per CTA (grid covers M,N), K%64==0, lda%4==0.
// 2-term split: D = Ah*Bh + Ah*Bl + Al*Bh (fp32 accum, rel err ~1e-6).
// smem: sAh/sAl/sBh/sBl each [128][72] bf16 (dynamic, 72KB).
// optional C2[m,n] = raw/deg[m] + bias2[n]  (GCN init path).
// =================================================================
#define GSTRIDE 72
#define GTILEB (128 * GSTRIDE * 2)   // 18432 bytes per array
#define GM_SMEM (4 * GTILEB)

__global__ __launch_bounds__(256) void gemm_mma(
    const float* __restrict__ A, int lda, const int* __restrict__ rowmap,
    const float* __restrict__ B, int ldb, const float* __restrict__ bias,
    float* __restrict__ C, int ldc, const int* __restrict__ Mdyn,
    int K, int act, int preRelu,
    float* __restrict__ C2, const float* __restrict__ degv,
    const float* __restrict__ bias2)
{
    const int m0 = blockIdx.y * 128;
    if (Mdyn && m0 >= *Mdyn) return;
    const int col0 = blockIdx.x * 128;
    const int tid = threadIdx.x;
    const int wid = tid >> 5, lane = tid & 31;
    const int warp_m = (wid >> 2) * 64;    // 0 or 64
    const int warp_n = (wid & 3) * 32;     // 0,32,64,96

    extern __shared__ char smraw[];
    char* sAh = smraw;
    char* sAl = smraw + GTILEB;
    char* sBh = smraw + 2 * GTILEB;
    char* sBl = smraw + 3 * GTILEB;
    const unsigned uAh = su32(sAh), uAl = su32(sAl);
    const unsigned uBh = su32(sBh), uBl = su32(sBl);

    // A conversion descriptors: 8 chunks of (m, q) with q = 4-elem offset
    const float* arow[8];
    int amq[8];
    #pragma unroll
    for (int i = 0; i < 8; i++) {
        int idx = tid + i * 256;         // 0..2047
        int m = idx >> 4;                // 0..127
        int q = (idx & 15) << 2;         // 0..60
        int gr = m0 + m;
        int ar = rowmap ? rowmap[gr] : gr;
        arow[i] = A + (long)ar * lda + q;
        amq[i] = (m * GSTRIDE + q) * 2;  // byte offset
    }

    float d[4][4][4];
    #pragma unroll
    for (int i = 0; i < 4; i++)
        #pragma unroll
        for (int j = 0; j < 4; j++)
            #pragma unroll
            for (int r = 0; r < 4; r++) d[i][j][r] = 0.f;

    // ldmatrix address components (bytes)
    const int a_row = lane & 15, a_half = (lane >> 4) * 8;
    const int b_row = lane & 7,  b_half = ((lane >> 3) & 1) * 8;

    const int kc = K >> 6;
    for (int c = 0; c < kc; c++) {
        // ---- convert A chunk [128m x 64k] to bf16 hi/lo ----
        #pragma unroll
        for (int i = 0; i < 8; i++) {
            float4 v = *(const float4*)(arow[i] + (c << 6));
            if (preRelu) {
                v.x = fmaxf(v.x, 0.f); v.y = fmaxf(v.y, 0.f);
                v.z = fmaxf(v.z, 0.f); v.w = fmaxf(v.w, 0.f);
            }
            __nv_bfloat16 h0 = __float2bfloat16_rn(v.x), h1 = __float2bfloat16_rn(v.y);
            __nv_bfloat16 h2 = __float2bfloat16_rn(v.z), h3 = __float2bfloat16_rn(v.w);
            float l0 = v.x - __bfloat162float(h0), l1 = v.y - __bfloat162float(h1);
            float l2 = v.z - __bfloat162float(h2), l3 = v.w - __bfloat162float(h3);
            unsigned hp0 = ((unsigned)__bfloat16_as_ushort(h0)) | ((unsigned)__bfloat16_as_ushort(h1) << 16);
            unsigned hp1 = ((unsigned)__bfloat16_as_ushort(h2)) | ((unsigned)__bfloat16_as_ushort(h3) << 16);
            *(uint2*)(sAh + amq[i]) = make_uint2(hp0, hp1);
            *(uint2*)(sAl + amq[i]) = make_uint2(bfpack(l0, l1), bfpack(l2, l3));
        }
        // ---- convert + transpose B chunk [64k x 128n] -> smem [n][k] ----
        #pragma unroll
        for (int i = 0; i < 8; i++) {
            int idx = tid + i * 256;       // 0..2047
            int kk = idx >> 5;             // 0..63
            int q4 = (idx & 31) << 2;      // n offset
            float4 v = *(const float4*)(B + (long)((c << 6) + kk) * ldb + col0 + q4);
            float vv[4] = { v.x, v.y, v.z, v.w };
            #pragma unroll
            for (int j = 0; j < 4; j++) {
                int off = ((q4 + j) * GSTRIDE + kk) * 2;
                __nv_bfloat16 h = __float2bfloat16_rn(vv[j]);
                *(__nv_bfloat16*)(sBh + off) = h;
                *(__nv_bfloat16*)(sBl + off) = __float2bfloat16_rn(vv[j] - __bfloat162float(h));
            }
        }
        __syncthreads();

        #pragma unroll
        for (int ks = 0; ks < 4; ks++) {
            const int kb = ks * 16;
            unsigned ah[4][4], al[4][4], bh[4][2], bl[4][2];
            #pragma unroll
            for (int mt = 0; mt < 4; mt++) {
                int off = ((warp_m + mt * 16 + a_row) * GSTRIDE + kb + a_half) * 2;
                ldsm4(ah[mt], uAh + off);
                ldsm4(al[mt], uAl + off);
            }
            #pragma unroll
            for (int nt = 0; nt < 4; nt++) {
                int off = ((warp_n + nt * 8 + b_row) * GSTRIDE + kb + b_half) * 2;
                ldsm2(bh[nt], uBh + off);
                ldsm2(bl[nt], uBl + off);
            }
            #pragma unroll
            for (int mt = 0; mt < 4; mt++)
                #pragma unroll
                for (int nt = 0; nt < 4; nt++) {
                    mma16816(d[mt][nt], ah[mt], bh[nt]);
                    mma16816(d[mt][nt], ah[mt], bl[nt]);
                    mma16816(d[mt][nt], al[mt], bh[nt]);
                }
        }
        __syncthreads();
    }

    // ---- epilogue: fragment (lane>>2, (lane&3)*2) rows +0/+8 ----
    const int r0 = lane >> 2;
    const int c0 = (lane & 3) * 2;
    #pragma unroll
    for (int mt = 0; mt < 4; mt++) {
        int gmA = m0 + warp_m + mt * 16 + r0;
        int gmB = gmA + 8;
        float dgA = 1.f, dgB = 1.f;
        if (C2) { dgA = degv[gmA]; dgB = degv[gmB]; }
        #pragma unroll
        for (int nt = 0; nt < 4; nt++) {
            int gn = col0 + warp_n + nt * 8 + c0;
            float2 vA = make_float2(d[mt][nt][0], d[mt][nt][1]);
            float2 vB = make_float2(d[mt][nt][2], d[mt][nt][3]);
            if (C2) {
                *(float2*)&C2[(long)gmA * ldc + gn] =
                    make_float2(vA.x / dgA + bias2[gn], vA.y / dgA + bias2[gn + 1]);
                *(float2*)&C2[(long)gmB * ldc + gn] =
                    make_float2(vB.x / dgB + bias2[gn], vB.y / dgB + bias2[gn + 1]);
            }
            if (bias) {
                float b0 = bias[gn], b1 = bias[gn + 1];
                vA.x += b0; vA.y += b1; vB.x += b0; vB.y += b1;
            }
            if (act == 1) {
                vA.x = fmaxf(vA.x, 0.f); vA.y = fmaxf(vA.y, 0.f);
                vB.x = fmaxf(vB.x, 0.f); vB.y = fmaxf(vB.y, 0.f);
            } else if (act == 2) {
                vA.x = tanhf(vA.x); vA.y = tanhf(vA.y);
                vB.x = tanhf(vB.x); vB.y = tanhf(vB.y);
            }
            *(float2*)&C[(long)gmA * ldc + gn] = vA;
            *(float2*)&C[(long)gmB * ldc + gn] = vB;
        }
    }
}

// ---------------- generic SGEMM (GCN layer 1, K=78) ----------------
__global__ __launch_bounds__(256) void sgemm64(
    const float* __restrict__ A, int lda,
    const float* __restrict__ B, float* __restrict__ C,
    int M, int N, int K,
    float* __restrict__ C2, const float* __restrict__ degv,
    const float* __restrict__ bias2)
{
    __shared__ float As[16][64];
    __shared__ float Bs[16][68];
    const int tid = threadIdx.y * 16 + threadIdx.x;
    const int m0 = blockIdx.y * 64;
    const int n0 = blockIdx.x * 64;
    float acc[4][4] = {};
    for (int kt = 0; kt < K; kt += 16) {
        #pragma unroll
        for (int i = tid; i < 64 * 16; i += 256) {
            int m = i >> 4, kk = i & 15;
            int gm = m0 + m, gk = kt + kk;
            float v = 0.f;
            if (gm < M && gk < K) v = A[(long)gm * lda + gk];
            As[kk][m] = v;
        }
        #pragma unroll
        for (int i = tid; i < 16 * 64; i += 256) {
            int kk = i >> 6, n = i & 63;
            int gk = kt + kk, gn = n0 + n;
            Bs[kk][n] = (gk < K && gn < N) ? B[(long)gk * N + gn] : 0.f;
        }
        __syncthreads();
        #pragma unroll
        for (int kk = 0; kk < 16; kk++) {
            float a[4];
            #pragma unroll
            for (int i = 0; i < 4; i++) a[i] = As[kk][threadIdx.y * 4 + i];
            float4 b4 = *(const float4*)&Bs[kk][threadIdx.x * 4];
            float bv[4] = { b4.x, b4.y, b4.z, b4.w };
            #pragma unroll
            for (int i = 0; i < 4; i++)
                #pragma unroll
                for (int j = 0; j < 4; j++) acc[i][j] += a[i] * bv[j];
        }
        __syncthreads();
    }
    #pragma unroll
    for (int i = 0; i < 4; i++) {
        int gm = m0 + threadIdx.y * 4 + i;
        if (gm >= M) continue;
        #pragma unroll
        for (int j = 0; j < 4; j++) {
            int gn = n0 + threadIdx.x * 4 + j;
            if (gn >= N) continue;
            float v = acc[i][j];
            if (C2) C2[(long)gm * N + gn] = v / degv[gm] + bias2[gn];
            C[(long)gm * N + gn] = v;
        }
    }
}

// ---------------- prep_all ----------------
__global__ __launch_bounds__(1024) void prep_all(
    const int* __restrict__ tgt, const int* __restrict__ src,
    const int* __restrict__ dst, const int* __restrict__ batch,
    int n, int E,
    int* bslot, int* rowmap, int* Mdyn,
    float* deg, float* coef, int* counts, int* starts)
{
    __shared__ float sdeg[NNODES];
    __shared__ int flag[NPROT];
    __shared__ int slot[NPROT];
    __shared__ int uniq[BGR];
    __shared__ int cbin[BGR];
    __shared__ int nu_s;
    const int tid = threadIdx.x;

    for (int i = tid; i < n; i += 1024) sdeg[i] = 1.0f;
    if (tid < NPROT) flag[tid] = 0;
    if (tid < BGR) cbin[tid] = 0;
    __syncthreads();
    if (tid < BGR) flag[tgt[tid]] = 1;
    for (int e = tid; e < E; e += 1024) atomicAdd(&sdeg[dst[e]], 1.0f);
    for (int i = tid; i < n; i += 1024) atomicAdd(&cbin[batch[i]], 1);
    __syncthreads();
    if (tid == 0) {
        int s = 0;
        for (int p = 0; p < NPROT; p++) {
            if (flag[p]) { slot[p] = s; uniq[s] = p; s++; }
            else slot[p] = -1;
        }
        nu_s = s;
        Mdyn[0] = s * LPROT;
    } else if (tid == 32) {
        int s = 0;
        for (int b = 0; b < BGR; b++) { starts[b] = s; counts[b] = cbin[b]; s += cbin[b]; }
    }
    __syncthreads();
    if (tid < BGR) bslot[tid] = slot[tgt[tid]];
    for (int i = tid; i < n; i += 1024) deg[i] = sdeg[i];
    for (int e = tid; e < E; e += 1024)
        coef[e] = rsqrtf(sdeg[src[e]]) * rsqrtf(sdeg[dst[e]]);
    int nu = nu_s;
    for (int r = tid; r < TROWS; r += 1024) {
        int s = r >> 9;
        rowmap[r] = (s < nu) ? (uniq[s] * LPROT + (r & (LPROT - 1))) : 0;
    }
}

// ---------------- GCN scatter (float4) ----------------
__global__ void gcn_scatter4(const int* __restrict__ src, const int* __restrict__ dst,
                             const float* __restrict__ coef, const float* __restrict__ xw,
                             float* out, int E, int F4) {
    long i = (long)blockIdx.x * blockDim.x + threadIdx.x;
    if (i >= (long)E * F4) return;
    int e = (int)(i / F4);
    int f = (int)(i - (long)e * F4) * 4;
    float c = coef[e];
    int s = src[e], d = dst[e];
    const int F = F4 * 4;
    float4 v = *(const float4*)&xw[(long)s * F + f];
    float* o = &out[(long)d * F + f];
    atomicAdd(o + 0, v.x * c);
    atomicAdd(o + 1, v.y * c);
    atomicAdd(o + 2, v.z * c);
    atomicAdd(o + 3, v.w * c);
}

// ---------------- to_dense_batch gather ----------------
__global__ void dense_build(const float* __restrict__ h3,
                            const int* __restrict__ counts,
                            const int* __restrict__ starts,
                            float* __restrict__ dense) {
    int i = blockIdx.x * blockDim.x + threadIdx.x;
    if (i >= BGR * MAXN * 64) return;
    int b = i / (MAXN * 64);
    int rem = i - b * (MAXN * 64);
    int pos = rem >> 6, f4 = rem & 63;
    float4 v = make_float4(0.f, 0.f, 0.f, 0.f);
    if (pos < counts[b]) {
        v = ((const float4*)(h3 + (long)(starts[b] + pos) * 256))[f4];
        v.x = fmaxf(v.x, 0.f); v.y = fmaxf(v.y, 0.f);
        v.z = fmaxf(v.z, 0.f); v.w = fmaxf(v.w, 0.f);
    }
    ((float4*)dense)[i] = v;
}

// ---------------- Wcomb = [W_b | W_p^T | 0]  [128,256] ----------------
__global__ void wcomb_build(const float* __restrict__ Wb, const float* __restrict__ Wp,
                            float* __restrict__ Wc) {
    int i = blockIdx.x * 256 + threadIdx.x;
    if (i >= 128 * 256) return;
    int k = i >> 8, n = i & 255;
    float v = 0.f;
    if (n < 128) v = Wb[k * 128 + n];
    else if (n < 160) v = Wp[(n - 128) * 128 + k];
    Wc[i] = v;
}

// =================================================================
// FUSED CO-ATTENTION (unchanged)
// =================================================================
#define PHD 132
#define OFF_HD   0
#define OFF_WCX  (OFF_HD + 45*PHD)
#define OFF_C    (OFF_WCX + 32*48)
#define OFF_TB   (OFF_C + 64*48)
#define OFF_AP   (OFF_TB + 64*PHD)
#define OFF_AC   (OFF_AP + 512)
#define OFF_RED  (OFF_AC + 48)
#define OFF_WC   (OFF_RED + 256)
#define OFF_WP   (OFF_WC + 32)
#define OFF_SCAL (OFF_WP + 32)
#define SM_FLOATS (OFF_SCAL + 4)

__global__ __launch_bounds__(256) void coattn_fused(
    const float* __restrict__ tbw, const float* __restrict__ t,
    const float* __restrict__ hd, const float* __restrict__ Wc_g,
    const float* __restrict__ whc, const float* __restrict__ whp,
    const int* __restrict__ bslot, float* __restrict__ cp)
{
    extern __shared__ float sm[];
    float* s_hd  = sm + OFF_HD;
    float* s_wcx = sm + OFF_WCX;
    float* s_C   = sm + OFF_C;
    float* s_tb  = sm + OFF_TB;
    float* s_ap  = sm + OFF_AP;
    float* s_ac  = sm + OFF_AC;
    float* s_red = sm + OFF_RED;
    float* s_wc  = sm + OFF_WC;
    float* s_wp  = sm + OFF_WP;
    float* s_scal= sm + OFF_SCAL;

    const int b = blockIdx.x;
    const int tid = threadIdx.x;
    const long base = (long)bslot[b] * LPROT;
    const float* hd_b = hd + (long)b * MAXN * 128;

    for (int idx = tid; idx < MAXN * 32; idx += 256) {
        int s = idx >> 5, v4 = (idx & 31) * 4;
        *(float4*)&s_hd[s * PHD + v4] = *(const float4*)&hd_b[s * 128 + v4];
    }
    if (tid < 32) { s_wc[tid] = whc[tid]; s_wp[tid] = whp[tid]; }
    if (tid < 48) s_ac[tid] = 0.f;
    __syncthreads();

    for (int idx = tid; idx < 32 * MAXN; idx += 256) {
        int k = idx / MAXN, s = idx - k * MAXN;
        float acc = 0.f;
        #pragma unroll
        for (int kk = 0; kk < 32; kk++) {
            float4 a = *(const float4*)&Wc_g[k * 128 + kk * 4];
            float4 h4 = *(const float4*)&s_hd[s * PHD + kk * 4];
            acc += a.x * h4.x + a.y * h4.y + a.z * h4.z + a.w * h4.w;
        }
        s_wcx[k * 48 + s] = acc;
    }

    const int kt2 = (tid / 15) * 2;
    const int st3 = (tid % 15) * 3;
    float hc00 = 0.f, hc01 = 0.f, hc02 = 0.f, hc10 = 0.f, hc11 = 0.f, hc12 = 0.f;

    for (int cc = 0; cc < 8; cc++) {
        const int lbase = cc * 64;
        __syncthreads();
        for (int idx = tid; idx < 64 * 32; idx += 256) {
            int l = idx >> 5, v4 = (idx & 31) * 4;
            *(float4*)&s_tb[l * PHD + v4] =
                *(const float4*)&tbw[(base + lbase + l) * 256 + v4];
        }
        __syncthreads();
        if (tid < 240) {
            int lt = (tid / 15) * 4;
            float ca[4][3] = {};
            #pragma unroll 8
            for (int kk = 0; kk < 32; kk++) {
                float4 a0 = *(const float4*)&s_tb[(lt + 0) * PHD + kk * 4];
                float4 a1 = *(const float4*)&s_tb[(lt + 1) * PHD + kk * 4];
                float4 a2 = *(const float4*)&s_tb[(lt + 2) * PHD + kk * 4];
                float4 a3 = *(const float4*)&s_tb[(lt + 3) * PHD + kk * 4];
                float4 h0 = *(const float4*)&s_hd[(st3 + 0) * PHD + kk * 4];
                float4 h1 = *(const float4*)&s_hd[(st3 + 1) * PHD + kk * 4];
                float4 h2 = *(const float4*)&s_hd[(st3 + 2) * PHD + kk * 4];
                ca[0][0] += a0.x*h0.x + a0.y*h0.y + a0.z*h0.z + a0.w*h0.w;
                ca[0][1] += a0.x*h1.x + a0.y*h1.y + a0.z*h1.z + a0.w*h1.w;
                ca[0][2] += a0.x*h2.x + a0.y*h2.y + a0.z*h2.z + a0.w*h2.w;
                ca[1][0] += a1.x*h0.x + a1.y*h0.y + a1.z*h0.z + a1.w*h0.w;
                ca[1][1] += a1.x*h1.x + a1.y*h1.y + a1.z*h1.z + a1.w*h1.w;
                ca[1][2] += a1.x*h2.x + a1.y*h2.y + a1.z*h2.z + a1.w*h2.w;
                ca[2][0] += a2.x*h0.x + a2.y*h0.y + a2.z*h0.z + a2.w*h0.w;
                ca[2][1] += a2.x*h1.x + a2.y*h1.y + a2.z*h1.z + a2.w*h1.w;
                ca[2][2] += a2.x*h2.x + a2.y*h2.y + a2.z*h2.z + a2.w*h2.w;
                ca[3][0] += a3.x*h0.x + a3.y*h0.y + a3.z*h0.z + a3.w*h0.w;
                ca[3][1] += a3.x*h1.x + a3.y*h1.y + a3.z*h1.z + a3.w*h1.w;
                ca[3][2] += a3.x*h2.x + a3.y*h2.y + a3.z*h2.z + a3.w*h2.w;
            }
            #pragma unroll
            for (int i = 0; i < 4; i++)
                #pragma unroll
                for (int j = 0; j < 3; j++)
                    s_C[(lt + i) * 48 + st3 + j] = tanhf(ca[i][j]);
        }
        __syncthreads();
        if (tid < 240) {
            for (int l = 0; l < 64; l++) {
                const float* wrow = &tbw[(base + lbase + l) * 256 + 128];
                float w0 = wrow[kt2], w1 = wrow[kt2 + 1];
                float c0 = s_C[l * 48 + st3];
                float c1 = s_C[l * 48 + st3 + 1];
                float c2 = s_C[l * 48 + st3 + 2];
                hc00 += w0 * c0; hc01 += w0 * c1; hc02 += w0 * c2;
                hc10 += w1 * c0; hc11 += w1 * c1; hc12 += w1 * c2;
            }
        }
        {
            int l = tid >> 2, q = tid & 3;
            float cl[45];
            #pragma unroll
            for (int s = 0; s < 45; s++) cl[s] = s_C[l * 48 + s];
            const float* wrow = &tbw[(base + lbase + l) * 256 + 128];
            float part = 0.f;
            #pragma unroll
            for (int i = 0; i < 8; i++) {
                int k = q * 8 + i;
                float v = wrow[k];
                const float* wx = &s_wcx[k * 48];
                #pragma unroll
                for (int s = 0; s < 45; s++) v += wx[s] * cl[s];
                part += s_wp[k] * tanhf(v);
            }
            part += __shfl_down_sync(0xffffffffu, part, 2);
            part += __shfl_down_sync(0xffffffffu, part, 1);
            if (q == 0) s_ap[lbase + l] = part;
        }
    }
    __syncthreads();

    if (tid < 240) {
        float h;
        h = tanhf(s_wcx[kt2 * 48 + st3] + hc00);       atomicAdd(&s_ac[st3],     s_wc[kt2] * h);
        h = tanhf(s_wcx[kt2 * 48 + st3 + 1] + hc01);   atomicAdd(&s_ac[st3 + 1], s_wc[kt2] * h);
        h = tanhf(s_wcx[kt2 * 48 + st3 + 2] + hc02);   atomicAdd(&s_ac[st3 + 2], s_wc[kt2] * h);
        h = tanhf(s_wcx[(kt2+1) * 48 + st3] + hc10);     atomicAdd(&s_ac[st3],     s_wc[kt2+1] * h);
        h = tanhf(s_wcx[(kt2+1) * 48 + st3 + 1] + hc11); atomicAdd(&s_ac[st3 + 1], s_wc[kt2+1] * h);
        h = tanhf(s_wcx[(kt2+1) * 48 + st3 + 2] + hc12); atomicAdd(&s_ac[st3 + 2], s_wc[kt2+1] * h);
    }
    __syncthreads();

    float m1 = fmaxf(s_ap[tid], s_ap[tid + 256]);
    s_red[tid] = m1; __syncthreads();
    for (int o = 128; o > 0; o >>= 1) {
        if (tid < o) s_red[tid] = fmaxf(s_red[tid], s_red[tid + o]);
        __syncthreads();
    }
    float mx = s_red[0]; __syncthreads();
    float e1 = expf(s_ap[tid] - mx), e2 = expf(s_ap[tid + 256] - mx);
    s_ap[tid] = e1; s_ap[tid + 256] = e2;
    s_red[tid] = e1 + e2; __syncthreads();
    for (int o = 128; o > 0; o >>= 1) {
        if (tid < o) s_red[tid] += s_red[tid + o];
        __syncthreads();
    }
    if (tid == 0) s_scal[0] = 1.f / s_red[0];
    if (tid == 0) {
        float amx = -1e30f;
        for (int s = 0; s < MAXN; s++) amx = fmaxf(amx, s_ac[s]);
        float sum = 0.f;
        for (int s = 0; s < MAXN; s++) { float e = expf(s_ac[s] - amx); s_ac[s] = e; sum += e; }
        float inv = 1.f / sum;
        for (int s = 0; s < MAXN; s++) s_ac[s] *= inv;
    }
    __syncthreads();

    {
        int h = tid >> 7, m = tid & 127;
        float accp = 0.f;
        int l0 = h * 256;
        for (int l = 0; l < 256; l++)
            accp += s_ap[l0 + l] * t[(base + l0 + l) * 128 + m];
        s_red[tid] = accp;
        __syncthreads();
        if (h == 0) {
            float accc = 0.f;
            #pragma unroll
            for (int s = 0; s < MAXN; s++) accc += s_ac[s] * s_hd[s * PHD + m];
            cp[b * 256 + m] = accc;
            cp[b * 256 + 128 + m] = (s_red[m] + s_red[128 + m]) * s_scal[0];
        }
    }
}

// ---------------- final output ----------------
__global__ void out_kernel(const float* __restrict__ f2, const float* __restrict__ oW,
                           const float* __restrict__ ob, float* __restrict__ out) {
    int b = threadIdx.x;
    if (b < BGR) {
        float s = 0.f;
        for (int j = 0; j < 512; j += 4) {
            float4 a = *(const float4*)&f2[b * 512 + j];
            float4 w = *(const float4*)&oW[j];
            s += a.x * w.x + a.y * w.y + a.z * w.z + a.w * w.w;
        }
        out[b] = s + ob[0];
    }
}

// ---------------- host launcher ----------------
static float* sym_f(const void* s) { void* p = nullptr; cudaGetSymbolAddress(&p, s); return (float*)p; }
static int*   sym_i(const void* s) { void* p = nullptr; cudaGetSymbolAddress(&p, s); return (int*)p; }

extern "C" void kernel_launch(void* const* d_in, const int* in_sizes, int n_in,
                              void* d_out, int out_size)
{
    const float* x      = (const float*)d_in[0];
    const int*   ei     = (const int*)d_in[1];
    const int*   tgt    = (const int*)d_in[2];
    const int*   batch  = (const int*)d_in[3];
    const float* prot   = (const float*)d_in[4];
    const float* gW1 = (const float*)d_in[5],  *gb1 = (const float*)d_in[6];
    const float* gW2 = (const float*)d_in[7],  *gb2 = (const float*)d_in[8];
    const float* gW3 = (const float*)d_in[9],  *gb3 = (const float*)d_in[10];
    const float* fc1W = (const float*)d_in[11], *fc1b = (const float*)d_in[12];
    const float* fc2W = (const float*)d_in[13], *fc2b = (const float*)d_in[14];
    const float* b1W = (const float*)d_in[15],  *b1b = (const float*)d_in[16];
    const float* b2W = (const float*)d_in[17],  *b2b = (const float*)d_in[18];
    const float* W_b = (const float*)d_in[19];
    const float* W_c = (const float*)d_in[20];
    const float* W_p = (const float*)d_in[21];
    const float* w_hc = (const float*)d_in[22], *w_hp = (const float*)d_in[23];
    const float* c1W = (const float*)d_in[24], *c1b = (const float*)d_in[25];
    const float* c2W = (const float*)d_in[26], *c2b = (const float*)d_in[27];
    const float* oW  = (const float*)d_in[28], *ob  = (const float*)d_in[29];

    const int N = in_sizes[0] / 78;
    const int E = in_sizes[1] / 2;
    const int* src = ei;
    const int* dst = ei + E;

    float* deg   = sym_f(g_deg);
    float* coef  = sym_f(g_coef);
    float* xw    = sym_f(g_xw);
    float* hA    = sym_f(g_hA);
    float* hB    = sym_f(g_hB);
    float* h3    = sym_f(g_h3);
    int*   counts = sym_i(g_counts);
    int*   starts = sym_i(g_starts);
    float* dense = sym_f(g_dense);
    float* fc1o  = sym_f(g_fc1);
    float* hd    = sym_f(g_hd);
    int*   rowmap = sym_i(g_rowmap);
    float* t1    = sym_f(g_t1);
    float* t     = sym_f(g_t);
    float* tbw   = sym_f(g_tbw);
    float* wcomb = sym_f(g_wcomb);
    float* cp    = sym_f(g_cp);
    float* f1    = sym_f(g_f1);
    float* f2    = sym_f(g_f2);
    int* Mdyn  = sym_i(g_Mdyn);
    int* bslot = sym_i(g_bslot);

    static cudaStream_t sB = 0;
    static cudaEvent_t evF = 0, evJ = 0;
    static int tried = 0;
    if (!tried) {
        tried = 1;
        if (cudaStreamCreateWithFlags(&sB, cudaStreamNonBlocking) != cudaSuccess) sB = 0;
        if (sB) {
            if (cudaEventCreateWithFlags(&evF, cudaEventDisableTiming) != cudaSuccess ||
                cudaEventCreateWithFlags(&evJ, cudaEventDisableTiming) != cudaSuccess) {
                sB = 0;
            }
        }
        cudaFuncSetAttribute(coattn_fused, cudaFuncAttributeMaxDynamicSharedMemorySize,
                             SM_FLOATS * 4 + 1024);
        cudaFuncSetAttribute(gemm_mma, cudaFuncAttributeMaxDynamicSharedMemorySize, GM_SMEM);
    }
    const bool fork = (sB != 0);
    cudaStream_t PS = fork ? sB : (cudaStream_t)0;

    dim3 t16(16, 16);

    // ---- fused prep ----
    prep_all<<<1, 1024>>>(tgt, src, dst, batch, N, E,
                          bslot, rowmap, Mdyn, deg, coef, counts, starts);

    // ---- fork: protein branch (warp MMA tensor cores) ----
    if (fork) { cudaEventRecord(evF, 0); cudaStreamWaitEvent(sB, evF, 0); }
    wcomb_build<<<128, 256, 0, PS>>>(W_b, W_p, wcomb);
    gemm_mma<<<dim3(1, TROWS / 128), 256, GM_SMEM, PS>>>(prot, DPROT, rowmap, b1W, 128, b1b, t1, 128, Mdyn, DPROT, 1, 0, nullptr, nullptr, nullptr);
    gemm_mma<<<dim3(1, TROWS / 128), 256, GM_SMEM, PS>>>(t1, 128, nullptr, b2W, 128, b2b, t, 128, Mdyn, 128, 1, 0, nullptr, nullptr, nullptr);
    gemm_mma<<<dim3(2, TROWS / 128), 256, GM_SMEM, PS>>>(t, 128, nullptr, wcomb, 256, nullptr, tbw, 256, Mdyn, 128, 0, 0, nullptr, nullptr, nullptr);
    if (fork) cudaEventRecord(evJ, sB);

    // ---- main branch: GCN stack ----
    sgemm64<<<dim3(2, (N + 63) / 64), t16>>>(x, 78, gW1, xw, N, 128, 78, hA, deg, gb1);
    gcn_scatter4<<<((long)E * 32 + 255) / 256, 256>>>(src, dst, coef, xw, hA, E, 32);

    gemm_mma<<<dim3(1, N / 128), 256, GM_SMEM>>>(hA, 128, nullptr, gW2, 128, nullptr, xw, 128, nullptr, 128, 0, 1, hB, deg, gb2);
    gcn_scatter4<<<((long)E * 32 + 255) / 256, 256>>>(src, dst, coef, xw, hB, E, 32);

    gemm_mma<<<dim3(2, N / 128), 256, GM_SMEM>>>(hB, 128, nullptr, gW3, 256, nullptr, xw, 256, nullptr, 128, 0, 1, h3, deg, gb3);
    gcn_scatter4<<<((long)E * 64 + 255) / 256, 256>>>(src, dst, coef, xw, h3, E, 64);

    dense_build<<<(BGR * MAXN * 64 + 255) / 256, 256>>>(h3, counts, starts, dense);
    const int MD = BGR * MAXN;  // 5760
    gemm_mma<<<dim3(8, MD / 128), 256, GM_SMEM>>>(dense, 256, nullptr, fc1W, 1024, fc1b, fc1o, 1024, nullptr, 256, 1, 0, nullptr, nullptr, nullptr);
    gemm_mma<<<dim3(1, MD / 128), 256, GM_SMEM>>>(fc1o, 1024, nullptr, fc2W, 128, fc2b, hd, 128, nullptr, 1024, 1, 0, nullptr, nullptr, nullptr);

    // ---- join, fused co-attention ----
    if (fork) cudaStreamWaitEvent(0, evJ, 0);
    coattn_fused<<<BGR, 256, SM_FLOATS * 4 + 1024>>>(tbw, t, hd, W_c, w_hc, w_hp, bslot, cp);

    // ---- final MLP (warp MMA) ----
    gemm_mma<<<dim3(8, 1), 256, GM_SMEM>>>(cp, 256, nullptr, c1W, 1024, c1b, f1, 1024, nullptr, 256, 1, 0, nullptr, nullptr, nullptr);
    gemm_mma<<<dim3(4, 1), 256, GM_SMEM>>>(f1, 1024, nullptr, c2W, 512, c2b, f2, 512, nullptr, 1024, 1, 0, nullptr, nullptr, nullptr);
    out_kernel<<<1, 128>>>(f2, oW, ob, (float*)d_out);
}

// round 10
// speedup vs baseline: 1.1146x; 1.1146x over previous
#include <cuda_runtime.h>
#include <cuda_bf16.h>
#include <math.h>
#include <stdint.h>

// ---------------- problem constants ----------------
#define NNODES 5120
#define NEDGES 20000
#define BGR    128
#define MAXN   45
#define LPROT  512
#define DPROT  1280
#define NPROT  229
#define TROWS  (BGR*LPROT)   // 65536

typedef unsigned long long u64;

// ---------------- converted-weight pool (bf16 hi/lo, [n][k] k-major) ----------------
#define SZ_B1 (1280*128)
#define SZ_B2 (128*128)
#define SZ_WC (256*128)
#define SZ_G2 (128*128)
#define SZ_G3 (256*128)
#define SZ_F1 (1024*256)
#define SZ_F2 (128*1024)
#define SZ_C1 (1024*256)
#define SZ_C2 (512*1024)
#define WOFF_B1 0
#define WOFF_B2 (WOFF_B1+SZ_B1)
#define WOFF_WC (WOFF_B2+SZ_B2)
#define WOFF_G2 (WOFF_WC+SZ_WC)
#define WOFF_G3 (WOFF_G2+SZ_G2)
#define WOFF_F1 (WOFF_G3+SZ_G3)
#define WOFF_F2 (WOFF_F1+SZ_F1)
#define WOFF_C1 (WOFF_F2+SZ_F2)
#define WOFF_C2 (WOFF_C1+SZ_C1)
#define TOTALW  (WOFF_C2+SZ_C2)

// ---------------- device scratch ----------------
__device__ float g_deg[NNODES];
__device__ float g_coef[NEDGES];
__device__ float g_xw[NNODES*256];
__device__ float g_hA[NNODES*128];
__device__ float g_hB[NNODES*128];
__device__ float g_h3[NNODES*256];
__device__ int   g_counts[BGR];
__device__ int   g_starts[BGR];
__device__ float g_dense[BGR*MAXN*256];
__device__ float g_fc1[BGR*MAXN*1024];
__device__ float g_hd[BGR*MAXN*128];
__device__ int   g_rowmap[TROWS];
__device__ float g_t1[TROWS*128];
__device__ float g_t[TROWS*128];
__device__ float g_tbw[(long)TROWS*256];   // [tb | WptT | pad]
__device__ float g_cp[BGR*256];
__device__ float g_f1[BGR*1024];
__device__ float g_f2[BGR*512];
__device__ int g_Mdyn[1];
__device__ int g_bslot[BGR];
__device__ __nv_bfloat16 g_whi[TOTALW];
__device__ __nv_bfloat16 g_wlo[TOTALW];

// ---------------- helpers ----------------
__device__ __forceinline__ unsigned su32(const void* p) {
    unsigned r;
    asm("{ .reg .u64 t; cvta.to.shared.u64 t, %1; cvt.u32.u64 %0, t; }" : "=r"(r) : "l"(p));
    return r;
}
__device__ __forceinline__ void ldsm4(unsigned* r, unsigned addr) {
    asm volatile("ldmatrix.sync.aligned.m8n8.x4.shared.b16 {%0,%1,%2,%3}, [%4];"
        : "=r"(r[0]), "=r"(r[1]), "=r"(r[2]), "=r"(r[3]) : "r"(addr));
}
__device__ __forceinline__ void ldsm2(unsigned* r, unsigned addr) {
    asm volatile("ldmatrix.sync.aligned.m8n8.x2.shared.b16 {%0,%1}, [%2];"
        : "=r"(r[0]), "=r"(r[1]) : "r"(addr));
}
__device__ __forceinline__ void mma16816(float* d, const unsigned* a, const unsigned* b) {
    asm volatile("mma.sync.aligned.m16n8k16.row.col.f32.bf16.bf16.f32 "
        "{%0,%1,%2,%3}, {%4,%5,%6,%7}, {%8,%9}, {%0,%1,%2,%3};"
        : "+f"(d[0]), "+f"(d[1]), "+f"(d[2]), "+f"(d[3])
        : "r"(a[0]), "r"(a[1]), "r"(a[2]), "r"(a[3]), "r"(b[0]), "r"(b[1]));
}
__device__ __forceinline__ unsigned bfpack(float a, float b) {
    __nv_bfloat162 h = __floats2bfloat162_rn(a, b);
    return *(unsigned*)&h;
}
__device__ __forceinline__ void cp16(unsigned dst, const void* src) {
    asm volatile("cp.async.ca.shared.global [%0], [%1], 16;" :: "r"(dst), "l"(src));
}
__device__ __forceinline__ void cp_wait0() {
    asm volatile("cp.async.wait_all;" ::: "memory");
}

// ---------------- weight conversion: fp32 [K][N] -> bf16 hi/lo [N][K] ----------------
__global__ void convert_w(
    const float* __restrict__ b1W, const float* __restrict__ b2W,
    const float* __restrict__ Wb,  const float* __restrict__ Wp,
    const float* __restrict__ gW2, const float* __restrict__ gW3,
    const float* __restrict__ fc1W, const float* __restrict__ fc2W,
    const float* __restrict__ c1W, const float* __restrict__ c2W,
    __nv_bfloat16* __restrict__ hi, __nv_bfloat16* __restrict__ lo)
{
    int i = blockIdx.x * 256 + threadIdx.x;
    if (i >= TOTALW) return;
    float v;
    if (i < WOFF_B2)      { int j = i;           int n = j / 1280, k = j % 1280; v = b1W[k * 128 + n]; }
    else if (i < WOFF_WC) { int j = i - WOFF_B2; int n = j >> 7,  k = j & 127;  v = b2W[k * 128 + n]; }
    else if (i < WOFF_G2) { int j = i - WOFF_WC; int n = j >> 7,  k = j & 127;
                            v = (n < 128) ? Wb[k * 128 + n] : ((n < 160) ? Wp[(n - 128) * 128 + k] : 0.f); }
    else if (i < WOFF_G3) { int j = i - WOFF_G2; int n = j >> 7,  k = j & 127;  v = gW2[k * 128 + n]; }
    else if (i < WOFF_F1) { int j = i - WOFF_G3; int n = j >> 7,  k = j & 127;  v = gW3[k * 256 + n]; }
    else if (i < WOFF_F2) { int j = i - WOFF_F1; int n = j >> 8,  k = j & 255;  v = fc1W[k * 1024 + n]; }
    else if (i < WOFF_C1) { int j = i - WOFF_F2; int n = j >> 10, k = j & 1023; v = fc2W[k * 128 + n]; }
    else if (i < WOFF_C2) { int j = i - WOFF_C1; int n = j >> 8,  k = j & 255;  v = c1W[k * 1024 + n]; }
    else                  { int j = i - WOFF_C2; int n = j >> 10, k = j & 1023; v = c2W[k * 512 + n]; }
    __nv_bfloat16 h = __float2bfloat16_rn(v);
    hi[i] = h;
    lo[i] = __float2bfloat16_rn(v - __bfloat162float(h));
}

// =================================================================
// bf16-split warp-MMA GEMM v2: B pre-converted ([N][K] bf16 hi/lo).
// C[M,N] = act(pre(gather(A))[M,K] @ W + bias); K%64==0.
// Tile 128x128/CTA, 8 warps 2x4 (64x32 each).
// smem: sAh/sAl/sBh/sBl each [128][72] bf16.
// =================================================================
#define GSTRIDE 72
#define GTILEB (128 * GSTRIDE * 2)
#define GM_SMEM (4 * GTILEB)

__global__ __launch_bounds__(256) void gemm_mma(
    const float* __restrict__ A, int lda, const int* __restrict__ rowmap,
    const __nv_bfloat16* __restrict__ Bhi, const __nv_bfloat16* __restrict__ Blo,
    const float* __restrict__ bias,
    float* __restrict__ C, int ldc, const int* __restrict__ Mdyn,
    int K, int act, int preRelu,
    float* __restrict__ C2, const float* __restrict__ degv,
    const float* __restrict__ bias2)
{
    const int m0 = blockIdx.y * 128;
    if (Mdyn && m0 >= *Mdyn) return;
    const int col0 = blockIdx.x * 128;
    const int tid = threadIdx.x;
    const int wid = tid >> 5, lane = tid & 31;
    const int warp_m = (wid >> 2) * 64;
    const int warp_n = (wid & 3) * 32;

    extern __shared__ char smraw[];
    char* sAh = smraw;
    char* sAl = smraw + GTILEB;
    char* sBh = smraw + 2 * GTILEB;
    char* sBl = smraw + 3 * GTILEB;
    const unsigned uAh = su32(sAh), uAl = su32(sAl);
    const unsigned uBh = su32(sBh), uBl = su32(sBl);

    // A conversion descriptors
    const float* arow[8];
    int amq[8];
    #pragma unroll
    for (int i = 0; i < 8; i++) {
        int idx = tid + i * 256;
        int m = idx >> 4;
        int q = (idx & 15) << 2;
        int gr = m0 + m;
        int ar = rowmap ? rowmap[gr] : gr;
        arow[i] = A + (long)ar * lda + q;
        amq[i] = (m * GSTRIDE + q) * 2;
    }
    // B cp.async descriptors: 4 chunks per thread per array
    const __nv_bfloat16* bsrc_h[4];
    const __nv_bfloat16* bsrc_l[4];
    unsigned bdst[4];
    #pragma unroll
    for (int i = 0; i < 4; i++) {
        int idx = tid + i * 256;          // 0..1023
        int n = idx >> 3;                 // 0..127
        int k8 = (idx & 7) << 3;          // 0..56
        bsrc_h[i] = Bhi + (long)(col0 + n) * K + k8;
        bsrc_l[i] = Blo + (long)(col0 + n) * K + k8;
        bdst[i] = (n * GSTRIDE + k8) * 2; // byte offset in tile
    }

    float d[4][4][4];
    #pragma unroll
    for (int i = 0; i < 4; i++)
        #pragma unroll
        for (int j = 0; j < 4; j++)
            #pragma unroll
            for (int r = 0; r < 4; r++) d[i][j][r] = 0.f;

    const int a_row = lane & 15, a_half = (lane >> 4) * 8;
    const int b_row = lane & 7,  b_half = ((lane >> 3) & 1) * 8;

    const int kc = K >> 6;
    for (int c = 0; c < kc; c++) {
        // ---- issue B chunk copies (async) ----
        #pragma unroll
        for (int i = 0; i < 4; i++) {
            cp16(uBh + bdst[i], bsrc_h[i] + (c << 6));
            cp16(uBl + bdst[i], bsrc_l[i] + (c << 6));
        }
        // ---- convert A chunk while B flies ----
        #pragma unroll
        for (int i = 0; i < 8; i++) {
            float4 v = *(const float4*)(arow[i] + (c << 6));
            if (preRelu) {
                v.x = fmaxf(v.x, 0.f); v.y = fmaxf(v.y, 0.f);
                v.z = fmaxf(v.z, 0.f); v.w = fmaxf(v.w, 0.f);
            }
            __nv_bfloat16 h0 = __float2bfloat16_rn(v.x), h1 = __float2bfloat16_rn(v.y);
            __nv_bfloat16 h2 = __float2bfloat16_rn(v.z), h3 = __float2bfloat16_rn(v.w);
            float l0 = v.x - __bfloat162float(h0), l1 = v.y - __bfloat162float(h1);
            float l2 = v.z - __bfloat162float(h2), l3 = v.w - __bfloat162float(h3);
            unsigned hp0 = ((unsigned)__bfloat16_as_ushort(h0)) | ((unsigned)__bfloat16_as_ushort(h1) << 16);
            unsigned hp1 = ((unsigned)__bfloat16_as_ushort(h2)) | ((unsigned)__bfloat16_as_ushort(h3) << 16);
            *(uint2*)(sAh + amq[i]) = make_uint2(hp0, hp1);
            *(uint2*)(sAl + amq[i]) = make_uint2(bfpack(l0, l1), bfpack(l2, l3));
        }
        cp_wait0();
        __syncthreads();

        #pragma unroll
        for (int ks = 0; ks < 4; ks++) {
            const int kb = ks * 16;
            unsigned ah[4][4], al[4][4], bh[4][2], bl[4][2];
            #pragma unroll
            for (int mt = 0; mt < 4; mt++) {
                int off = ((warp_m + mt * 16 + a_row) * GSTRIDE + kb + a_half) * 2;
                ldsm4(ah[mt], uAh + off);
                ldsm4(al[mt], uAl + off);
            }
            #pragma unroll
            for (int nt = 0; nt < 4; nt++) {
                int off = ((warp_n + nt * 8 + b_row) * GSTRIDE + kb + b_half) * 2;
                ldsm2(bh[nt], uBh + off);
                ldsm2(bl[nt], uBl + off);
            }
            #pragma unroll
            for (int mt = 0; mt < 4; mt++)
                #pragma unroll
                for (int nt = 0; nt < 4; nt++) {
                    mma16816(d[mt][nt], ah[mt], bh[nt]);
                    mma16816(d[mt][nt], ah[mt], bl[nt]);
                    mma16816(d[mt][nt], al[mt], bh[nt]);
                }
        }
        __syncthreads();
    }

    // ---- epilogue ----
    const int r0 = lane >> 2;
    const int c0 = (lane & 3) * 2;
    #pragma unroll
    for (int mt = 0; mt < 4; mt++) {
        int gmA = m0 + warp_m + mt * 16 + r0;
        int gmB = gmA + 8;
        float dgA = 1.f, dgB = 1.f;
        if (C2) { dgA = degv[gmA]; dgB = degv[gmB]; }
        #pragma unroll
        for (int nt = 0; nt < 4; nt++) {
            int gn = col0 + warp_n + nt * 8 + c0;
            float2 vA = make_float2(d[mt][nt][0], d[mt][nt][1]);
            float2 vB = make_float2(d[mt][nt][2], d[mt][nt][3]);
            if (C2) {
                *(float2*)&C2[(long)gmA * ldc + gn] =
                    make_float2(vA.x / dgA + bias2[gn], vA.y / dgA + bias2[gn + 1]);
                *(float2*)&C2[(long)gmB * ldc + gn] =
                    make_float2(vB.x / dgB + bias2[gn], vB.y / dgB + bias2[gn + 1]);
            }
            if (bias) {
                float b0 = bias[gn], b1 = bias[gn + 1];
                vA.x += b0; vA.y += b1; vB.x += b0; vB.y += b1;
            }
            if (act == 1) {
                vA.x = fmaxf(vA.x, 0.f); vA.y = fmaxf(vA.y, 0.f);
                vB.x = fmaxf(vB.x, 0.f); vB.y = fmaxf(vB.y, 0.f);
            } else if (act == 2) {
                vA.x = tanhf(vA.x); vA.y = tanhf(vA.y);
                vB.x = tanhf(vB.x); vB.y = tanhf(vB.y);
            }
            *(float2*)&C[(long)gmA * ldc + gn] = vA;
            *(float2*)&C[(long)gmB * ldc + gn] = vB;
        }
    }
}

// ---------------- generic SGEMM (GCN layer 1, K=78) ----------------
__global__ __launch_bounds__(256) void sgemm64(
    const float* __restrict__ A, int lda,
    const float* __restrict__ B, float* __restrict__ C,
    int M, int N, int K,
    float* __restrict__ C2, const float* __restrict__ degv,
    const float* __restrict__ bias2)
{
    __shared__ float As[16][64];
    __shared__ float Bs[16][68];
    const int tid = threadIdx.y * 16 + threadIdx.x;
    const int m0 = blockIdx.y * 64;
    const int n0 = blockIdx.x * 64;
    float acc[4][4] = {};
    for (int kt = 0; kt < K; kt += 16) {
        #pragma unroll
        for (int i = tid; i < 64 * 16; i += 256) {
            int m = i >> 4, kk = i & 15;
            int gm = m0 + m, gk = kt + kk;
            float v = 0.f;
            if (gm < M && gk < K) v = A[(long)gm * lda + gk];
            As[kk][m] = v;
        }
        #pragma unroll
        for (int i = tid; i < 16 * 64; i += 256) {
            int kk = i >> 6, n = i & 63;
            int gk = kt + kk, gn = n0 + n;
            Bs[kk][n] = (gk < K && gn < N) ? B[(long)gk * N + gn] : 0.f;
        }
        __syncthreads();
        #pragma unroll
        for (int kk = 0; kk < 16; kk++) {
            float a[4];
            #pragma unroll
            for (int i = 0; i < 4; i++) a[i] = As[kk][threadIdx.y * 4 + i];
            float4 b4 = *(const float4*)&Bs[kk][threadIdx.x * 4];
            float bv[4] = { b4.x, b4.y, b4.z, b4.w };
            #pragma unroll
            for (int i = 0; i < 4; i++)
                #pragma unroll
                for (int j = 0; j < 4; j++) acc[i][j] += a[i] * bv[j];
        }
        __syncthreads();
    }
    #pragma unroll
    for (int i = 0; i < 4; i++) {
        int gm = m0 + threadIdx.y * 4 + i;
        if (gm >= M) continue;
        #pragma unroll
        for (int j = 0; j < 4; j++) {
            int gn = n0 + threadIdx.x * 4 + j;
            if (gn >= N) continue;
            float v = acc[i][j];
            if (C2) C2[(long)gm * N + gn] = v / degv[gm] + bias2[gn];
            C[(long)gm * N + gn] = v;
        }
    }
}

// ---------------- prep_all ----------------
__global__ __launch_bounds__(1024) void prep_all(
    const int* __restrict__ tgt, const int* __restrict__ src,
    const int* __restrict__ dst, const int* __restrict__ batch,
    int n, int E,
    int* bslot, int* rowmap, int* Mdyn,
    float* deg, float* coef, int* counts, int* starts)
{
    __shared__ float sdeg[NNODES];
    __shared__ int flag[NPROT];
    __shared__ int slot[NPROT];
    __shared__ int uniq[BGR];
    __shared__ int cbin[BGR];
    __shared__ int nu_s;
    const int tid = threadIdx.x;

    for (int i = tid; i < n; i += 1024) sdeg[i] = 1.0f;
    if (tid < NPROT) flag[tid] = 0;
    if (tid < BGR) cbin[tid] = 0;
    __syncthreads();
    if (tid < BGR) flag[tgt[tid]] = 1;
    for (int e = tid; e < E; e += 1024) atomicAdd(&sdeg[dst[e]], 1.0f);
    for (int i = tid; i < n; i += 1024) atomicAdd(&cbin[batch[i]], 1);
    __syncthreads();
    if (tid == 0) {
        int s = 0;
        for (int p = 0; p < NPROT; p++) {
            if (flag[p]) { slot[p] = s; uniq[s] = p; s++; }
            else slot[p] = -1;
        }
        nu_s = s;
        Mdyn[0] = s * LPROT;
    } else if (tid == 32) {
        int s = 0;
        for (int b = 0; b < BGR; b++) { starts[b] = s; counts[b] = cbin[b]; s += cbin[b]; }
    }
    __syncthreads();
    if (tid < BGR) bslot[tid] = slot[tgt[tid]];
    for (int i = tid; i < n; i += 1024) deg[i] = sdeg[i];
    for (int e = tid; e < E; e += 1024)
        coef[e] = rsqrtf(sdeg[src[e]]) * rsqrtf(sdeg[dst[e]]);
    int nu = nu_s;
    for (int r = tid; r < TROWS; r += 1024) {
        int s = r >> 9;
        rowmap[r] = (s < nu) ? (uniq[s] * LPROT + (r & (LPROT - 1))) : 0;
    }
}

// ---------------- GCN scatter (float4) ----------------
__global__ void gcn_scatter4(const int* __restrict__ src, const int* __restrict__ dst,
                             const float* __restrict__ coef, const float* __restrict__ xw,
                             float* out, int E, int F4) {
    long i = (long)blockIdx.x * blockDim.x + threadIdx.x;
    if (i >= (long)E * F4) return;
    int e = (int)(i / F4);
    int f = (int)(i - (long)e * F4) * 4;
    float c = coef[e];
    int s = src[e], d = dst[e];
    const int F = F4 * 4;
    float4 v = *(const float4*)&xw[(long)s * F + f];
    float* o = &out[(long)d * F + f];
    atomicAdd(o + 0, v.x * c);
    atomicAdd(o + 1, v.y * c);
    atomicAdd(o + 2, v.z * c);
    atomicAdd(o + 3, v.w * c);
}

// ---------------- to_dense_batch gather ----------------
__global__ void dense_build(const float* __restrict__ h3,
                            const int* __restrict__ counts,
                            const int* __restrict__ starts,
                            float* __restrict__ dense) {
    int i = blockIdx.x * blockDim.x + threadIdx.x;
    if (i >= BGR * MAXN * 64) return;
    int b = i / (MAXN * 64);
    int rem = i - b * (MAXN * 64);
    int pos = rem >> 6, f4 = rem & 63;
    float4 v = make_float4(0.f, 0.f, 0.f, 0.f);
    if (pos < counts[b]) {
        v = ((const float4*)(h3 + (long)(starts[b] + pos) * 256))[f4];
        v.x = fmaxf(v.x, 0.f); v.y = fmaxf(v.y, 0.f);
        v.z = fmaxf(v.z, 0.f); v.w = fmaxf(v.w, 0.f);
    }
    ((float4*)dense)[i] = v;
}

// =================================================================
// FUSED CO-ATTENTION (unchanged)
// =================================================================
#define PHD 132
#define OFF_HD   0
#define OFF_WCX  (OFF_HD + 45*PHD)
#define OFF_C    (OFF_WCX + 32*48)
#define OFF_TB   (OFF_C + 64*48)
#define OFF_AP   (OFF_TB + 64*PHD)
#define OFF_AC   (OFF_AP + 512)
#define OFF_RED  (OFF_AC + 48)
#define OFF_WC   (OFF_RED + 256)
#define OFF_WP   (OFF_WC + 32)
#define OFF_SCAL (OFF_WP + 32)
#define SM_FLOATS (OFF_SCAL + 4)

__global__ __launch_bounds__(256) void coattn_fused(
    const float* __restrict__ tbw, const float* __restrict__ t,
    const float* __restrict__ hd, const float* __restrict__ Wc_g,
    const float* __restrict__ whc, const float* __restrict__ whp,
    const int* __restrict__ bslot, float* __restrict__ cp)
{
    extern __shared__ float sm[];
    float* s_hd  = sm + OFF_HD;
    float* s_wcx = sm + OFF_WCX;
    float* s_C   = sm + OFF_C;
    float* s_tb  = sm + OFF_TB;
    float* s_ap  = sm + OFF_AP;
    float* s_ac  = sm + OFF_AC;
    float* s_red = sm + OFF_RED;
    float* s_wc  = sm + OFF_WC;
    float* s_wp  = sm + OFF_WP;
    float* s_scal= sm + OFF_SCAL;

    const int b = blockIdx.x;
    const int tid = threadIdx.x;
    const long base = (long)bslot[b] * LPROT;
    const float* hd_b = hd + (long)b * MAXN * 128;

    for (int idx = tid; idx < MAXN * 32; idx += 256) {
        int s = idx >> 5, v4 = (idx & 31) * 4;
        *(float4*)&s_hd[s * PHD + v4] = *(const float4*)&hd_b[s * 128 + v4];
    }
    if (tid < 32) { s_wc[tid] = whc[tid]; s_wp[tid] = whp[tid]; }
    if (tid < 48) s_ac[tid] = 0.f;
    __syncthreads();

    for (int idx = tid; idx < 32 * MAXN; idx += 256) {
        int k = idx / MAXN, s = idx - k * MAXN;
        float acc = 0.f;
        #pragma unroll
        for (int kk = 0; kk < 32; kk++) {
            float4 a = *(const float4*)&Wc_g[k * 128 + kk * 4];
            float4 h4 = *(const float4*)&s_hd[s * PHD + kk * 4];
            acc += a.x * h4.x + a.y * h4.y + a.z * h4.z + a.w * h4.w;
        }
        s_wcx[k * 48 + s] = acc;
    }

    const int kt2 = (tid / 15) * 2;
    const int st3 = (tid % 15) * 3;
    float hc00 = 0.f, hc01 = 0.f, hc02 = 0.f, hc10 = 0.f, hc11 = 0.f, hc12 = 0.f;

    for (int cc = 0; cc < 8; cc++) {
        const int lbase = cc * 64;
        __syncthreads();
        for (int idx = tid; idx < 64 * 32; idx += 256) {
            int l = idx >> 5, v4 = (idx & 31) * 4;
            *(float4*)&s_tb[l * PHD + v4] =
                *(const float4*)&tbw[(base + lbase + l) * 256 + v4];
        }
        __syncthreads();
        if (tid < 240) {
            int lt = (tid / 15) * 4;
            float ca[4][3] = {};
            #pragma unroll 8
            for (int kk = 0; kk < 32; kk++) {
                float4 a0 = *(const float4*)&s_tb[(lt + 0) * PHD + kk * 4];
                float4 a1 = *(const float4*)&s_tb[(lt + 1) * PHD + kk * 4];
                float4 a2 = *(const float4*)&s_tb[(lt + 2) * PHD + kk * 4];
                float4 a3 = *(const float4*)&s_tb[(lt + 3) * PHD + kk * 4];
                float4 h0 = *(const float4*)&s_hd[(st3 + 0) * PHD + kk * 4];
                float4 h1 = *(const float4*)&s_hd[(st3 + 1) * PHD + kk * 4];
                float4 h2 = *(const float4*)&s_hd[(st3 + 2) * PHD + kk * 4];
                ca[0][0] += a0.x*h0.x + a0.y*h0.y + a0.z*h0.z + a0.w*h0.w;
                ca[0][1] += a0.x*h1.x + a0.y*h1.y + a0.z*h1.z + a0.w*h1.w;
                ca[0][2] += a0.x*h2.x + a0.y*h2.y + a0.z*h2.z + a0.w*h2.w;
                ca[1][0] += a1.x*h0.x + a1.y*h0.y + a1.z*h0.z + a1.w*h0.w;
                ca[1][1] += a1.x*h1.x + a1.y*h1.y + a1.z*h1.z + a1.w*h1.w;
                ca[1][2] += a1.x*h2.x + a1.y*h2.y + a1.z*h2.z + a1.w*h2.w;
                ca[2][0] += a2.x*h0.x + a2.y*h0.y + a2.z*h0.z + a2.w*h0.w;
                ca[2][1] += a2.x*h1.x + a2.y*h1.y + a2.z*h1.z + a2.w*h1.w;
                ca[2][2] += a2.x*h2.x + a2.y*h2.y + a2.z*h2.z + a2.w*h2.w;
                ca[3][0] += a3.x*h0.x + a3.y*h0.y + a3.z*h0.z + a3.w*h0.w;
                ca[3][1] += a3.x*h1.x + a3.y*h1.y + a3.z*h1.z + a3.w*h1.w;
                ca[3][2] += a3.x*h2.x + a3.y*h2.y + a3.z*h2.z + a3.w*h2.w;
            }
            #pragma unroll
            for (int i = 0; i < 4; i++)
                #pragma unroll
                for (int j = 0; j < 3; j++)
                    s_C[(lt + i) * 48 + st3 + j] = tanhf(ca[i][j]);
        }
        __syncthreads();
        if (tid < 240) {
            for (int l = 0; l < 64; l++) {
                const float* wrow = &tbw[(base + lbase + l) * 256 + 128];
                float w0 = wrow[kt2], w1 = wrow[kt2 + 1];
                float c0 = s_C[l * 48 + st3];
                float c1 = s_C[l * 48 + st3 + 1];
                float c2 = s_C[l * 48 + st3 + 2];
                hc00 += w0 * c0; hc01 += w0 * c1; hc02 += w0 * c2;
                hc10 += w1 * c0; hc11 += w1 * c1; hc12 += w1 * c2;
            }
        }
        {
            int l = tid >> 2, q = tid & 3;
            float cl[45];
            #pragma unroll
            for (int s = 0; s < 45; s++) cl[s] = s_C[l * 48 + s];
            const float* wrow = &tbw[(base + lbase + l) * 256 + 128];
            float part = 0.f;
            #pragma unroll
            for (int i = 0; i < 8; i++) {
                int k = q * 8 + i;
                float v = wrow[k];
                const float* wx = &s_wcx[k * 48];
                #pragma unroll
                for (int s = 0; s < 45; s++) v += wx[s] * cl[s];
                part += s_wp[k] * tanhf(v);
            }
            part += __shfl_down_sync(0xffffffffu, part, 2);
            part += __shfl_down_sync(0xffffffffu, part, 1);
            if (q == 0) s_ap[lbase + l] = part;
        }
    }
    __syncthreads();

    if (tid < 240) {
        float h;
        h = tanhf(s_wcx[kt2 * 48 + st3] + hc00);       atomicAdd(&s_ac[st3],     s_wc[kt2] * h);
        h = tanhf(s_wcx[kt2 * 48 + st3 + 1] + hc01);   atomicAdd(&s_ac[st3 + 1], s_wc[kt2] * h);
        h = tanhf(s_wcx[kt2 * 48 + st3 + 2] + hc02);   atomicAdd(&s_ac[st3 + 2], s_wc[kt2] * h);
        h = tanhf(s_wcx[(kt2+1) * 48 + st3] + hc10);     atomicAdd(&s_ac[st3],     s_wc[kt2+1] * h);
        h = tanhf(s_wcx[(kt2+1) * 48 + st3 + 1] + hc11); atomicAdd(&s_ac[st3 + 1], s_wc[kt2+1] * h);
        h = tanhf(s_wcx[(kt2+1) * 48 + st3 + 2] + hc12); atomicAdd(&s_ac[st3 + 2], s_wc[kt2+1] * h);
    }
    __syncthreads();

    float m1 = fmaxf(s_ap[tid], s_ap[tid + 256]);
    s_red[tid] = m1; __syncthreads();
    for (int o = 128; o > 0; o >>= 1) {
        if (tid < o) s_red[tid] = fmaxf(s_red[tid], s_red[tid + o]);
        __syncthreads();
    }
    float mx = s_red[0]; __syncthreads();
    float e1 = expf(s_ap[tid] - mx), e2 = expf(s_ap[tid + 256] - mx);
    s_ap[tid] = e1; s_ap[tid + 256] = e2;
    s_red[tid] = e1 + e2; __syncthreads();
    for (int o = 128; o > 0; o >>= 1) {
        if (tid < o) s_red[tid] += s_red[tid + o];
        __syncthreads();
    }
    if (tid == 0) s_scal[0] = 1.f / s_red[0];
    if (tid == 0) {
        float amx = -1e30f;
        for (int s = 0; s < MAXN; s++) amx = fmaxf(amx, s_ac[s]);
        float sum = 0.f;
        for (int s = 0; s < MAXN; s++) { float e = expf(s_ac[s] - amx); s_ac[s] = e; sum += e; }
        float inv = 1.f / sum;
        for (int s = 0; s < MAXN; s++) s_ac[s] *= inv;
    }
    __syncthreads();

    {
        int h = tid >> 7, m = tid & 127;
        float accp = 0.f;
        int l0 = h * 256;
        for (int l = 0; l < 256; l++)
            accp += s_ap[l0 + l] * t[(base + l0 + l) * 128 + m];
        s_red[tid] = accp;
        __syncthreads();
        if (h == 0) {
            float accc = 0.f;
            #pragma unroll
            for (int s = 0; s < MAXN; s++) accc += s_ac[s] * s_hd[s * PHD + m];
            cp[b * 256 + m] = accc;
            cp[b * 256 + 128 + m] = (s_red[m] + s_red[128 + m]) * s_scal[0];
        }
    }
}

// ---------------- final output ----------------
__global__ void out_kernel(const float* __restrict__ f2, const float* __restrict__ oW,
                           const float* __restrict__ ob, float* __restrict__ out) {
    int b = threadIdx.x;
    if (b < BGR) {
        float s = 0.f;
        for (int j = 0; j < 512; j += 4) {
            float4 a = *(const float4*)&f2[b * 512 + j];
            float4 w = *(const float4*)&oW[j];
            s += a.x * w.x + a.y * w.y + a.z * w.z + a.w * w.w;
        }
        out[b] = s + ob[0];
    }
}

// ---------------- host launcher ----------------
static float* sym_f(const void* s) { void* p = nullptr; cudaGetSymbolAddress(&p, s); return (float*)p; }
static int*   sym_i(const void* s) { void* p = nullptr; cudaGetSymbolAddress(&p, s); return (int*)p; }
static __nv_bfloat16* sym_b(const void* s) { void* p = nullptr; cudaGetSymbolAddress(&p, s); return (__nv_bfloat16*)p; }

extern "C" void kernel_launch(void* const* d_in, const int* in_sizes, int n_in,
                              void* d_out, int out_size)
{
    const float* x      = (const float*)d_in[0];
    const int*   ei     = (const int*)d_in[1];
    const int*   tgt    = (const int*)d_in[2];
    const int*   batch  = (const int*)d_in[3];
    const float* prot   = (const float*)d_in[4];
    const float* gW1 = (const float*)d_in[5],  *gb1 = (const float*)d_in[6];
    const float* gW2 = (const float*)d_in[7],  *gb2 = (const float*)d_in[8];
    const float* gW3 = (const float*)d_in[9],  *gb3 = (const float*)d_in[10];
    const float* fc1W = (const float*)d_in[11], *fc1b = (const float*)d_in[12];
    const float* fc2W = (const float*)d_in[13], *fc2b = (const float*)d_in[14];
    const float* b1W = (const float*)d_in[15],  *b1b = (const float*)d_in[16];
    const float* b2W = (const float*)d_in[17],  *b2b = (const float*)d_in[18];
    const float* W_b = (const float*)d_in[19];
    const float* W_c = (const float*)d_in[20];
    const float* W_p = (const float*)d_in[21];
    const float* w_hc = (const float*)d_in[22], *w_hp = (const float*)d_in[23];
    const float* c1W = (const float*)d_in[24], *c1b = (const float*)d_in[25];
    const float* c2W = (const float*)d_in[26], *c2b = (const float*)d_in[27];
    const float* oW  = (const float*)d_in[28], *ob  = (const float*)d_in[29];

    const int N = in_sizes[0] / 78;
    const int E = in_sizes[1] / 2;
    const int* src = ei;
    const int* dst = ei + E;

    float* deg   = sym_f(g_deg);
    float* coef  = sym_f(g_coef);
    float* xw    = sym_f(g_xw);
    float* hA    = sym_f(g_hA);
    float* hB    = sym_f(g_hB);
    float* h3    = sym_f(g_h3);
    int*   counts = sym_i(g_counts);
    int*   starts = sym_i(g_starts);
    float* dense = sym_f(g_dense);
    float* fc1o  = sym_f(g_fc1);
    float* hd    = sym_f(g_hd);
    int*   rowmap = sym_i(g_rowmap);
    float* t1    = sym_f(g_t1);
    float* t     = sym_f(g_t);
    float* tbw   = sym_f(g_tbw);
    float* cp    = sym_f(g_cp);
    float* f1    = sym_f(g_f1);
    float* f2    = sym_f(g_f2);
    int* Mdyn  = sym_i(g_Mdyn);
    int* bslot = sym_i(g_bslot);
    __nv_bfloat16* whi = sym_b(g_whi);
    __nv_bfloat16* wlo = sym_b(g_wlo);

    static cudaStream_t sB = 0;
    static cudaEvent_t evF = 0, evJ = 0;
    static int tried = 0;
    if (!tried) {
        tried = 1;
        if (cudaStreamCreateWithFlags(&sB, cudaStreamNonBlocking) != cudaSuccess) sB = 0;
        if (sB) {
            if (cudaEventCreateWithFlags(&evF, cudaEventDisableTiming) != cudaSuccess ||
                cudaEventCreateWithFlags(&evJ, cudaEventDisableTiming) != cudaSuccess) {
                sB = 0;
            }
        }
        cudaFuncSetAttribute(coattn_fused, cudaFuncAttributeMaxDynamicSharedMemorySize,
                             SM_FLOATS * 4 + 1024);
        cudaFuncSetAttribute(gemm_mma, cudaFuncAttributeMaxDynamicSharedMemorySize, GM_SMEM);
    }
    const bool fork = (sB != 0);
    cudaStream_t PS = fork ? sB : (cudaStream_t)0;

    dim3 t16(16, 16);

    // ---- prep + weight conversion (both branches depend) ----
    prep_all<<<1, 1024>>>(tgt, src, dst, batch, N, E,
                          bslot, rowmap, Mdyn, deg, coef, counts, starts);
    convert_w<<<(TOTALW + 255) / 256, 256>>>(b1W, b2W, W_b, W_p, gW2, gW3,
                                             fc1W, fc2W, c1W, c2W, whi, wlo);

    // ---- fork: protein branch ----
    if (fork) { cudaEventRecord(evF, 0); cudaStreamWaitEvent(sB, evF, 0); }
    gemm_mma<<<dim3(1, TROWS / 128), 256, GM_SMEM, PS>>>(prot, DPROT, rowmap,
        whi + WOFF_B1, wlo + WOFF_B1, b1b, t1, 128, Mdyn, DPROT, 1, 0, nullptr, nullptr, nullptr);
    gemm_mma<<<dim3(1, TROWS / 128), 256, GM_SMEM, PS>>>(t1, 128, nullptr,
        whi + WOFF_B2, wlo + WOFF_B2, b2b, t, 128, Mdyn, 128, 1, 0, nullptr, nullptr, nullptr);
    gemm_mma<<<dim3(2, TROWS / 128), 256, GM_SMEM, PS>>>(t, 128, nullptr,
        whi + WOFF_WC, wlo + WOFF_WC, nullptr, tbw, 256, Mdyn, 128, 0, 0, nullptr, nullptr, nullptr);
    if (fork) cudaEventRecord(evJ, sB);

    // ---- main branch: GCN stack ----
    sgemm64<<<dim3(2, (N + 63) / 64), t16>>>(x, 78, gW1, xw, N, 128, 78, hA, deg, gb1);
    gcn_scatter4<<<((long)E * 32 + 255) / 256, 256>>>(src, dst, coef, xw, hA, E, 32);

    gemm_mma<<<dim3(1, N / 128), 256, GM_SMEM>>>(hA, 128, nullptr,
        whi + WOFF_G2, wlo + WOFF_G2, nullptr, xw, 128, nullptr, 128, 0, 1, hB, deg, gb2);
    gcn_scatter4<<<((long)E * 32 + 255) / 256, 256>>>(src, dst, coef, xw, hB, E, 32);

    gemm_mma<<<dim3(2, N / 128), 256, GM_SMEM>>>(hB, 128, nullptr,
        whi + WOFF_G3, wlo + WOFF_G3, nullptr, xw, 256, nullptr, 128, 0, 1, h3, deg, gb3);
    gcn_scatter4<<<((long)E * 64 + 255) / 256, 256>>>(src, dst, coef, xw, h3, E, 64);

    dense_build<<<(BGR * MAXN * 64 + 255) / 256, 256>>>(h3, counts, starts, dense);
    const int MD = BGR * MAXN;  // 5760
    gemm_mma<<<dim3(8, MD / 128), 256, GM_SMEM>>>(dense, 256, nullptr,
        whi + WOFF_F1, wlo + WOFF_F1, fc1b, fc1o, 1024, nullptr, 256, 1, 0, nullptr, nullptr, nullptr);
    gemm_mma<<<dim3(1, MD / 128), 256, GM_SMEM>>>(fc1o, 1024, nullptr,
        whi + WOFF_F2, wlo + WOFF_F2, fc2b, hd, 128, nullptr, 1024, 1, 0, nullptr, nullptr, nullptr);

    // ---- join, fused co-attention ----
    if (fork) cudaStreamWaitEvent(0, evJ, 0);
    coattn_fused<<<BGR, 256, SM_FLOATS * 4 + 1024>>>(tbw, t, hd, W_c, w_hc, w_hp, bslot, cp);

    // ---- final MLP ----
    gemm_mma<<<dim3(8, 1), 256, GM_SMEM>>>(cp, 256, nullptr,
        whi + WOFF_C1, wlo + WOFF_C1, c1b, f1, 1024, nullptr, 256, 1, 0, nullptr, nullptr, nullptr);
    gemm_mma<<<dim3(4, 1), 256, GM_SMEM>>>(f1, 1024, nullptr,
        whi + WOFF_C2, wlo + WOFF_C2, c2b, f2, 512, nullptr, 1024, 1, 0, nullptr, nullptr, nullptr);
    out_kernel<<<1, 128>>>(f2, oW, ob, (float*)d_out);
}

// round 11
// speedup vs baseline: 1.5556x; 1.3957x over previous
#include <cuda_runtime.h>
#include <cuda_bf16.h>
#include <math.h>
#include <stdint.h>

// ---------------- problem constants ----------------
#define NNODES 5120
#define NEDGES 20000
#define BGR    128
#define MAXN   45
#define LPROT  512
#define DPROT  1280
#define NPROT  229
#define TROWS  (BGR*LPROT)   // 65536
#define MD     (BGR*MAXN)    // 5760

typedef unsigned long long u64;

// ---------------- converted-weight pool (bf16 hi/lo, [n][k] k-major) ----------------
#define SZ_B1 (1280*128)
#define SZ_B2 (128*128)
#define SZ_WC (256*128)
#define SZ_G2 (128*128)
#define SZ_G3 (256*128)
#define SZ_F1 (1024*256)
#define SZ_F2 (128*1024)
#define SZ_C1 (1024*256)
#define SZ_C2 (512*1024)
#define WOFF_B1 0
#define WOFF_B2 (WOFF_B1+SZ_B1)
#define WOFF_WC (WOFF_B2+SZ_B2)
#define WOFF_G2 (WOFF_WC+SZ_WC)
#define WOFF_G3 (WOFF_G2+SZ_G2)
#define WOFF_F1 (WOFF_G3+SZ_G3)
#define WOFF_F2 (WOFF_F1+SZ_F1)
#define WOFF_C1 (WOFF_F2+SZ_F2)
#define WOFF_C2 (WOFF_C1+SZ_C1)
#define TOTALW  (WOFF_C2+SZ_C2)

// ---------------- device scratch ----------------
__device__ float g_deg[NNODES];
__device__ float g_coef[NEDGES];
__device__ float g_xw[NNODES*256];
__device__ float g_hA[NNODES*128];
__device__ float g_hB[NNODES*128];
__device__ float g_h3[NNODES*256];
__device__ int   g_counts[BGR];
__device__ int   g_starts[BGR];
__device__ float g_hd[MD*128];
__device__ int   g_rowmap[TROWS];
__device__ float g_t[TROWS*128];
__device__ float g_tbw[(long)TROWS*256];   // [tb | WptT | pad]
__device__ float g_cp[BGR*256];
__device__ float g_f2[BGR*512];
__device__ int g_Mdyn[1];
__device__ int g_bslot[BGR];
__device__ __nv_bfloat16 g_whi[TOTALW];
__device__ __nv_bfloat16 g_wlo[TOTALW];
// activation hi/lo chains
__device__ __nv_bfloat16 g_t1h[TROWS*128], g_t1l[TROWS*128];
__device__ __nv_bfloat16 g_th[TROWS*128],  g_tl[TROWS*128];
__device__ __nv_bfloat16 g_dh[MD*256],     g_dl[MD*256];
__device__ __nv_bfloat16 g_fc1h[(long)MD*1024], g_fc1l[(long)MD*1024];
__device__ __nv_bfloat16 g_f1h[BGR*1024],  g_f1l[BGR*1024];

// ---------------- helpers ----------------
__device__ __forceinline__ unsigned su32(const void* p) {
    unsigned r;
    asm("{ .reg .u64 t; cvta.to.shared.u64 t, %1; cvt.u32.u64 %0, t; }" : "=r"(r) : "l"(p));
    return r;
}
__device__ __forceinline__ void ldsm4(unsigned* r, unsigned addr) {
    asm volatile("ldmatrix.sync.aligned.m8n8.x4.shared.b16 {%0,%1,%2,%3}, [%4];"
        : "=r"(r[0]), "=r"(r[1]), "=r"(r[2]), "=r"(r[3]) : "r"(addr));
}
__device__ __forceinline__ void ldsm2(unsigned* r, unsigned addr) {
    asm volatile("ldmatrix.sync.aligned.m8n8.x2.shared.b16 {%0,%1}, [%2];"
        : "=r"(r[0]), "=r"(r[1]) : "r"(addr));
}
__device__ __forceinline__ void mma16816(float* d, const unsigned* a, const unsigned* b) {
    asm volatile("mma.sync.aligned.m16n8k16.row.col.f32.bf16.bf16.f32 "
        "{%0,%1,%2,%3}, {%4,%5,%6,%7}, {%8,%9}, {%0,%1,%2,%3};"
        : "+f"(d[0]), "+f"(d[1]), "+f"(d[2]), "+f"(d[3])
        : "r"(a[0]), "r"(a[1]), "r"(a[2]), "r"(a[3]), "r"(b[0]), "r"(b[1]));
}
__device__ __forceinline__ unsigned bfpack(float a, float b) {
    __nv_bfloat162 h = __floats2bfloat162_rn(a, b);
    return *(unsigned*)&h;
}
__device__ __forceinline__ void cp16(unsigned dst, const void* src) {
    asm volatile("cp.async.ca.shared.global [%0], [%1], 16;" :: "r"(dst), "l"(src));
}
__device__ __forceinline__ void cp_commit() { asm volatile("cp.async.commit_group;"); }
__device__ __forceinline__ void cp_waitall() { asm volatile("cp.async.wait_all;" ::: "memory"); }
__device__ __forceinline__ void cp_wait1() { asm volatile("cp.async.wait_group 1;" ::: "memory"); }
__device__ __forceinline__ void cp_wait0g() { asm volatile("cp.async.wait_group 0;" ::: "memory"); }

__device__ __forceinline__ void split_store(float v, __nv_bfloat16* hi, __nv_bfloat16* lo, long off) {
    __nv_bfloat16 h = __float2bfloat16_rn(v);
    hi[off] = h;
    lo[off] = __float2bfloat16_rn(v - __bfloat162float(h));
}

// ---------------- weight conversion: fp32 [K][N] -> bf16 hi/lo [N][K] ----------------
__global__ void convert_w(
    const float* __restrict__ b1W, const float* __restrict__ b2W,
    const float* __restrict__ Wb,  const float* __restrict__ Wp,
    const float* __restrict__ gW2, const float* __restrict__ gW3,
    const float* __restrict__ fc1W, const float* __restrict__ fc2W,
    const float* __restrict__ c1W, const float* __restrict__ c2W,
    __nv_bfloat16* __restrict__ hi, __nv_bfloat16* __restrict__ lo)
{
    int i = blockIdx.x * 256 + threadIdx.x;
    if (i >= TOTALW) return;
    float v;
    if (i < WOFF_B2)      { int j = i;           int n = j / 1280, k = j % 1280; v = b1W[k * 128 + n]; }
    else if (i < WOFF_WC) { int j = i - WOFF_B2; int n = j >> 7,  k = j & 127;  v = b2W[k * 128 + n]; }
    else if (i < WOFF_G2) { int j = i - WOFF_WC; int n = j >> 7,  k = j & 127;
                            v = (n < 128) ? Wb[k * 128 + n] : ((n < 160) ? Wp[(n - 128) * 128 + k] : 0.f); }
    else if (i < WOFF_G3) { int j = i - WOFF_G2; int n = j >> 7,  k = j & 127;  v = gW2[k * 128 + n]; }
    else if (i < WOFF_F1) { int j = i - WOFF_G3; int n = j >> 7,  k = j & 127;  v = gW3[k * 256 + n]; }
    else if (i < WOFF_F2) { int j = i - WOFF_F1; int n = j >> 8,  k = j & 255;  v = fc1W[k * 1024 + n]; }
    else if (i < WOFF_C1) { int j = i - WOFF_F2; int n = j >> 10, k = j & 1023; v = fc2W[k * 128 + n]; }
    else if (i < WOFF_C2) { int j = i - WOFF_C1; int n = j >> 8,  k = j & 255;  v = c1W[k * 1024 + n]; }
    else                  { int j = i - WOFF_C2; int n = j >> 10, k = j & 1023; v = c2W[k * 512 + n]; }
    __nv_bfloat16 h = __float2bfloat16_rn(v);
    hi[i] = h;
    lo[i] = __float2bfloat16_rn(v - __bfloat162float(h));
}

#define GSTRIDE 72
#define GTILEB (128 * GSTRIDE * 2)
#define GM_SMEM_F32 (4 * GTILEB)
#define GM_SMEM_BF  (8 * GTILEB)

// =================================================================
// gemm_f32A: A fp32 (optional rowmap/preRelu), B pre-converted.
// Epilogue: C fp32 (opt), Chi/Clo bf16 (opt), C2 GCN dual (opt).
// =================================================================
__global__ __launch_bounds__(256) void gemm_f32A(
    const float* __restrict__ A, int lda, const int* __restrict__ rowmap,
    const __nv_bfloat16* __restrict__ Bhi, const __nv_bfloat16* __restrict__ Blo,
    const float* __restrict__ bias,
    float* __restrict__ C, __nv_bfloat16* __restrict__ Chi, __nv_bfloat16* __restrict__ Clo,
    int ldc, const int* __restrict__ Mdyn,
    int K, int act, int preRelu,
    float* __restrict__ C2, const float* __restrict__ degv,
    const float* __restrict__ bias2)
{
    const int m0 = blockIdx.y * 128;
    if (Mdyn && m0 >= *Mdyn) return;
    const int col0 = blockIdx.x * 128;
    const int tid = threadIdx.x;
    const int wid = tid >> 5, lane = tid & 31;
    const int warp_m = (wid >> 2) * 64;
    const int warp_n = (wid & 3) * 32;

    extern __shared__ char smraw[];
    char* sAh = smraw;
    char* sAl = smraw + GTILEB;
    char* sBh = smraw + 2 * GTILEB;
    char* sBl = smraw + 3 * GTILEB;
    const unsigned uAh = su32(sAh), uAl = su32(sAl);
    const unsigned uBh = su32(sBh), uBl = su32(sBl);

    const float* arow[8];
    int amq[8];
    #pragma unroll
    for (int i = 0; i < 8; i++) {
        int idx = tid + i * 256;
        int m = idx >> 4;
        int q = (idx & 15) << 2;
        int gr = m0 + m;
        int ar = rowmap ? rowmap[gr] : gr;
        arow[i] = A + (long)ar * lda + q;
        amq[i] = (m * GSTRIDE + q) * 2;
    }
    const __nv_bfloat16* bsrc_h[4];
    const __nv_bfloat16* bsrc_l[4];
    unsigned bdst[4];
    #pragma unroll
    for (int i = 0; i < 4; i++) {
        int idx = tid + i * 256;
        int n = idx >> 3;
        int k8 = (idx & 7) << 3;
        bsrc_h[i] = Bhi + (long)(col0 + n) * K + k8;
        bsrc_l[i] = Blo + (long)(col0 + n) * K + k8;
        bdst[i] = (n * GSTRIDE + k8) * 2;
    }

    float d[4][4][4];
    #pragma unroll
    for (int i = 0; i < 4; i++)
        #pragma unroll
        for (int j = 0; j < 4; j++)
            #pragma unroll
            for (int r = 0; r < 4; r++) d[i][j][r] = 0.f;

    const int a_row = lane & 15, a_half = (lane >> 4) * 8;
    const int b_row = lane & 7,  b_half = ((lane >> 3) & 1) * 8;

    const int kc = K >> 6;
    for (int c = 0; c < kc; c++) {
        #pragma unroll
        for (int i = 0; i < 4; i++) {
            cp16(uBh + bdst[i], bsrc_h[i] + (c << 6));
            cp16(uBl + bdst[i], bsrc_l[i] + (c << 6));
        }
        #pragma unroll
        for (int i = 0; i < 8; i++) {
            float4 v = *(const float4*)(arow[i] + (c << 6));
            if (preRelu) {
                v.x = fmaxf(v.x, 0.f); v.y = fmaxf(v.y, 0.f);
                v.z = fmaxf(v.z, 0.f); v.w = fmaxf(v.w, 0.f);
            }
            __nv_bfloat16 h0 = __float2bfloat16_rn(v.x), h1 = __float2bfloat16_rn(v.y);
            __nv_bfloat16 h2 = __float2bfloat16_rn(v.z), h3 = __float2bfloat16_rn(v.w);
            float l0 = v.x - __bfloat162float(h0), l1 = v.y - __bfloat162float(h1);
            float l2 = v.z - __bfloat162float(h2), l3 = v.w - __bfloat162float(h3);
            unsigned hp0 = ((unsigned)__bfloat16_as_ushort(h0)) | ((unsigned)__bfloat16_as_ushort(h1) << 16);
            unsigned hp1 = ((unsigned)__bfloat16_as_ushort(h2)) | ((unsigned)__bfloat16_as_ushort(h3) << 16);
            *(uint2*)(sAh + amq[i]) = make_uint2(hp0, hp1);
            *(uint2*)(sAl + amq[i]) = make_uint2(bfpack(l0, l1), bfpack(l2, l3));
        }
        cp_waitall();
        __syncthreads();
        #pragma unroll
        for (int ks = 0; ks < 4; ks++) {
            const int kb = ks * 16;
            unsigned ah[4][4], al[4][4], bh[4][2], bl[4][2];
            #pragma unroll
            for (int mt = 0; mt < 4; mt++) {
                int off = ((warp_m + mt * 16 + a_row) * GSTRIDE + kb + a_half) * 2;
                ldsm4(ah[mt], uAh + off);
                ldsm4(al[mt], uAl + off);
            }
            #pragma unroll
            for (int nt = 0; nt < 4; nt++) {
                int off = ((warp_n + nt * 8 + b_row) * GSTRIDE + kb + b_half) * 2;
                ldsm2(bh[nt], uBh + off);
                ldsm2(bl[nt], uBl + off);
            }
            #pragma unroll
            for (int mt = 0; mt < 4; mt++)
                #pragma unroll
                for (int nt = 0; nt < 4; nt++) {
                    mma16816(d[mt][nt], ah[mt], bh[nt]);
                    mma16816(d[mt][nt], ah[mt], bl[nt]);
                    mma16816(d[mt][nt], al[mt], bh[nt]);
                }
        }
        __syncthreads();
    }

    const int r0 = lane >> 2;
    const int c0 = (lane & 3) * 2;
    #pragma unroll
    for (int mt = 0; mt < 4; mt++) {
        int gmA = m0 + warp_m + mt * 16 + r0;
        int gmB = gmA + 8;
        float dgA = 1.f, dgB = 1.f;
        if (C2) { dgA = degv[gmA]; dgB = degv[gmB]; }
        #pragma unroll
        for (int nt = 0; nt < 4; nt++) {
            int gn = col0 + warp_n + nt * 8 + c0;
            float2 vA = make_float2(d[mt][nt][0], d[mt][nt][1]);
            float2 vB = make_float2(d[mt][nt][2], d[mt][nt][3]);
            if (C2) {
                *(float2*)&C2[(long)gmA * ldc + gn] =
                    make_float2(vA.x / dgA + bias2[gn], vA.y / dgA + bias2[gn + 1]);
                *(float2*)&C2[(long)gmB * ldc + gn] =
                    make_float2(vB.x / dgB + bias2[gn], vB.y / dgB + bias2[gn + 1]);
            }
            if (bias) {
                float b0 = bias[gn], b1 = bias[gn + 1];
                vA.x += b0; vA.y += b1; vB.x += b0; vB.y += b1;
            }
            if (act == 1) {
                vA.x = fmaxf(vA.x, 0.f); vA.y = fmaxf(vA.y, 0.f);
                vB.x = fmaxf(vB.x, 0.f); vB.y = fmaxf(vB.y, 0.f);
            } else if (act == 2) {
                vA.x = tanhf(vA.x); vA.y = tanhf(vA.y);
                vB.x = tanhf(vB.x); vB.y = tanhf(vB.y);
            }
            if (C) {
                *(float2*)&C[(long)gmA * ldc + gn] = vA;
                *(float2*)&C[(long)gmB * ldc + gn] = vB;
            }
            if (Chi) {
                split_store(vA.x, Chi, Clo, (long)gmA * ldc + gn);
                split_store(vA.y, Chi, Clo, (long)gmA * ldc + gn + 1);
                split_store(vB.x, Chi, Clo, (long)gmB * ldc + gn);
                split_store(vB.y, Chi, Clo, (long)gmB * ldc + gn + 1);
            }
        }
    }
}

// =================================================================
// gemm_bfA: A pre-converted bf16 hi/lo [M][K]; all cp.async,
// double-buffered. Epilogue same options.
// =================================================================
__global__ __launch_bounds__(256) void gemm_bfA(
    const __nv_bfloat16* __restrict__ Ahi, const __nv_bfloat16* __restrict__ Alo, int lda,
    const __nv_bfloat16* __restrict__ Bhi, const __nv_bfloat16* __restrict__ Blo,
    const float* __restrict__ bias,
    float* __restrict__ C, __nv_bfloat16* __restrict__ Chi, __nv_bfloat16* __restrict__ Clo,
    int ldc, const int* __restrict__ Mdyn, int K, int act)
{
    const int m0 = blockIdx.y * 128;
    if (Mdyn && m0 >= *Mdyn) return;
    const int col0 = blockIdx.x * 128;
    const int tid = threadIdx.x;
    const int wid = tid >> 5, lane = tid & 31;
    const int warp_m = (wid >> 2) * 64;
    const int warp_n = (wid & 3) * 32;

    extern __shared__ char smraw[];
    // slot layout: [Ah Al Bh Bl] x2
    const unsigned base0 = su32(smraw);
    const unsigned base1 = base0 + 4 * GTILEB;

    // per-thread chunk descriptors (4 per array)
    const __nv_bfloat16 *ah_s[4], *al_s[4], *bh_s[4], *bl_s[4];
    unsigned doff[4];
    #pragma unroll
    for (int i = 0; i < 4; i++) {
        int idx = tid + i * 256;
        int r = idx >> 3;
        int k8 = (idx & 7) << 3;
        ah_s[i] = Ahi + (long)(m0 + r) * lda + k8;
        al_s[i] = Alo + (long)(m0 + r) * lda + k8;
        bh_s[i] = Bhi + (long)(col0 + r) * K + k8;
        bl_s[i] = Blo + (long)(col0 + r) * K + k8;
        doff[i] = (r * GSTRIDE + k8) * 2;
    }

    float d[4][4][4];
    #pragma unroll
    for (int i = 0; i < 4; i++)
        #pragma unroll
        for (int j = 0; j < 4; j++)
            #pragma unroll
            for (int r = 0; r < 4; r++) d[i][j][r] = 0.f;

    const int a_row = lane & 15, a_half = (lane >> 4) * 8;
    const int b_row = lane & 7,  b_half = ((lane >> 3) & 1) * 8;
    const int kc = K >> 6;

    // prologue: chunk 0 -> slot 0
    #pragma unroll
    for (int i = 0; i < 4; i++) {
        cp16(base0 + doff[i], ah_s[i]);
        cp16(base0 + GTILEB + doff[i], al_s[i]);
        cp16(base0 + 2 * GTILEB + doff[i], bh_s[i]);
        cp16(base0 + 3 * GTILEB + doff[i], bl_s[i]);
    }
    cp_commit();

    for (int c = 0; c < kc; c++) {
        const unsigned cur = (c & 1) ? base1 : base0;
        if (c + 1 < kc) {
            const unsigned nxt = (c & 1) ? base0 : base1;
            const int kof = (c + 1) << 6;
            #pragma unroll
            for (int i = 0; i < 4; i++) {
                cp16(nxt + doff[i], ah_s[i] + kof);
                cp16(nxt + GTILEB + doff[i], al_s[i] + kof);
                cp16(nxt + 2 * GTILEB + doff[i], bh_s[i] + kof);
                cp16(nxt + 3 * GTILEB + doff[i], bl_s[i] + kof);
            }
            cp_commit();
            cp_wait1();
        } else {
            cp_wait0g();
        }
        __syncthreads();
        const unsigned uAh = cur, uAl = cur + GTILEB;
        const unsigned uBh = cur + 2 * GTILEB, uBl = cur + 3 * GTILEB;
        #pragma unroll
        for (int ks = 0; ks < 4; ks++) {
            const int kb = ks * 16;
            unsigned ah[4][4], al[4][4], bh[4][2], bl[4][2];
            #pragma unroll
            for (int mt = 0; mt < 4; mt++) {
                int off = ((warp_m + mt * 16 + a_row) * GSTRIDE + kb + a_half) * 2;
                ldsm4(ah[mt], uAh + off);
                ldsm4(al[mt], uAl + off);
            }
            #pragma unroll
            for (int nt = 0; nt < 4; nt++) {
                int off = ((warp_n + nt * 8 + b_row) * GSTRIDE + kb + b_half) * 2;
                ldsm2(bh[nt], uBh + off);
                ldsm2(bl[nt], uBl + off);
            }
            #pragma unroll
            for (int mt = 0; mt < 4; mt++)
                #pragma unroll
                for (int nt = 0; nt < 4; nt++) {
                    mma16816(d[mt][nt], ah[mt], bh[nt]);
                    mma16816(d[mt][nt], ah[mt], bl[nt]);
                    mma16816(d[mt][nt], al[mt], bh[nt]);
                }
        }
        __syncthreads();
    }

    const int r0 = lane >> 2;
    const int c0 = (lane & 3) * 2;
    #pragma unroll
    for (int mt = 0; mt < 4; mt++) {
        int gmA = m0 + warp_m + mt * 16 + r0;
        int gmB = gmA + 8;
        #pragma unroll
        for (int nt = 0; nt < 4; nt++) {
            int gn = col0 + warp_n + nt * 8 + c0;
            float2 vA = make_float2(d[mt][nt][0], d[mt][nt][1]);
            float2 vB = make_float2(d[mt][nt][2], d[mt][nt][3]);
            if (bias) {
                float b0 = bias[gn], b1 = bias[gn + 1];
                vA.x += b0; vA.y += b1; vB.x += b0; vB.y += b1;
            }
            if (act == 1) {
                vA.x = fmaxf(vA.x, 0.f); vA.y = fmaxf(vA.y, 0.f);
                vB.x = fmaxf(vB.x, 0.f); vB.y = fmaxf(vB.y, 0.f);
            } else if (act == 2) {
                vA.x = tanhf(vA.x); vA.y = tanhf(vA.y);
                vB.x = tanhf(vB.x); vB.y = tanhf(vB.y);
            }
            if (C) {
                *(float2*)&C[(long)gmA * ldc + gn] = vA;
                *(float2*)&C[(long)gmB * ldc + gn] = vB;
            }
            if (Chi) {
                split_store(vA.x, Chi, Clo, (long)gmA * ldc + gn);
                split_store(vA.y, Chi, Clo, (long)gmA * ldc + gn + 1);
                split_store(vB.x, Chi, Clo, (long)gmB * ldc + gn);
                split_store(vB.y, Chi, Clo, (long)gmB * ldc + gn + 1);
            }
        }
    }
}

// ---------------- generic SGEMM (GCN layer 1, K=78) ----------------
__global__ __launch_bounds__(256) void sgemm64(
    const float* __restrict__ A, int lda,
    const float* __restrict__ B, float* __restrict__ C,
    int M, int N, int K,
    float* __restrict__ C2, const float* __restrict__ degv,
    const float* __restrict__ bias2)
{
    __shared__ float As[16][64];
    __shared__ float Bs[16][68];
    const int tid = threadIdx.y * 16 + threadIdx.x;
    const int m0 = blockIdx.y * 64;
    const int n0 = blockIdx.x * 64;
    float acc[4][4] = {};
    for (int kt = 0; kt < K; kt += 16) {
        #pragma unroll
        for (int i = tid; i < 64 * 16; i += 256) {
            int m = i >> 4, kk = i & 15;
            int gm = m0 + m, gk = kt + kk;
            float v = 0.f;
            if (gm < M && gk < K) v = A[(long)gm * lda + gk];
            As[kk][m] = v;
        }
        #pragma unroll
        for (int i = tid; i < 16 * 64; i += 256) {
            int kk = i >> 6, n = i & 63;
            int gk = kt + kk, gn = n0 + n;
            Bs[kk][n] = (gk < K && gn < N) ? B[(long)gk * N + gn] : 0.f;
        }
        __syncthreads();
        #pragma unroll
        for (int kk = 0; kk < 16; kk++) {
            float a[4];
            #pragma unroll
            for (int i = 0; i < 4; i++) a[i] = As[kk][threadIdx.y * 4 + i];
            float4 b4 = *(const float4*)&Bs[kk][threadIdx.x * 4];
            float bv[4] = { b4.x, b4.y, b4.z, b4.w };
            #pragma unroll
            for (int i = 0; i < 4; i++)
                #pragma unroll
                for (int j = 0; j < 4; j++) acc[i][j] += a[i] * bv[j];
        }
        __syncthreads();
    }
    #pragma unroll
    for (int i = 0; i < 4; i++) {
        int gm = m0 + threadIdx.y * 4 + i;
        if (gm >= M) continue;
        #pragma unroll
        for (int j = 0; j < 4; j++) {
            int gn = n0 + threadIdx.x * 4 + j;
            if (gn >= N) continue;
            float v = acc[i][j];
            if (C2) C2[(long)gm * N + gn] = v / degv[gm] + bias2[gn];
            C[(long)gm * N + gn] = v;
        }
    }
}

// ---------------- prep_all ----------------
__global__ __launch_bounds__(1024) void prep_all(
    const int* __restrict__ tgt, const int* __restrict__ src,
    const int* __restrict__ dst, const int* __restrict__ batch,
    int n, int E,
    int* bslot, int* rowmap, int* Mdyn,
    float* deg, float* coef, int* counts, int* starts)
{
    __shared__ float sdeg[NNODES];
    __shared__ int flag[NPROT];
    __shared__ int slot[NPROT];
    __shared__ int uniq[BGR];
    __shared__ int cbin[BGR];
    __shared__ int nu_s;
    const int tid = threadIdx.x;

    for (int i = tid; i < n; i += 1024) sdeg[i] = 1.0f;
    if (tid < NPROT) flag[tid] = 0;
    if (tid < BGR) cbin[tid] = 0;
    __syncthreads();
    if (tid < BGR) flag[tgt[tid]] = 1;
    for (int e = tid; e < E; e += 1024) atomicAdd(&sdeg[dst[e]], 1.0f);
    for (int i = tid; i < n; i += 1024) atomicAdd(&cbin[batch[i]], 1);
    __syncthreads();
    if (tid == 0) {
        int s = 0;
        for (int p = 0; p < NPROT; p++) {
            if (flag[p]) { slot[p] = s; uniq[s] = p; s++; }
            else slot[p] = -1;
        }
        nu_s = s;
        Mdyn[0] = s * LPROT;
    } else if (tid == 32) {
        int s = 0;
        for (int b = 0; b < BGR; b++) { starts[b] = s; counts[b] = cbin[b]; s += cbin[b]; }
    }
    __syncthreads();
    if (tid < BGR) bslot[tid] = slot[tgt[tid]];
    for (int i = tid; i < n; i += 1024) deg[i] = sdeg[i];
    for (int e = tid; e < E; e += 1024)
        coef[e] = rsqrtf(sdeg[src[e]]) * rsqrtf(sdeg[dst[e]]);
    int nu = nu_s;
    for (int r = tid; r < TROWS; r += 1024) {
        int s = r >> 9;
        rowmap[r] = (s < nu) ? (uniq[s] * LPROT + (r & (LPROT - 1))) : 0;
    }
}

// ---------------- GCN scatter (float4) ----------------
__global__ void gcn_scatter4(const int* __restrict__ src, const int* __restrict__ dst,
                             const float* __restrict__ coef, const float* __restrict__ xw,
                             float* out, int E, int F4) {
    long i = (long)blockIdx.x * blockDim.x + threadIdx.x;
    if (i >= (long)E * F4) return;
    int e = (int)(i / F4);
    int f = (int)(i - (long)e * F4) * 4;
    float c = coef[e];
    int s = src[e], d = dst[e];
    const int F = F4 * 4;
    float4 v = *(const float4*)&xw[(long)s * F + f];
    float* o = &out[(long)d * F + f];
    atomicAdd(o + 0, v.x * c);
    atomicAdd(o + 1, v.y * c);
    atomicAdd(o + 2, v.z * c);
    atomicAdd(o + 3, v.w * c);
}

// ---------------- to_dense_batch gather -> bf16 hi/lo ----------------
__global__ void dense_build(const float* __restrict__ h3,
                            const int* __restrict__ counts,
                            const int* __restrict__ starts,
                            __nv_bfloat16* __restrict__ dh,
                            __nv_bfloat16* __restrict__ dl) {
    int i = blockIdx.x * blockDim.x + threadIdx.x;
    if (i >= MD * 64) return;
    int b = i / (MAXN * 64);
    int rem = i - b * (MAXN * 64);
    int pos = rem >> 6, f4 = rem & 63;
    float4 v = make_float4(0.f, 0.f, 0.f, 0.f);
    if (pos < counts[b]) {
        v = ((const float4*)(h3 + (long)(starts[b] + pos) * 256))[f4];
        v.x = fmaxf(v.x, 0.f); v.y = fmaxf(v.y, 0.f);
        v.z = fmaxf(v.z, 0.f); v.w = fmaxf(v.w, 0.f);
    }
    long off = (long)i * 4;
    split_store(v.x, dh, dl, off + 0);
    split_store(v.y, dh, dl, off + 1);
    split_store(v.z, dh, dl, off + 2);
    split_store(v.w, dh, dl, off + 3);
}

// =================================================================
// FUSED CO-ATTENTION (unchanged)
// =================================================================
#define PHD 132
#define OFF_HD   0
#define OFF_WCX  (OFF_HD + 45*PHD)
#define OFF_C    (OFF_WCX + 32*48)
#define OFF_TB   (OFF_C + 64*48)
#define OFF_AP   (OFF_TB + 64*PHD)
#define OFF_AC   (OFF_AP + 512)
#define OFF_RED  (OFF_AC + 48)
#define OFF_WC   (OFF_RED + 256)
#define OFF_WP   (OFF_WC + 32)
#define OFF_SCAL (OFF_WP + 32)
#define SM_FLOATS (OFF_SCAL + 4)

__global__ __launch_bounds__(256) void coattn_fused(
    const float* __restrict__ tbw, const float* __restrict__ t,
    const float* __restrict__ hd, const float* __restrict__ Wc_g,
    const float* __restrict__ whc, const float* __restrict__ whp,
    const int* __restrict__ bslot, float* __restrict__ cp)
{
    extern __shared__ float sm[];
    float* s_hd  = sm + OFF_HD;
    float* s_wcx = sm + OFF_WCX;
    float* s_C   = sm + OFF_C;
    float* s_tb  = sm + OFF_TB;
    float* s_ap  = sm + OFF_AP;
    float* s_ac  = sm + OFF_AC;
    float* s_red = sm + OFF_RED;
    float* s_wc  = sm + OFF_WC;
    float* s_wp  = sm + OFF_WP;
    float* s_scal= sm + OFF_SCAL;

    const int b = blockIdx.x;
    const int tid = threadIdx.x;
    const long base = (long)bslot[b] * LPROT;
    const float* hd_b = hd + (long)b * MAXN * 128;

    for (int idx = tid; idx < MAXN * 32; idx += 256) {
        int s = idx >> 5, v4 = (idx & 31) * 4;
        *(float4*)&s_hd[s * PHD + v4] = *(const float4*)&hd_b[s * 128 + v4];
    }
    if (tid < 32) { s_wc[tid] = whc[tid]; s_wp[tid] = whp[tid]; }
    if (tid < 48) s_ac[tid] = 0.f;
    __syncthreads();

    for (int idx = tid; idx < 32 * MAXN; idx += 256) {
        int k = idx / MAXN, s = idx - k * MAXN;
        float acc = 0.f;
        #pragma unroll
        for (int kk = 0; kk < 32; kk++) {
            float4 a = *(const float4*)&Wc_g[k * 128 + kk * 4];
            float4 h4 = *(const float4*)&s_hd[s * PHD + kk * 4];
            acc += a.x * h4.x + a.y * h4.y + a.z * h4.z + a.w * h4.w;
        }
        s_wcx[k * 48 + s] = acc;
    }

    const int kt2 = (tid / 15) * 2;
    const int st3 = (tid % 15) * 3;
    float hc00 = 0.f, hc01 = 0.f, hc02 = 0.f, hc10 = 0.f, hc11 = 0.f, hc12 = 0.f;

    for (int cc = 0; cc < 8; cc++) {
        const int lbase = cc * 64;
        __syncthreads();
        for (int idx = tid; idx < 64 * 32; idx += 256) {
            int l = idx >> 5, v4 = (idx & 31) * 4;
            *(float4*)&s_tb[l * PHD + v4] =
                *(const float4*)&tbw[(base + lbase + l) * 256 + v4];
        }
        __syncthreads();
        if (tid < 240) {
            int lt = (tid / 15) * 4;
            float ca[4][3] = {};
            #pragma unroll 8
            for (int kk = 0; kk < 32; kk++) {
                float4 a0 = *(const float4*)&s_tb[(lt + 0) * PHD + kk * 4];
                float4 a1 = *(const float4*)&s_tb[(lt + 1) * PHD + kk * 4];
                float4 a2 = *(const float4*)&s_tb[(lt + 2) * PHD + kk * 4];
                float4 a3 = *(const float4*)&s_tb[(lt + 3) * PHD + kk * 4];
                float4 h0 = *(const float4*)&s_hd[(st3 + 0) * PHD + kk * 4];
                float4 h1 = *(const float4*)&s_hd[(st3 + 1) * PHD + kk * 4];
                float4 h2 = *(const float4*)&s_hd[(st3 + 2) * PHD + kk * 4];
                ca[0][0] += a0.x*h0.x + a0.y*h0.y + a0.z*h0.z + a0.w*h0.w;
                ca[0][1] += a0.x*h1.x + a0.y*h1.y + a0.z*h1.z + a0.w*h1.w;
                ca[0][2] += a0.x*h2.x + a0.y*h2.y + a0.z*h2.z + a0.w*h2.w;
                ca[1][0] += a1.x*h0.x + a1.y*h0.y + a1.z*h0.z + a1.w*h0.w;
                ca[1][1] += a1.x*h1.x + a1.y*h1.y + a1.z*h1.z + a1.w*h1.w;
                ca[1][2] += a1.x*h2.x + a1.y*h2.y + a1.z*h2.z + a1.w*h2.w;
                ca[2][0] += a2.x*h0.x + a2.y*h0.y + a2.z*h0.z + a2.w*h0.w;
                ca[2][1] += a2.x*h1.x + a2.y*h1.y + a2.z*h1.z + a2.w*h1.w;
                ca[2][2] += a2.x*h2.x + a2.y*h2.y + a2.z*h2.z + a2.w*h2.w;
                ca[3][0] += a3.x*h0.x + a3.y*h0.y + a3.z*h0.z + a3.w*h0.w;
                ca[3][1] += a3.x*h1.x + a3.y*h1.y + a3.z*h1.z + a3.w*h1.w;
                ca[3][2] += a3.x*h2.x + a3.y*h2.y + a3.z*h2.z + a3.w*h2.w;
            }
            #pragma unroll
            for (int i = 0; i < 4; i++)
                #pragma unroll
                for (int j = 0; j < 3; j++)
                    s_C[(lt + i) * 48 + st3 + j] = tanhf(ca[i][j]);
        }
        __syncthreads();
        if (tid < 240) {
            for (int l = 0; l < 64; l++) {
                const float* wrow = &tbw[(base + lbase + l) * 256 + 128];
                float w0 = wrow[kt2], w1 = wrow[kt2 + 1];
                float c0 = s_C[l * 48 + st3];
                float c1 = s_C[l * 48 + st3 + 1];
                float c2 = s_C[l * 48 + st3 + 2];
                hc00 += w0 * c0; hc01 += w0 * c1; hc02 += w0 * c2;
                hc10 += w1 * c0; hc11 += w1 * c1; hc12 += w1 * c2;
            }
        }
        {
            int l = tid >> 2, q = tid & 3;
            float cl[45];
            #pragma unroll
            for (int s = 0; s < 45; s++) cl[s] = s_C[l * 48 + s];
            const float* wrow = &tbw[(base + lbase + l) * 256 + 128];
            float part = 0.f;
            #pragma unroll
            for (int i = 0; i < 8; i++) {
                int k = q * 8 + i;
                float v = wrow[k];
                const float* wx = &s_wcx[k * 48];
                #pragma unroll
                for (int s = 0; s < 45; s++) v += wx[s] * cl[s];
                part += s_wp[k] * tanhf(v);
            }
            part += __shfl_down_sync(0xffffffffu, part, 2);
            part += __shfl_down_sync(0xffffffffu, part, 1);
            if (q == 0) s_ap[lbase + l] = part;
        }
    }
    __syncthreads();

    if (tid < 240) {
        float h;
        h = tanhf(s_wcx[kt2 * 48 + st3] + hc00);       atomicAdd(&s_ac[st3],     s_wc[kt2] * h);
        h = tanhf(s_wcx[kt2 * 48 + st3 + 1] + hc01);   atomicAdd(&s_ac[st3 + 1], s_wc[kt2] * h);
        h = tanhf(s_wcx[kt2 * 48 + st3 + 2] + hc02);   atomicAdd(&s_ac[st3 + 2], s_wc[kt2] * h);
        h = tanhf(s_wcx[(kt2+1) * 48 + st3] + hc10);     atomicAdd(&s_ac[st3],     s_wc[kt2+1] * h);
        h = tanhf(s_wcx[(kt2+1) * 48 + st3 + 1] + hc11); atomicAdd(&s_ac[st3 + 1], s_wc[kt2+1] * h);
        h = tanhf(s_wcx[(kt2+1) * 48 + st3 + 2] + hc12); atomicAdd(&s_ac[st3 + 2], s_wc[kt2+1] * h);
    }
    __syncthreads();

    float m1 = fmaxf(s_ap[tid], s_ap[tid + 256]);
    s_red[tid] = m1; __syncthreads();
    for (int o = 128; o > 0; o >>= 1) {
        if (tid < o) s_red[tid] = fmaxf(s_red[tid], s_red[tid + o]);
        __syncthreads();
    }
    float mx = s_red[0]; __syncthreads();
    float e1 = expf(s_ap[tid] - mx), e2 = expf(s_ap[tid + 256] - mx);
    s_ap[tid] = e1; s_ap[tid + 256] = e2;
    s_red[tid] = e1 + e2; __syncthreads();
    for (int o = 128; o > 0; o >>= 1) {
        if (tid < o) s_red[tid] += s_red[tid + o];
        __syncthreads();
    }
    if (tid == 0) s_scal[0] = 1.f / s_red[0];
    if (tid == 0) {
        float amx = -1e30f;
        for (int s = 0; s < MAXN; s++) amx = fmaxf(amx, s_ac[s]);
        float sum = 0.f;
        for (int s = 0; s < MAXN; s++) { float e = expf(s_ac[s] - amx); s_ac[s] = e; sum += e; }
        float inv = 1.f / sum;
        for (int s = 0; s < MAXN; s++) s_ac[s] *= inv;
    }
    __syncthreads();

    {
        int h = tid >> 7, m = tid & 127;
        float accp = 0.f;
        int l0 = h * 256;
        for (int l = 0; l < 256; l++)
            accp += s_ap[l0 + l] * t[(base + l0 + l) * 128 + m];
        s_red[tid] = accp;
        __syncthreads();
        if (h == 0) {
            float accc = 0.f;
            #pragma unroll
            for (int s = 0; s < MAXN; s++) accc += s_ac[s] * s_hd[s * PHD + m];
            cp[b * 256 + m] = accc;
            cp[b * 256 + 128 + m] = (s_red[m] + s_red[128 + m]) * s_scal[0];
        }
    }
}

// ---------------- final output ----------------
__global__ void out_kernel(const float* __restrict__ f2, const float* __restrict__ oW,
                           const float* __restrict__ ob, float* __restrict__ out) {
    int b = threadIdx.x;
    if (b < BGR) {
        float s = 0.f;
        for (int j = 0; j < 512; j += 4) {
            float4 a = *(const float4*)&f2[b * 512 + j];
            float4 w = *(const float4*)&oW[j];
            s += a.x * w.x + a.y * w.y + a.z * w.z + a.w * w.w;
        }
        out[b] = s + ob[0];
    }
}

// ---------------- host launcher ----------------
static float* sym_f(const void* s) { void* p = nullptr; cudaGetSymbolAddress(&p, s); return (float*)p; }
static int*   sym_i(const void* s) { void* p = nullptr; cudaGetSymbolAddress(&p, s); return (int*)p; }
static __nv_bfloat16* sym_b(const void* s) { void* p = nullptr; cudaGetSymbolAddress(&p, s); return (__nv_bfloat16*)p; }

extern "C" void kernel_launch(void* const* d_in, const int* in_sizes, int n_in,
                              void* d_out, int out_size)
{
    const float* x      = (const float*)d_in[0];
    const int*   ei     = (const int*)d_in[1];
    const int*   tgt    = (const int*)d_in[2];
    const int*   batch  = (const int*)d_in[3];
    const float* prot   = (const float*)d_in[4];
    const float* gW1 = (const float*)d_in[5],  *gb1 = (const float*)d_in[6];
    const float* gW2 = (const float*)d_in[7],  *gb2 = (const float*)d_in[8];
    const float* gW3 = (const float*)d_in[9],  *gb3 = (const float*)d_in[10];
    const float* fc1W = (const float*)d_in[11], *fc1b = (const float*)d_in[12];
    const float* fc2W = (const float*)d_in[13], *fc2b = (const float*)d_in[14];
    const float* b1W = (const float*)d_in[15],  *b1b = (const float*)d_in[16];
    const float* b2W = (const float*)d_in[17],  *b2b = (const float*)d_in[18];
    const float* W_b = (const float*)d_in[19];
    const float* W_c = (const float*)d_in[20];
    const float* W_p = (const float*)d_in[21];
    const float* w_hc = (const float*)d_in[22], *w_hp = (const float*)d_in[23];
    const float* c1W = (const float*)d_in[24], *c1b = (const float*)d_in[25];
    const float* c2W = (const float*)d_in[26], *c2b = (const float*)d_in[27];
    const float* oW  = (const float*)d_in[28], *ob  = (const float*)d_in[29];

    const int N = in_sizes[0] / 78;
    const int E = in_sizes[1] / 2;
    const int* src = ei;
    const int* dst = ei + E;

    float* deg   = sym_f(g_deg);
    float* coef  = sym_f(g_coef);
    float* xw    = sym_f(g_xw);
    float* hA    = sym_f(g_hA);
    float* hB    = sym_f(g_hB);
    float* h3    = sym_f(g_h3);
    int*   counts = sym_i(g_counts);
    int*   starts = sym_i(g_starts);
    float* hd    = sym_f(g_hd);
    int*   rowmap = sym_i(g_rowmap);
    float* t     = sym_f(g_t);
    float* tbw   = sym_f(g_tbw);
    float* cp    = sym_f(g_cp);
    float* f2    = sym_f(g_f2);
    int* Mdyn  = sym_i(g_Mdyn);
    int* bslot = sym_i(g_bslot);
    __nv_bfloat16* whi = sym_b(g_whi);
    __nv_bfloat16* wlo = sym_b(g_wlo);
    __nv_bfloat16* t1h = sym_b(g_t1h), *t1l = sym_b(g_t1l);
    __nv_bfloat16* th  = sym_b(g_th),  *tl  = sym_b(g_tl);
    __nv_bfloat16* dh  = sym_b(g_dh),  *dl  = sym_b(g_dl);
    __nv_bfloat16* fc1h = sym_b(g_fc1h), *fc1l = sym_b(g_fc1l);
    __nv_bfloat16* f1h = sym_b(g_f1h), *f1l = sym_b(g_f1l);

    static cudaStream_t sB = 0;
    static cudaEvent_t evF = 0, evJ = 0;
    static int tried = 0;
    if (!tried) {
        tried = 1;
        if (cudaStreamCreateWithFlags(&sB, cudaStreamNonBlocking) != cudaSuccess) sB = 0;
        if (sB) {
            if (cudaEventCreateWithFlags(&evF, cudaEventDisableTiming) != cudaSuccess ||
                cudaEventCreateWithFlags(&evJ, cudaEventDisableTiming) != cudaSuccess) {
                sB = 0;
            }
        }
        cudaFuncSetAttribute(coattn_fused, cudaFuncAttributeMaxDynamicSharedMemorySize,
                             SM_FLOATS * 4 + 1024);
        cudaFuncSetAttribute(gemm_f32A, cudaFuncAttributeMaxDynamicSharedMemorySize, GM_SMEM_F32);
        cudaFuncSetAttribute(gemm_bfA, cudaFuncAttributeMaxDynamicSharedMemorySize, GM_SMEM_BF);
    }
    const bool fork = (sB != 0);
    cudaStream_t PS = fork ? sB : (cudaStream_t)0;

    dim3 t16(16, 16);

    // ---- prep + weight conversion ----
    prep_all<<<1, 1024>>>(tgt, src, dst, batch, N, E,
                          bslot, rowmap, Mdyn, deg, coef, counts, starts);
    convert_w<<<(TOTALW + 255) / 256, 256>>>(b1W, b2W, W_b, W_p, gW2, gW3,
                                             fc1W, fc2W, c1W, c2W, whi, wlo);

    // ---- fork: protein branch ----
    if (fork) { cudaEventRecord(evF, 0); cudaStreamWaitEvent(sB, evF, 0); }
    // bert1: prot (fp32 gather) -> t1 hi/lo
    gemm_f32A<<<dim3(1, TROWS / 128), 256, GM_SMEM_F32, PS>>>(prot, DPROT, rowmap,
        whi + WOFF_B1, wlo + WOFF_B1, b1b, nullptr, t1h, t1l, 128, Mdyn, DPROT, 1, 0, nullptr, nullptr, nullptr);
    // bert2: t1 hi/lo -> t fp32 + t hi/lo
    gemm_bfA<<<dim3(1, TROWS / 128), 256, GM_SMEM_BF, PS>>>(t1h, t1l, 128,
        whi + WOFF_B2, wlo + WOFF_B2, b2b, t, th, tl, 128, Mdyn, 128, 1);
    // tbw: t hi/lo -> tbw fp32 (N=256)
    gemm_bfA<<<dim3(2, TROWS / 128), 256, GM_SMEM_BF, PS>>>(th, tl, 128,
        whi + WOFF_WC, wlo + WOFF_WC, nullptr, tbw, nullptr, nullptr, 256, Mdyn, 128, 0);
    if (fork) cudaEventRecord(evJ, sB);

    // ---- main branch: GCN stack ----
    sgemm64<<<dim3(2, (N + 63) / 64), t16>>>(x, 78, gW1, xw, N, 128, 78, hA, deg, gb1);
    gcn_scatter4<<<((long)E * 32 + 255) / 256, 256>>>(src, dst, coef, xw, hA, E, 32);

    gemm_f32A<<<dim3(1, N / 128), 256, GM_SMEM_F32>>>(hA, 128, nullptr,
        whi + WOFF_G2, wlo + WOFF_G2, nullptr, xw, nullptr, nullptr, 128, nullptr, 128, 0, 1, hB, deg, gb2);
    gcn_scatter4<<<((long)E * 32 + 255) / 256, 256>>>(src, dst, coef, xw, hB, E, 32);

    gemm_f32A<<<dim3(2, N / 128), 256, GM_SMEM_F32>>>(hB, 128, nullptr,
        whi + WOFF_G3, wlo + WOFF_G3, nullptr, xw, nullptr, nullptr, 256, nullptr, 128, 0, 1, h3, deg, gb3);
    gcn_scatter4<<<((long)E * 64 + 255) / 256, 256>>>(src, dst, coef, xw, h3, E, 64);

    // dense (relu fused) -> bf16 hi/lo
    dense_build<<<(MD * 64 + 255) / 256, 256>>>(h3, counts, starts, dh, dl);
    // fc1: dense hi/lo -> fc1o hi/lo
    gemm_bfA<<<dim3(8, MD / 128), 256, GM_SMEM_BF>>>(dh, dl, 256,
        whi + WOFF_F1, wlo + WOFF_F1, fc1b, nullptr, fc1h, fc1l, 1024, nullptr, 256, 1);
    // fc2: fc1o hi/lo -> hd fp32
    gemm_bfA<<<dim3(1, MD / 128), 256, GM_SMEM_BF>>>(fc1h, fc1l, 1024,
        whi + WOFF_F2, wlo + WOFF_F2, fc2b, hd, nullptr, nullptr, 128, nullptr, 1024, 1);

    // ---- join, fused co-attention ----
    if (fork) cudaStreamWaitEvent(0, evJ, 0);
    coattn_fused<<<BGR, 256, SM_FLOATS * 4 + 1024>>>(tbw, t, hd, W_c, w_hc, w_hp, bslot, cp);

    // ---- final MLP ----
    gemm_f32A<<<dim3(8, 1), 256, GM_SMEM_F32>>>(cp, 256, nullptr,
        whi + WOFF_C1, wlo + WOFF_C1, c1b, nullptr, f1h, f1l, 1024, nullptr, 256, 1, 0, nullptr, nullptr, nullptr);
    gemm_bfA<<<dim3(4, 1), 256, GM_SMEM_BF>>>(f1h, f1l, 1024,
        whi + WOFF_C2, wlo + WOFF_C2, c2b, f2, nullptr, nullptr, 512, nullptr, 1024, 1);
    out_kernel<<<1, 128>>>(f2, oW, ob, (float*)d_out);
}

// round 12
// speedup vs baseline: 1.6494x; 1.0603x over previous
#include <cuda_runtime.h>
#include <cuda_bf16.h>
#include <math.h>
#include <stdint.h>

// ---------------- problem constants ----------------
#define NNODES 5120
#define NEDGES 20000
#define BGR    128
#define MAXN   45
#define LPROT  512
#define DPROT  1280
#define NPROT  229
#define TROWS  (BGR*LPROT)   // 65536
#define MD     (BGR*MAXN)    // 5760

typedef unsigned long long u64;

// ---------------- converted-weight pool (bf16 hi/lo, [n][k] k-major) ----------------
#define SZ_B1 (1280*128)
#define SZ_B2 (128*128)
#define SZ_WC (256*128)
#define SZ_G2 (128*128)
#define SZ_G3 (256*128)
#define SZ_F1 (1024*256)
#define SZ_F2 (128*1024)
#define SZ_C1 (1024*256)
#define SZ_C2 (512*1024)
#define WOFF_B1 0
#define WOFF_B2 (WOFF_B1+SZ_B1)
#define WOFF_WC (WOFF_B2+SZ_B2)
#define WOFF_G2 (WOFF_WC+SZ_WC)
#define WOFF_G3 (WOFF_G2+SZ_G2)
#define WOFF_F1 (WOFF_G3+SZ_G3)
#define WOFF_F2 (WOFF_F1+SZ_F1)
#define WOFF_C1 (WOFF_F2+SZ_F2)
#define WOFF_C2 (WOFF_C1+SZ_C1)
#define TOTALW  (WOFF_C2+SZ_C2)

// ---------------- device scratch ----------------
__device__ float g_deg[NNODES];
__device__ float g_coef[NEDGES];
__device__ float g_xw[NNODES*256];
__device__ float g_hA[NNODES*128];
__device__ float g_hB[NNODES*128];
__device__ float g_h3[NNODES*256];
__device__ int   g_counts[BGR];
__device__ int   g_starts[BGR];
__device__ float g_hd[MD*128];
__device__ int   g_rowmap[TROWS];
__device__ float g_t[TROWS*128];
__device__ float g_tbw[(long)TROWS*256];   // [tb | WptT | pad]
__device__ float g_cp[BGR*256];
__device__ float g_f2[BGR*512];
__device__ int g_Mdyn[1];
__device__ int g_bslot[BGR];
__device__ __nv_bfloat16 g_whi[TOTALW];
__device__ __nv_bfloat16 g_wlo[TOTALW];
// activation hi/lo chains
__device__ __nv_bfloat16 g_t1h[TROWS*128], g_t1l[TROWS*128];
__device__ __nv_bfloat16 g_th[TROWS*128],  g_tl[TROWS*128];
__device__ __nv_bfloat16 g_dh[MD*256],     g_dl[MD*256];
__device__ __nv_bfloat16 g_fc1h[(long)MD*1024], g_fc1l[(long)MD*1024];
__device__ __nv_bfloat16 g_f1h[BGR*1024],  g_f1l[BGR*1024];

// ---------------- helpers ----------------
__device__ __forceinline__ unsigned su32(const void* p) {
    unsigned r;
    asm("{ .reg .u64 t; cvta.to.shared.u64 t, %1; cvt.u32.u64 %0, t; }" : "=r"(r) : "l"(p));
    return r;
}
__device__ __forceinline__ void ldsm4(unsigned* r, unsigned addr) {
    asm volatile("ldmatrix.sync.aligned.m8n8.x4.shared.b16 {%0,%1,%2,%3}, [%4];"
        : "=r"(r[0]), "=r"(r[1]), "=r"(r[2]), "=r"(r[3]) : "r"(addr));
}
__device__ __forceinline__ void ldsm2(unsigned* r, unsigned addr) {
    asm volatile("ldmatrix.sync.aligned.m8n8.x2.shared.b16 {%0,%1}, [%2];"
        : "=r"(r[0]), "=r"(r[1]) : "r"(addr));
}
__device__ __forceinline__ void mma16816(float* d, const unsigned* a, const unsigned* b) {
    asm volatile("mma.sync.aligned.m16n8k16.row.col.f32.bf16.bf16.f32 "
        "{%0,%1,%2,%3}, {%4,%5,%6,%7}, {%8,%9}, {%0,%1,%2,%3};"
        : "+f"(d[0]), "+f"(d[1]), "+f"(d[2]), "+f"(d[3])
        : "r"(a[0]), "r"(a[1]), "r"(a[2]), "r"(a[3]), "r"(b[0]), "r"(b[1]));
}
__device__ __forceinline__ unsigned bfpack(float a, float b) {
    __nv_bfloat162 h = __floats2bfloat162_rn(a, b);
    return *(unsigned*)&h;
}
__device__ __forceinline__ void cp16(unsigned dst, const void* src) {
    asm volatile("cp.async.ca.shared.global [%0], [%1], 16;" :: "r"(dst), "l"(src));
}
__device__ __forceinline__ void cp_commit() { asm volatile("cp.async.commit_group;"); }
__device__ __forceinline__ void cp_waitall() { asm volatile("cp.async.wait_all;" ::: "memory"); }

// packed split store: v = (x,y) at even offset
__device__ __forceinline__ void split_store2(float2 v, __nv_bfloat16* hi, __nv_bfloat16* lo, long off) {
    __nv_bfloat162 h = __floats2bfloat162_rn(v.x, v.y);
    *(__nv_bfloat162*)&hi[off] = h;
    float lx = v.x - __bfloat162float(__low2bfloat16(h));
    float ly = v.y - __bfloat162float(__high2bfloat16(h));
    *(__nv_bfloat162*)&lo[off] = __floats2bfloat162_rn(lx, ly);
}

// ---------------- weight conversion: fp32 [K][N] -> bf16 hi/lo [N][K] ----------------
__global__ void convert_w(
    const float* __restrict__ b1W, const float* __restrict__ b2W,
    const float* __restrict__ Wb,  const float* __restrict__ Wp,
    const float* __restrict__ gW2, const float* __restrict__ gW3,
    const float* __restrict__ fc1W, const float* __restrict__ fc2W,
    const float* __restrict__ c1W, const float* __restrict__ c2W,
    __nv_bfloat16* __restrict__ hi, __nv_bfloat16* __restrict__ lo)
{
    int i = blockIdx.x * 256 + threadIdx.x;
    if (i >= TOTALW) return;
    float v;
    if (i < WOFF_B2)      { int j = i;           int n = j / 1280, k = j % 1280; v = b1W[k * 128 + n]; }
    else if (i < WOFF_WC) { int j = i - WOFF_B2; int n = j >> 7,  k = j & 127;  v = b2W[k * 128 + n]; }
    else if (i < WOFF_G2) { int j = i - WOFF_WC; int n = j >> 7,  k = j & 127;
                            v = (n < 128) ? Wb[k * 128 + n] : ((n < 160) ? Wp[(n - 128) * 128 + k] : 0.f); }
    else if (i < WOFF_G3) { int j = i - WOFF_G2; int n = j >> 7,  k = j & 127;  v = gW2[k * 128 + n]; }
    else if (i < WOFF_F1) { int j = i - WOFF_G3; int n = j >> 7,  k = j & 127;  v = gW3[k * 256 + n]; }
    else if (i < WOFF_F2) { int j = i - WOFF_F1; int n = j >> 8,  k = j & 255;  v = fc1W[k * 1024 + n]; }
    else if (i < WOFF_C1) { int j = i - WOFF_F2; int n = j >> 10, k = j & 1023; v = fc2W[k * 128 + n]; }
    else if (i < WOFF_C2) { int j = i - WOFF_C1; int n = j >> 8,  k = j & 255;  v = c1W[k * 1024 + n]; }
    else                  { int j = i - WOFF_C2; int n = j >> 10, k = j & 1023; v = c2W[k * 512 + n]; }
    __nv_bfloat16 h = __float2bfloat16_rn(v);
    hi[i] = h;
    lo[i] = __float2bfloat16_rn(v - __bfloat162float(h));
}

#define GSTRIDE 72
#define GTILEB (128 * GSTRIDE * 2)
#define GM_SMEM (4 * GTILEB)   // 73728 bytes — both kernels single-buffered

// =================================================================
// gemm_f32A: A fp32 (optional rowmap/preRelu), B pre-converted.
// =================================================================
__global__ __launch_bounds__(256) void gemm_f32A(
    const float* __restrict__ A, int lda, const int* __restrict__ rowmap,
    const __nv_bfloat16* __restrict__ Bhi, const __nv_bfloat16* __restrict__ Blo,
    const float* __restrict__ bias,
    float* __restrict__ C, __nv_bfloat16* __restrict__ Chi, __nv_bfloat16* __restrict__ Clo,
    int ldc, const int* __restrict__ Mdyn,
    int K, int act, int preRelu,
    float* __restrict__ C2, const float* __restrict__ degv,
    const float* __restrict__ bias2)
{
    const int m0 = blockIdx.y * 128;
    if (Mdyn && m0 >= *Mdyn) return;
    const int col0 = blockIdx.x * 128;
    const int tid = threadIdx.x;
    const int wid = tid >> 5, lane = tid & 31;
    const int warp_m = (wid >> 2) * 64;
    const int warp_n = (wid & 3) * 32;

    extern __shared__ char smraw[];
    char* sAh = smraw;
    char* sAl = smraw + GTILEB;
    char* sBh = smraw + 2 * GTILEB;
    char* sBl = smraw + 3 * GTILEB;
    const unsigned uAh = su32(sAh), uAl = su32(sAl);
    const unsigned uBh = su32(sBh), uBl = su32(sBl);

    const float* arow[8];
    int amq[8];
    #pragma unroll
    for (int i = 0; i < 8; i++) {
        int idx = tid + i * 256;
        int m = idx >> 4;
        int q = (idx & 15) << 2;
        int gr = m0 + m;
        int ar = rowmap ? rowmap[gr] : gr;
        arow[i] = A + (long)ar * lda + q;
        amq[i] = (m * GSTRIDE + q) * 2;
    }
    const __nv_bfloat16* bsrc_h[4];
    const __nv_bfloat16* bsrc_l[4];
    unsigned bdst[4];
    #pragma unroll
    for (int i = 0; i < 4; i++) {
        int idx = tid + i * 256;
        int n = idx >> 3;
        int k8 = (idx & 7) << 3;
        bsrc_h[i] = Bhi + (long)(col0 + n) * K + k8;
        bsrc_l[i] = Blo + (long)(col0 + n) * K + k8;
        bdst[i] = (n * GSTRIDE + k8) * 2;
    }

    float d[4][4][4];
    #pragma unroll
    for (int i = 0; i < 4; i++)
        #pragma unroll
        for (int j = 0; j < 4; j++)
            #pragma unroll
            for (int r = 0; r < 4; r++) d[i][j][r] = 0.f;

    const int a_row = lane & 15, a_half = (lane >> 4) * 8;
    const int b_row = lane & 7,  b_half = ((lane >> 3) & 1) * 8;

    const int kc = K >> 6;
    for (int c = 0; c < kc; c++) {
        #pragma unroll
        for (int i = 0; i < 4; i++) {
            cp16(uBh + bdst[i], bsrc_h[i] + (c << 6));
            cp16(uBl + bdst[i], bsrc_l[i] + (c << 6));
        }
        #pragma unroll
        for (int i = 0; i < 8; i++) {
            float4 v = *(const float4*)(arow[i] + (c << 6));
            if (preRelu) {
                v.x = fmaxf(v.x, 0.f); v.y = fmaxf(v.y, 0.f);
                v.z = fmaxf(v.z, 0.f); v.w = fmaxf(v.w, 0.f);
            }
            __nv_bfloat16 h0 = __float2bfloat16_rn(v.x), h1 = __float2bfloat16_rn(v.y);
            __nv_bfloat16 h2 = __float2bfloat16_rn(v.z), h3 = __float2bfloat16_rn(v.w);
            float l0 = v.x - __bfloat162float(h0), l1 = v.y - __bfloat162float(h1);
            float l2 = v.z - __bfloat162float(h2), l3 = v.w - __bfloat162float(h3);
            unsigned hp0 = ((unsigned)__bfloat16_as_ushort(h0)) | ((unsigned)__bfloat16_as_ushort(h1) << 16);
            unsigned hp1 = ((unsigned)__bfloat16_as_ushort(h2)) | ((unsigned)__bfloat16_as_ushort(h3) << 16);
            *(uint2*)(sAh + amq[i]) = make_uint2(hp0, hp1);
            *(uint2*)(sAl + amq[i]) = make_uint2(bfpack(l0, l1), bfpack(l2, l3));
        }
        cp_waitall();
        __syncthreads();
        #pragma unroll
        for (int ks = 0; ks < 4; ks++) {
            const int kb = ks * 16;
            unsigned ah[4][4], al[4][4], bh[4][2], bl[4][2];
            #pragma unroll
            for (int mt = 0; mt < 4; mt++) {
                int off = ((warp_m + mt * 16 + a_row) * GSTRIDE + kb + a_half) * 2;
                ldsm4(ah[mt], uAh + off);
                ldsm4(al[mt], uAl + off);
            }
            #pragma unroll
            for (int nt = 0; nt < 4; nt++) {
                int off = ((warp_n + nt * 8 + b_row) * GSTRIDE + kb + b_half) * 2;
                ldsm2(bh[nt], uBh + off);
                ldsm2(bl[nt], uBl + off);
            }
            #pragma unroll
            for (int mt = 0; mt < 4; mt++)
                #pragma unroll
                for (int nt = 0; nt < 4; nt++) {
                    mma16816(d[mt][nt], ah[mt], bh[nt]);
                    mma16816(d[mt][nt], ah[mt], bl[nt]);
                    mma16816(d[mt][nt], al[mt], bh[nt]);
                }
        }
        __syncthreads();
    }

    const int r0 = lane >> 2;
    const int c0 = (lane & 3) * 2;
    #pragma unroll
    for (int mt = 0; mt < 4; mt++) {
        int gmA = m0 + warp_m + mt * 16 + r0;
        int gmB = gmA + 8;
        float dgA = 1.f, dgB = 1.f;
        if (C2) { dgA = degv[gmA]; dgB = degv[gmB]; }
        #pragma unroll
        for (int nt = 0; nt < 4; nt++) {
            int gn = col0 + warp_n + nt * 8 + c0;
            float2 vA = make_float2(d[mt][nt][0], d[mt][nt][1]);
            float2 vB = make_float2(d[mt][nt][2], d[mt][nt][3]);
            if (C2) {
                *(float2*)&C2[(long)gmA * ldc + gn] =
                    make_float2(vA.x / dgA + bias2[gn], vA.y / dgA + bias2[gn + 1]);
                *(float2*)&C2[(long)gmB * ldc + gn] =
                    make_float2(vB.x / dgB + bias2[gn], vB.y / dgB + bias2[gn + 1]);
            }
            if (bias) {
                float b0 = bias[gn], b1 = bias[gn + 1];
                vA.x += b0; vA.y += b1; vB.x += b0; vB.y += b1;
            }
            if (act == 1) {
                vA.x = fmaxf(vA.x, 0.f); vA.y = fmaxf(vA.y, 0.f);
                vB.x = fmaxf(vB.x, 0.f); vB.y = fmaxf(vB.y, 0.f);
            } else if (act == 2) {
                vA.x = tanhf(vA.x); vA.y = tanhf(vA.y);
                vB.x = tanhf(vB.x); vB.y = tanhf(vB.y);
            }
            if (C) {
                *(float2*)&C[(long)gmA * ldc + gn] = vA;
                *(float2*)&C[(long)gmB * ldc + gn] = vB;
            }
            if (Chi) {
                split_store2(vA, Chi, Clo, (long)gmA * ldc + gn);
                split_store2(vB, Chi, Clo, (long)gmB * ldc + gn);
            }
        }
    }
}

// =================================================================
// gemm_bfA: A pre-converted bf16 hi/lo [M][K]; single-buffered,
// __launch_bounds__(256,2) => 2 CTAs/SM for latency hiding.
// =================================================================
__global__ __launch_bounds__(256, 2) void gemm_bfA(
    const __nv_bfloat16* __restrict__ Ahi, const __nv_bfloat16* __restrict__ Alo, int lda,
    const __nv_bfloat16* __restrict__ Bhi, const __nv_bfloat16* __restrict__ Blo,
    const float* __restrict__ bias,
    float* __restrict__ C, __nv_bfloat16* __restrict__ Chi, __nv_bfloat16* __restrict__ Clo,
    int ldc, const int* __restrict__ Mdyn, int K, int act)
{
    const int m0 = blockIdx.y * 128;
    if (Mdyn && m0 >= *Mdyn) return;
    const int col0 = blockIdx.x * 128;
    const int tid = threadIdx.x;
    const int wid = tid >> 5, lane = tid & 31;
    const int warp_m = (wid >> 2) * 64;
    const int warp_n = (wid & 3) * 32;

    extern __shared__ char smraw[];
    const unsigned uAh = su32(smraw);
    const unsigned uAl = uAh + GTILEB;
    const unsigned uBh = uAh + 2 * GTILEB;
    const unsigned uBl = uAh + 3 * GTILEB;

    const __nv_bfloat16 *ah_s[4], *al_s[4], *bh_s[4], *bl_s[4];
    unsigned doff[4];
    #pragma unroll
    for (int i = 0; i < 4; i++) {
        int idx = tid + i * 256;
        int r = idx >> 3;
        int k8 = (idx & 7) << 3;
        ah_s[i] = Ahi + (long)(m0 + r) * lda + k8;
        al_s[i] = Alo + (long)(m0 + r) * lda + k8;
        bh_s[i] = Bhi + (long)(col0 + r) * K + k8;
        bl_s[i] = Blo + (long)(col0 + r) * K + k8;
        doff[i] = (r * GSTRIDE + k8) * 2;
    }

    float d[4][4][4];
    #pragma unroll
    for (int i = 0; i < 4; i++)
        #pragma unroll
        for (int j = 0; j < 4; j++)
            #pragma unroll
            for (int r = 0; r < 4; r++) d[i][j][r] = 0.f;

    const int a_row = lane & 15, a_half = (lane >> 4) * 8;
    const int b_row = lane & 7,  b_half = ((lane >> 3) & 1) * 8;
    const int kc = K >> 6;

    for (int c = 0; c < kc; c++) {
        const int kof = c << 6;
        #pragma unroll
        for (int i = 0; i < 4; i++) {
            cp16(uAh + doff[i], ah_s[i] + kof);
            cp16(uAl + doff[i], al_s[i] + kof);
            cp16(uBh + doff[i], bh_s[i] + kof);
            cp16(uBl + doff[i], bl_s[i] + kof);
        }
        cp_commit();
        cp_waitall();
        __syncthreads();
        #pragma unroll
        for (int ks = 0; ks < 4; ks++) {
            const int kb = ks * 16;
            unsigned ah[4][4], al[4][4], bh[4][2], bl[4][2];
            #pragma unroll
            for (int mt = 0; mt < 4; mt++) {
                int off = ((warp_m + mt * 16 + a_row) * GSTRIDE + kb + a_half) * 2;
                ldsm4(ah[mt], uAh + off);
                ldsm4(al[mt], uAl + off);
            }
            #pragma unroll
            for (int nt = 0; nt < 4; nt++) {
                int off = ((warp_n + nt * 8 + b_row) * GSTRIDE + kb + b_half) * 2;
                ldsm2(bh[nt], uBh + off);
                ldsm2(bl[nt], uBl + off);
            }
            #pragma unroll
            for (int mt = 0; mt < 4; mt++)
                #pragma unroll
                for (int nt = 0; nt < 4; nt++) {
                    mma16816(d[mt][nt], ah[mt], bh[nt]);
                    mma16816(d[mt][nt], ah[mt], bl[nt]);
                    mma16816(d[mt][nt], al[mt], bh[nt]);
                }
        }
        __syncthreads();
    }

    const int r0 = lane >> 2;
    const int c0 = (lane & 3) * 2;
    #pragma unroll
    for (int mt = 0; mt < 4; mt++) {
        int gmA = m0 + warp_m + mt * 16 + r0;
        int gmB = gmA + 8;
        #pragma unroll
        for (int nt = 0; nt < 4; nt++) {
            int gn = col0 + warp_n + nt * 8 + c0;
            float2 vA = make_float2(d[mt][nt][0], d[mt][nt][1]);
            float2 vB = make_float2(d[mt][nt][2], d[mt][nt][3]);
            if (bias) {
                float b0 = bias[gn], b1 = bias[gn + 1];
                vA.x += b0; vA.y += b1; vB.x += b0; vB.y += b1;
            }
            if (act == 1) {
                vA.x = fmaxf(vA.x, 0.f); vA.y = fmaxf(vA.y, 0.f);
                vB.x = fmaxf(vB.x, 0.f); vB.y = fmaxf(vB.y, 0.f);
            } else if (act == 2) {
                vA.x = tanhf(vA.x); vA.y = tanhf(vA.y);
                vB.x = tanhf(vB.x); vB.y = tanhf(vB.y);
            }
            if (C) {
                *(float2*)&C[(long)gmA * ldc + gn] = vA;
                *(float2*)&C[(long)gmB * ldc + gn] = vB;
            }
            if (Chi) {
                split_store2(vA, Chi, Clo, (long)gmA * ldc + gn);
                split_store2(vB, Chi, Clo, (long)gmB * ldc + gn);
            }
        }
    }
}

// ---------------- generic SGEMM (GCN layer 1, K=78) ----------------
__global__ __launch_bounds__(256) void sgemm64(
    const float* __restrict__ A, int lda,
    const float* __restrict__ B, float* __restrict__ C,
    int M, int N, int K,
    float* __restrict__ C2, const float* __restrict__ degv,
    const float* __restrict__ bias2)
{
    __shared__ float As[16][64];
    __shared__ float Bs[16][68];
    const int tid = threadIdx.y * 16 + threadIdx.x;
    const int m0 = blockIdx.y * 64;
    const int n0 = blockIdx.x * 64;
    float acc[4][4] = {};
    for (int kt = 0; kt < K; kt += 16) {
        #pragma unroll
        for (int i = tid; i < 64 * 16; i += 256) {
            int m = i >> 4, kk = i & 15;
            int gm = m0 + m, gk = kt + kk;
            float v = 0.f;
            if (gm < M && gk < K) v = A[(long)gm * lda + gk];
            As[kk][m] = v;
        }
        #pragma unroll
        for (int i = tid; i < 16 * 64; i += 256) {
            int kk = i >> 6, n = i & 63;
            int gk = kt + kk, gn = n0 + n;
            Bs[kk][n] = (gk < K && gn < N) ? B[(long)gk * N + gn] : 0.f;
        }
        __syncthreads();
        #pragma unroll
        for (int kk = 0; kk < 16; kk++) {
            float a[4];
            #pragma unroll
            for (int i = 0; i < 4; i++) a[i] = As[kk][threadIdx.y * 4 + i];
            float4 b4 = *(const float4*)&Bs[kk][threadIdx.x * 4];
            float bv[4] = { b4.x, b4.y, b4.z, b4.w };
            #pragma unroll
            for (int i = 0; i < 4; i++)
                #pragma unroll
                for (int j = 0; j < 4; j++) acc[i][j] += a[i] * bv[j];
        }
        __syncthreads();
    }
    #pragma unroll
    for (int i = 0; i < 4; i++) {
        int gm = m0 + threadIdx.y * 4 + i;
        if (gm >= M) continue;
        #pragma unroll
        for (int j = 0; j < 4; j++) {
            int gn = n0 + threadIdx.x * 4 + j;
            if (gn >= N) continue;
            float v = acc[i][j];
            if (C2) C2[(long)gm * N + gn] = v / degv[gm] + bias2[gn];
            C[(long)gm * N + gn] = v;
        }
    }
}

// ---------------- prep_all ----------------
__global__ __launch_bounds__(1024) void prep_all(
    const int* __restrict__ tgt, const int* __restrict__ src,
    const int* __restrict__ dst, const int* __restrict__ batch,
    int n, int E,
    int* bslot, int* rowmap, int* Mdyn,
    float* deg, float* coef, int* counts, int* starts)
{
    __shared__ float sdeg[NNODES];
    __shared__ int flag[NPROT];
    __shared__ int slot[NPROT];
    __shared__ int uniq[BGR];
    __shared__ int cbin[BGR];
    __shared__ int nu_s;
    const int tid = threadIdx.x;

    for (int i = tid; i < n; i += 1024) sdeg[i] = 1.0f;
    if (tid < NPROT) flag[tid] = 0;
    if (tid < BGR) cbin[tid] = 0;
    __syncthreads();
    if (tid < BGR) flag[tgt[tid]] = 1;
    for (int e = tid; e < E; e += 1024) atomicAdd(&sdeg[dst[e]], 1.0f);
    for (int i = tid; i < n; i += 1024) atomicAdd(&cbin[batch[i]], 1);
    __syncthreads();
    if (tid == 0) {
        int s = 0;
        for (int p = 0; p < NPROT; p++) {
            if (flag[p]) { slot[p] = s; uniq[s] = p; s++; }
            else slot[p] = -1;
        }
        nu_s = s;
        Mdyn[0] = s * LPROT;
    } else if (tid == 32) {
        int s = 0;
        for (int b = 0; b < BGR; b++) { starts[b] = s; counts[b] = cbin[b]; s += cbin[b]; }
    }
    __syncthreads();
    if (tid < BGR) bslot[tid] = slot[tgt[tid]];
    for (int i = tid; i < n; i += 1024) deg[i] = sdeg[i];
    for (int e = tid; e < E; e += 1024)
        coef[e] = rsqrtf(sdeg[src[e]]) * rsqrtf(sdeg[dst[e]]);
    int nu = nu_s;
    for (int r = tid; r < TROWS; r += 1024) {
        int s = r >> 9;
        rowmap[r] = (s < nu) ? (uniq[s] * LPROT + (r & (LPROT - 1))) : 0;
    }
}

// ---------------- GCN scatter (float4) ----------------
__global__ void gcn_scatter4(const int* __restrict__ src, const int* __restrict__ dst,
                             const float* __restrict__ coef, const float* __restrict__ xw,
                             float* out, int E, int F4) {
    long i = (long)blockIdx.x * blockDim.x + threadIdx.x;
    if (i >= (long)E * F4) return;
    int e = (int)(i / F4);
    int f = (int)(i - (long)e * F4) * 4;
    float c = coef[e];
    int s = src[e], d = dst[e];
    const int F = F4 * 4;
    float4 v = *(const float4*)&xw[(long)s * F + f];
    float* o = &out[(long)d * F + f];
    atomicAdd(o + 0, v.x * c);
    atomicAdd(o + 1, v.y * c);
    atomicAdd(o + 2, v.z * c);
    atomicAdd(o + 3, v.w * c);
}

// ---------------- to_dense_batch gather -> bf16 hi/lo ----------------
__global__ void dense_build(const float* __restrict__ h3,
                            const int* __restrict__ counts,
                            const int* __restrict__ starts,
                            __nv_bfloat16* __restrict__ dh,
                            __nv_bfloat16* __restrict__ dl) {
    int i = blockIdx.x * blockDim.x + threadIdx.x;
    if (i >= MD * 64) return;
    int b = i / (MAXN * 64);
    int rem = i - b * (MAXN * 64);
    int pos = rem >> 6, f4 = rem & 63;
    float4 v = make_float4(0.f, 0.f, 0.f, 0.f);
    if (pos < counts[b]) {
        v = ((const float4*)(h3 + (long)(starts[b] + pos) * 256))[f4];
        v.x = fmaxf(v.x, 0.f); v.y = fmaxf(v.y, 0.f);
        v.z = fmaxf(v.z, 0.f); v.w = fmaxf(v.w, 0.f);
    }
    long off = (long)i * 4;
    split_store2(make_float2(v.x, v.y), dh, dl, off);
    split_store2(make_float2(v.z, v.w), dh, dl, off + 2);
}

// =================================================================
// FUSED CO-ATTENTION (unchanged)
// =================================================================
#define PHD 132
#define OFF_HD   0
#define OFF_WCX  (OFF_HD + 45*PHD)
#define OFF_C    (OFF_WCX + 32*48)
#define OFF_TB   (OFF_C + 64*48)
#define OFF_AP   (OFF_TB + 64*PHD)
#define OFF_AC   (OFF_AP + 512)
#define OFF_RED  (OFF_AC + 48)
#define OFF_WC   (OFF_RED + 256)
#define OFF_WP   (OFF_WC + 32)
#define OFF_SCAL (OFF_WP + 32)
#define SM_FLOATS (OFF_SCAL + 4)

__global__ __launch_bounds__(256) void coattn_fused(
    const float* __restrict__ tbw, const float* __restrict__ t,
    const float* __restrict__ hd, const float* __restrict__ Wc_g,
    const float* __restrict__ whc, const float* __restrict__ whp,
    const int* __restrict__ bslot, float* __restrict__ cp)
{
    extern __shared__ float sm[];
    float* s_hd  = sm + OFF_HD;
    float* s_wcx = sm + OFF_WCX;
    float* s_C   = sm + OFF_C;
    float* s_tb  = sm + OFF_TB;
    float* s_ap  = sm + OFF_AP;
    float* s_ac  = sm + OFF_AC;
    float* s_red = sm + OFF_RED;
    float* s_wc  = sm + OFF_WC;
    float* s_wp  = sm + OFF_WP;
    float* s_scal= sm + OFF_SCAL;

    const int b = blockIdx.x;
    const int tid = threadIdx.x;
    const long base = (long)bslot[b] * LPROT;
    const float* hd_b = hd + (long)b * MAXN * 128;

    for (int idx = tid; idx < MAXN * 32; idx += 256) {
        int s = idx >> 5, v4 = (idx & 31) * 4;
        *(float4*)&s_hd[s * PHD + v4] = *(const float4*)&hd_b[s * 128 + v4];
    }
    if (tid < 32) { s_wc[tid] = whc[tid]; s_wp[tid] = whp[tid]; }
    if (tid < 48) s_ac[tid] = 0.f;
    __syncthreads();

    for (int idx = tid; idx < 32 * MAXN; idx += 256) {
        int k = idx / MAXN, s = idx - k * MAXN;
        float acc = 0.f;
        #pragma unroll
        for (int kk = 0; kk < 32; kk++) {
            float4 a = *(const float4*)&Wc_g[k * 128 + kk * 4];
            float4 h4 = *(const float4*)&s_hd[s * PHD + kk * 4];
            acc += a.x * h4.x + a.y * h4.y + a.z * h4.z + a.w * h4.w;
        }
        s_wcx[k * 48 + s] = acc;
    }

    const int kt2 = (tid / 15) * 2;
    const int st3 = (tid % 15) * 3;
    float hc00 = 0.f, hc01 = 0.f, hc02 = 0.f, hc10 = 0.f, hc11 = 0.f, hc12 = 0.f;

    for (int cc = 0; cc < 8; cc++) {
        const int lbase = cc * 64;
        __syncthreads();
        for (int idx = tid; idx < 64 * 32; idx += 256) {
            int l = idx >> 5, v4 = (idx & 31) * 4;
            *(float4*)&s_tb[l * PHD + v4] =
                *(const float4*)&tbw[(base + lbase + l) * 256 + v4];
        }
        __syncthreads();
        if (tid < 240) {
            int lt = (tid / 15) * 4;
            float ca[4][3] = {};
            #pragma unroll 8
            for (int kk = 0; kk < 32; kk++) {
                float4 a0 = *(const float4*)&s_tb[(lt + 0) * PHD + kk * 4];
                float4 a1 = *(const float4*)&s_tb[(lt + 1) * PHD + kk * 4];
                float4 a2 = *(const float4*)&s_tb[(lt + 2) * PHD + kk * 4];
                float4 a3 = *(const float4*)&s_tb[(lt + 3) * PHD + kk * 4];
                float4 h0 = *(const float4*)&s_hd[(st3 + 0) * PHD + kk * 4];
                float4 h1 = *(const float4*)&s_hd[(st3 + 1) * PHD + kk * 4];
                float4 h2 = *(const float4*)&s_hd[(st3 + 2) * PHD + kk * 4];
                ca[0][0] += a0.x*h0.x + a0.y*h0.y + a0.z*h0.z + a0.w*h0.w;
                ca[0][1] += a0.x*h1.x + a0.y*h1.y + a0.z*h1.z + a0.w*h1.w;
                ca[0][2] += a0.x*h2.x + a0.y*h2.y + a0.z*h2.z + a0.w*h2.w;
                ca[1][0] += a1.x*h0.x + a1.y*h0.y + a1.z*h0.z + a1.w*h0.w;
                ca[1][1] += a1.x*h1.x + a1.y*h1.y + a1.z*h1.z + a1.w*h1.w;
                ca[1][2] += a1.x*h2.x + a1.y*h2.y + a1.z*h2.z + a1.w*h2.w;
                ca[2][0] += a2.x*h0.x + a2.y*h0.y + a2.z*h0.z + a2.w*h0.w;
                ca[2][1] += a2.x*h1.x + a2.y*h1.y + a2.z*h1.z + a2.w*h1.w;
                ca[2][2] += a2.x*h2.x + a2.y*h2.y + a2.z*h2.z + a2.w*h2.w;
                ca[3][0] += a3.x*h0.x + a3.y*h0.y + a3.z*h0.z + a3.w*h0.w;
                ca[3][1] += a3.x*h1.x + a3.y*h1.y + a3.z*h1.z + a3.w*h1.w;
                ca[3][2] += a3.x*h2.x + a3.y*h2.y + a3.z*h2.z + a3.w*h2.w;
            }
            #pragma unroll
            for (int i = 0; i < 4; i++)
                #pragma unroll
                for (int j = 0; j < 3; j++)
                    s_C[(lt + i) * 48 + st3 + j] = tanhf(ca[i][j]);
        }
        __syncthreads();
        if (tid < 240) {
            for (int l = 0; l < 64; l++) {
                const float* wrow = &tbw[(base + lbase + l) * 256 + 128];
                float w0 = wrow[kt2], w1 = wrow[kt2 + 1];
                float c0 = s_C[l * 48 + st3];
                float c1 = s_C[l * 48 + st3 + 1];
                float c2 = s_C[l * 48 + st3 + 2];
                hc00 += w0 * c0; hc01 += w0 * c1; hc02 += w0 * c2;
                hc10 += w1 * c0; hc11 += w1 * c1; hc12 += w1 * c2;
            }
        }
        {
            int l = tid >> 2, q = tid & 3;
            float cl[45];
            #pragma unroll
            for (int s = 0; s < 45; s++) cl[s] = s_C[l * 48 + s];
            const float* wrow = &tbw[(base + lbase + l) * 256 + 128];
            float part = 0.f;
            #pragma unroll
            for (int i = 0; i < 8; i++) {
                int k = q * 8 + i;
                float v = wrow[k];
                const float* wx = &s_wcx[k * 48];
                #pragma unroll
                for (int s = 0; s < 45; s++) v += wx[s] * cl[s];
                part += s_wp[k] * tanhf(v);
            }
            part += __shfl_down_sync(0xffffffffu, part, 2);
            part += __shfl_down_sync(0xffffffffu, part, 1);
            if (q == 0) s_ap[lbase + l] = part;
        }
    }
    __syncthreads();

    if (tid < 240) {
        float h;
        h = tanhf(s_wcx[kt2 * 48 + st3] + hc00);       atomicAdd(&s_ac[st3],     s_wc[kt2] * h);
        h = tanhf(s_wcx[kt2 * 48 + st3 + 1] + hc01);   atomicAdd(&s_ac[st3 + 1], s_wc[kt2] * h);
        h = tanhf(s_wcx[kt2 * 48 + st3 + 2] + hc02);   atomicAdd(&s_ac[st3 + 2], s_wc[kt2] * h);
        h = tanhf(s_wcx[(kt2+1) * 48 + st3] + hc10);     atomicAdd(&s_ac[st3],     s_wc[kt2+1] * h);
        h = tanhf(s_wcx[(kt2+1) * 48 + st3 + 1] + hc11); atomicAdd(&s_ac[st3 + 1], s_wc[kt2+1] * h);
        h = tanhf(s_wcx[(kt2+1) * 48 + st3 + 2] + hc12); atomicAdd(&s_ac[st3 + 2], s_wc[kt2+1] * h);
    }
    __syncthreads();

    float m1 = fmaxf(s_ap[tid], s_ap[tid + 256]);
    s_red[tid] = m1; __syncthreads();
    for (int o = 128; o > 0; o >>= 1) {
        if (tid < o) s_red[tid] = fmaxf(s_red[tid], s_red[tid + o]);
        __syncthreads();
    }
    float mx = s_red[0]; __syncthreads();
    float e1 = expf(s_ap[tid] - mx), e2 = expf(s_ap[tid + 256] - mx);
    s_ap[tid] = e1; s_ap[tid + 256] = e2;
    s_red[tid] = e1 + e2; __syncthreads();
    for (int o = 128; o > 0; o >>= 1) {
        if (tid < o) s_red[tid] += s_red[tid + o];
        __syncthreads();
    }
    if (tid == 0) s_scal[0] = 1.f / s_red[0];
    if (tid == 0) {
        float amx = -1e30f;
        for (int s = 0; s < MAXN; s++) amx = fmaxf(amx, s_ac[s]);
        float sum = 0.f;
        for (int s = 0; s < MAXN; s++) { float e = expf(s_ac[s] - amx); s_ac[s] = e; sum += e; }
        float inv = 1.f / sum;
        for (int s = 0; s < MAXN; s++) s_ac[s] *= inv;
    }
    __syncthreads();

    {
        int h = tid >> 7, m = tid & 127;
        float accp = 0.f;
        int l0 = h * 256;
        for (int l = 0; l < 256; l++)
            accp += s_ap[l0 + l] * t[(base + l0 + l) * 128 + m];
        s_red[tid] = accp;
        __syncthreads();
        if (h == 0) {
            float accc = 0.f;
            #pragma unroll
            for (int s = 0; s < MAXN; s++) accc += s_ac[s] * s_hd[s * PHD + m];
            cp[b * 256 + m] = accc;
            cp[b * 256 + 128 + m] = (s_red[m] + s_red[128 + m]) * s_scal[0];
        }
    }
}

// ---------------- final output ----------------
__global__ void out_kernel(const float* __restrict__ f2, const float* __restrict__ oW,
                           const float* __restrict__ ob, float* __restrict__ out) {
    int b = threadIdx.x;
    if (b < BGR) {
        float s = 0.f;
        for (int j = 0; j < 512; j += 4) {
            float4 a = *(const float4*)&f2[b * 512 + j];
            float4 w = *(const float4*)&oW[j];
            s += a.x * w.x + a.y * w.y + a.z * w.z + a.w * w.w;
        }
        out[b] = s + ob[0];
    }
}

// ---------------- host launcher ----------------
static float* sym_f(const void* s) { void* p = nullptr; cudaGetSymbolAddress(&p, s); return (float*)p; }
static int*   sym_i(const void* s) { void* p = nullptr; cudaGetSymbolAddress(&p, s); return (int*)p; }
static __nv_bfloat16* sym_b(const void* s) { void* p = nullptr; cudaGetSymbolAddress(&p, s); return (__nv_bfloat16*)p; }

extern "C" void kernel_launch(void* const* d_in, const int* in_sizes, int n_in,
                              void* d_out, int out_size)
{
    const float* x      = (const float*)d_in[0];
    const int*   ei     = (const int*)d_in[1];
    const int*   tgt    = (const int*)d_in[2];
    const int*   batch  = (const int*)d_in[3];
    const float* prot   = (const float*)d_in[4];
    const float* gW1 = (const float*)d_in[5],  *gb1 = (const float*)d_in[6];
    const float* gW2 = (const float*)d_in[7],  *gb2 = (const float*)d_in[8];
    const float* gW3 = (const float*)d_in[9],  *gb3 = (const float*)d_in[10];
    const float* fc1W = (const float*)d_in[11], *fc1b = (const float*)d_in[12];
    const float* fc2W = (const float*)d_in[13], *fc2b = (const float*)d_in[14];
    const float* b1W = (const float*)d_in[15],  *b1b = (const float*)d_in[16];
    const float* b2W = (const float*)d_in[17],  *b2b = (const float*)d_in[18];
    const float* W_b = (const float*)d_in[19];
    const float* W_c = (const float*)d_in[20];
    const float* W_p = (const float*)d_in[21];
    const float* w_hc = (const float*)d_in[22], *w_hp = (const float*)d_in[23];
    const float* c1W = (const float*)d_in[24], *c1b = (const float*)d_in[25];
    const float* c2W = (const float*)d_in[26], *c2b = (const float*)d_in[27];
    const float* oW  = (const float*)d_in[28], *ob  = (const float*)d_in[29];

    const int N = in_sizes[0] / 78;
    const int E = in_sizes[1] / 2;
    const int* src = ei;
    const int* dst = ei + E;

    float* deg   = sym_f(g_deg);
    float* coef  = sym_f(g_coef);
    float* xw    = sym_f(g_xw);
    float* hA    = sym_f(g_hA);
    float* hB    = sym_f(g_hB);
    float* h3    = sym_f(g_h3);
    int*   counts = sym_i(g_counts);
    int*   starts = sym_i(g_starts);
    float* hd    = sym_f(g_hd);
    int*   rowmap = sym_i(g_rowmap);
    float* t     = sym_f(g_t);
    float* tbw   = sym_f(g_tbw);
    float* cp    = sym_f(g_cp);
    float* f2    = sym_f(g_f2);
    int* Mdyn  = sym_i(g_Mdyn);
    int* bslot = sym_i(g_bslot);
    __nv_bfloat16* whi = sym_b(g_whi);
    __nv_bfloat16* wlo = sym_b(g_wlo);
    __nv_bfloat16* t1h = sym_b(g_t1h), *t1l = sym_b(g_t1l);
    __nv_bfloat16* th  = sym_b(g_th),  *tl  = sym_b(g_tl);
    __nv_bfloat16* dh  = sym_b(g_dh),  *dl  = sym_b(g_dl);
    __nv_bfloat16* fc1h = sym_b(g_fc1h), *fc1l = sym_b(g_fc1l);
    __nv_bfloat16* f1h = sym_b(g_f1h), *f1l = sym_b(g_f1l);

    static cudaStream_t sB = 0;
    static cudaEvent_t evF = 0, evJ = 0;
    static int tried = 0;
    if (!tried) {
        tried = 1;
        if (cudaStreamCreateWithFlags(&sB, cudaStreamNonBlocking) != cudaSuccess) sB = 0;
        if (sB) {
            if (cudaEventCreateWithFlags(&evF, cudaEventDisableTiming) != cudaSuccess ||
                cudaEventCreateWithFlags(&evJ, cudaEventDisableTiming) != cudaSuccess) {
                sB = 0;
            }
        }
        cudaFuncSetAttribute(coattn_fused, cudaFuncAttributeMaxDynamicSharedMemorySize,
                             SM_FLOATS * 4 + 1024);
        cudaFuncSetAttribute(gemm_f32A, cudaFuncAttributeMaxDynamicSharedMemorySize, GM_SMEM);
        cudaFuncSetAttribute(gemm_bfA, cudaFuncAttributeMaxDynamicSharedMemorySize, GM_SMEM);
    }
    const bool fork = (sB != 0);
    cudaStream_t PS = fork ? sB : (cudaStream_t)0;

    dim3 t16(16, 16);

    // ---- prep + weight conversion ----
    prep_all<<<1, 1024>>>(tgt, src, dst, batch, N, E,
                          bslot, rowmap, Mdyn, deg, coef, counts, starts);
    convert_w<<<(TOTALW + 255) / 256, 256>>>(b1W, b2W, W_b, W_p, gW2, gW3,
                                             fc1W, fc2W, c1W, c2W, whi, wlo);

    // ---- fork: protein branch ----
    if (fork) { cudaEventRecord(evF, 0); cudaStreamWaitEvent(sB, evF, 0); }
    gemm_f32A<<<dim3(1, TROWS / 128), 256, GM_SMEM, PS>>>(prot, DPROT, rowmap,
        whi + WOFF_B1, wlo + WOFF_B1, b1b, nullptr, t1h, t1l, 128, Mdyn, DPROT, 1, 0, nullptr, nullptr, nullptr);
    gemm_bfA<<<dim3(1, TROWS / 128), 256, GM_SMEM, PS>>>(t1h, t1l, 128,
        whi + WOFF_B2, wlo + WOFF_B2, b2b, t, th, tl, 128, Mdyn, 128, 1);
    gemm_bfA<<<dim3(2, TROWS / 128), 256, GM_SMEM, PS>>>(th, tl, 128,
        whi + WOFF_WC, wlo + WOFF_WC, nullptr, tbw, nullptr, nullptr, 256, Mdyn, 128, 0);
    if (fork) cudaEventRecord(evJ, sB);

    // ---- main branch: GCN stack ----
    sgemm64<<<dim3(2, (N + 63) / 64), t16>>>(x, 78, gW1, xw, N, 128, 78, hA, deg, gb1);
    gcn_scatter4<<<((long)E * 32 + 255) / 256, 256>>>(src, dst, coef, xw, hA, E, 32);

    gemm_f32A<<<dim3(1, N / 128), 256, GM_SMEM>>>(hA, 128, nullptr,
        whi + WOFF_G2, wlo + WOFF_G2, nullptr, xw, nullptr, nullptr, 128, nullptr, 128, 0, 1, hB, deg, gb2);
    gcn_scatter4<<<((long)E * 32 + 255) / 256, 256>>>(src, dst, coef, xw, hB, E, 32);

    gemm_f32A<<<dim3(2, N / 128), 256, GM_SMEM>>>(hB, 128, nullptr,
        whi + WOFF_G3, wlo + WOFF_G3, nullptr, xw, nullptr, nullptr, 256, nullptr, 128, 0, 1, h3, deg, gb3);
    gcn_scatter4<<<((long)E * 64 + 255) / 256, 256>>>(src, dst, coef, xw, h3, E, 64);

    dense_build<<<(MD * 64 + 255) / 256, 256>>>(h3, counts, starts, dh, dl);
    gemm_bfA<<<dim3(8, MD / 128), 256, GM_SMEM>>>(dh, dl, 256,
        whi + WOFF_F1, wlo + WOFF_F1, fc1b, nullptr, fc1h, fc1l, 1024, nullptr, 256, 1);
    gemm_bfA<<<dim3(1, MD / 128), 256, GM_SMEM>>>(fc1h, fc1l, 1024,
        whi + WOFF_F2, wlo + WOFF_F2, fc2b, hd, nullptr, nullptr, 128, nullptr, 1024, 1);

    // ---- join, fused co-attention ----
    if (fork) cudaStreamWaitEvent(0, evJ, 0);
    coattn_fused<<<BGR, 256, SM_FLOATS * 4 + 1024>>>(tbw, t, hd, W_c, w_hc, w_hp, bslot, cp);

    // ---- final MLP ----
    gemm_f32A<<<dim3(8, 1), 256, GM_SMEM>>>(cp, 256, nullptr,
        whi + WOFF_C1, wlo + WOFF_C1, c1b, nullptr, f1h, f1l, 1024, nullptr, 256, 1, 0, nullptr, nullptr, nullptr);
    gemm_bfA<<<dim3(4, 1), 256, GM_SMEM>>>(f1h, f1l, 1024,
        whi + WOFF_C2, wlo + WOFF_C2, c2b, f2, nullptr, nullptr, 512, nullptr, 1024, 1);
    out_kernel<<<1, 128>>>(f2, oW, ob, (float*)d_out);
}

// round 15
// speedup vs baseline: 1.8190x; 1.1028x over previous
#include <cuda_runtime.h>
#include <cuda_bf16.h>
#include <math.h>
#include <stdint.h>

// ---------------- problem constants ----------------
#define NNODES 5120
#define NEDGES 20000
#define BGR    128
#define MAXN   45
#define LPROT  512
#define DPROT  1280
#define NPROT  229
#define TROWS  (BGR*LPROT)   // 65536
#define MD     (BGR*MAXN)    // 5760

typedef unsigned long long u64;

// ---------------- converted-weight pool (bf16 hi/lo, [n][k] k-major) ----------------
#define SZ_B1 (1280*128)
#define SZ_B2 (128*128)
#define SZ_WC (256*128)
#define SZ_G2 (128*128)
#define SZ_G3 (256*128)
#define SZ_F1 (1024*256)
#define SZ_F2 (128*1024)
#define SZ_C1 (1024*256)
#define SZ_C2 (512*1024)
#define WOFF_B1 0
#define WOFF_B2 (WOFF_B1+SZ_B1)
#define WOFF_WC (WOFF_B2+SZ_B2)
#define WOFF_G2 (WOFF_WC+SZ_WC)
#define WOFF_G3 (WOFF_G2+SZ_G2)
#define WOFF_F1 (WOFF_G3+SZ_G3)
#define WOFF_F2 (WOFF_F1+SZ_F1)
#define WOFF_C1 (WOFF_F2+SZ_F2)
#define WOFF_C2 (WOFF_C1+SZ_C1)
#define TOTALW  (WOFF_C2+SZ_C2)

// ---------------- device scratch ----------------
__device__ float g_deg[NNODES];
__device__ float g_coef[NEDGES];
__device__ float g_xw[NNODES*256];
__device__ float g_hA[NNODES*128];
__device__ float g_hB[NNODES*128];
__device__ float g_h3[NNODES*256];
__device__ int   g_counts[BGR];
__device__ int   g_starts[BGR];
__device__ float g_hd[MD*128];
__device__ int   g_rowmap[TROWS];
__device__ float g_t[TROWS*128];
__device__ float g_tbw[(long)TROWS*256];   // [tb | WptT | pad]
__device__ float g_cp[BGR*256];
__device__ float g_f2[BGR*512];
__device__ int g_Mdyn[1];
__device__ int g_bslot[BGR];
__device__ __nv_bfloat16 g_whi[TOTALW];
__device__ __nv_bfloat16 g_wlo[TOTALW];
// activation hi/lo chains
__device__ __nv_bfloat16 g_t1h[TROWS*128], g_t1l[TROWS*128];
__device__ __nv_bfloat16 g_th[TROWS*128],  g_tl[TROWS*128];
__device__ __nv_bfloat16 g_dh[MD*256],     g_dl[MD*256];
__device__ __nv_bfloat16 g_fc1h[(long)MD*1024], g_fc1l[(long)MD*1024];
__device__ __nv_bfloat16 g_f1h[BGR*1024],  g_f1l[BGR*1024];

// ---------------- helpers ----------------
__device__ __forceinline__ unsigned su32(const void* p) {
    unsigned r;
    asm("{ .reg .u64 t; cvta.to.shared.u64 t, %1; cvt.u32.u64 %0, t; }" : "=r"(r) : "l"(p));
    return r;
}
__device__ __forceinline__ void ldsm4(unsigned* r, unsigned addr) {
    asm volatile("ldmatrix.sync.aligned.m8n8.x4.shared.b16 {%0,%1,%2,%3}, [%4];"
        : "=r"(r[0]), "=r"(r[1]), "=r"(r[2]), "=r"(r[3]) : "r"(addr));
}
__device__ __forceinline__ void ldsm2(unsigned* r, unsigned addr) {
    asm volatile("ldmatrix.sync.aligned.m8n8.x2.shared.b16 {%0,%1}, [%2];"
        : "=r"(r[0]), "=r"(r[1]) : "r"(addr));
}
__device__ __forceinline__ void mma16816(float* d, const unsigned* a, const unsigned* b) {
    asm volatile("mma.sync.aligned.m16n8k16.row.col.f32.bf16.bf16.f32 "
        "{%0,%1,%2,%3}, {%4,%5,%6,%7}, {%8,%9}, {%0,%1,%2,%3};"
        : "+f"(d[0]), "+f"(d[1]), "+f"(d[2]), "+f"(d[3])
        : "r"(a[0]), "r"(a[1]), "r"(a[2]), "r"(a[3]), "r"(b[0]), "r"(b[1]));
}
__device__ __forceinline__ unsigned bfpack(float a, float b) {
    __nv_bfloat162 h = __floats2bfloat162_rn(a, b);
    return *(unsigned*)&h;
}
__device__ __forceinline__ void cp16(unsigned dst, const void* src) {
    asm volatile("cp.async.ca.shared.global [%0], [%1], 16;" :: "r"(dst), "l"(src));
}
__device__ __forceinline__ void cp_commit() { asm volatile("cp.async.commit_group;"); }
__device__ __forceinline__ void cp_waitall() { asm volatile("cp.async.wait_all;" ::: "memory"); }

// packed split store: v = (x,y) at even offset
__device__ __forceinline__ void split_store2(float2 v, __nv_bfloat16* hi, __nv_bfloat16* lo, long off) {
    __nv_bfloat162 h = __floats2bfloat162_rn(v.x, v.y);
    *(__nv_bfloat162*)&hi[off] = h;
    float lx = v.x - __bfloat162float(__low2bfloat16(h));
    float ly = v.y - __bfloat162float(__high2bfloat16(h));
    *(__nv_bfloat162*)&lo[off] = __floats2bfloat162_rn(lx, ly);
}

// ---------------- weight conversion: fp32 [K][N] -> bf16 hi/lo [N][K] ----------------
__global__ void convert_w(
    const float* __restrict__ b1W, const float* __restrict__ b2W,
    const float* __restrict__ Wb,  const float* __restrict__ Wp,
    const float* __restrict__ gW2, const float* __restrict__ gW3,
    const float* __restrict__ fc1W, const float* __restrict__ fc2W,
    const float* __restrict__ c1W, const float* __restrict__ c2W,
    __nv_bfloat16* __restrict__ hi, __nv_bfloat16* __restrict__ lo)
{
    int i = blockIdx.x * 256 + threadIdx.x;
    if (i >= TOTALW) return;
    float v;
    if (i < WOFF_B2)      { int j = i;           int n = j / 1280, k = j % 1280; v = b1W[k * 128 + n]; }
    else if (i < WOFF_WC) { int j = i - WOFF_B2; int n = j >> 7,  k = j & 127;  v = b2W[k * 128 + n]; }
    else if (i < WOFF_G2) { int j = i - WOFF_WC; int n = j >> 7,  k = j & 127;
                            v = (n < 128) ? Wb[k * 128 + n] : ((n < 160) ? Wp[(n - 128) * 128 + k] : 0.f); }
    else if (i < WOFF_G3) { int j = i - WOFF_G2; int n = j >> 7,  k = j & 127;  v = gW2[k * 128 + n]; }
    else if (i < WOFF_F1) { int j = i - WOFF_G3; int n = j >> 7,  k = j & 127;  v = gW3[k * 256 + n]; }
    else if (i < WOFF_F2) { int j = i - WOFF_F1; int n = j >> 8,  k = j & 255;  v = fc1W[k * 1024 + n]; }
    else if (i < WOFF_C1) { int j = i - WOFF_F2; int n = j >> 10, k = j & 1023; v = fc2W[k * 128 + n]; }
    else if (i < WOFF_C2) { int j = i - WOFF_C1; int n = j >> 8,  k = j & 255;  v = c1W[k * 1024 + n]; }
    else                  { int j = i - WOFF_C2; int n = j >> 10, k = j & 1023; v = c2W[k * 512 + n]; }
    __nv_bfloat16 h = __float2bfloat16_rn(v);
    hi[i] = h;
    lo[i] = __float2bfloat16_rn(v - __bfloat162float(h));
}

#define GSTRIDE 72
#define GTILEB (128 * GSTRIDE * 2)
#define GM_SMEM (4 * GTILEB)   // 73728 bytes

// =================================================================
// gemm_f32A: A fp32 (optional rowmap/preRelu), B pre-converted.
// 2 CTAs/SM via launch_bounds.
// =================================================================
__global__ __launch_bounds__(256, 2) void gemm_f32A(
    const float* __restrict__ A, int lda, const int* __restrict__ rowmap,
    const __nv_bfloat16* __restrict__ Bhi, const __nv_bfloat16* __restrict__ Blo,
    const float* __restrict__ bias,
    float* __restrict__ C, __nv_bfloat16* __restrict__ Chi, __nv_bfloat16* __restrict__ Clo,
    int ldc, const int* __restrict__ Mdyn,
    int K, int act, int preRelu,
    float* __restrict__ C2, const float* __restrict__ degv,
    const float* __restrict__ bias2)
{
    const int m0 = blockIdx.y * 128;
    if (Mdyn && m0 >= *Mdyn) return;
    const int col0 = blockIdx.x * 128;
    const int tid = threadIdx.x;
    const int wid = tid >> 5, lane = tid & 31;
    const int warp_m = (wid >> 2) * 64;
    const int warp_n = (wid & 3) * 32;

    extern __shared__ char smraw[];
    char* sAh = smraw;
    char* sAl = smraw + GTILEB;
    char* sBh = smraw + 2 * GTILEB;
    char* sBl = smraw + 3 * GTILEB;
    const unsigned uAh = su32(sAh), uAl = su32(sAl);
    const unsigned uBh = su32(sBh), uBl = su32(sBl);

    const float* arow[8];
    int amq[8];
    #pragma unroll
    for (int i = 0; i < 8; i++) {
        int idx = tid + i * 256;
        int m = idx >> 4;
        int q = (idx & 15) << 2;
        int gr = m0 + m;
        int ar = rowmap ? rowmap[gr] : gr;
        arow[i] = A + (long)ar * lda + q;
        amq[i] = (m * GSTRIDE + q) * 2;
    }
    const __nv_bfloat16* bsrc_h[4];
    const __nv_bfloat16* bsrc_l[4];
    unsigned bdst[4];
    #pragma unroll
    for (int i = 0; i < 4; i++) {
        int idx = tid + i * 256;
        int n = idx >> 3;
        int k8 = (idx & 7) << 3;
        bsrc_h[i] = Bhi + (long)(col0 + n) * K + k8;
        bsrc_l[i] = Blo + (long)(col0 + n) * K + k8;
        bdst[i] = (n * GSTRIDE + k8) * 2;
    }

    float d[4][4][4];
    #pragma unroll
    for (int i = 0; i < 4; i++)
        #pragma unroll
        for (int j = 0; j < 4; j++)
            #pragma unroll
            for (int r = 0; r < 4; r++) d[i][j][r] = 0.f;

    const int a_row = lane & 15, a_half = (lane >> 4) * 8;
    const int b_row = lane & 7,  b_half = ((lane >> 3) & 1) * 8;

    const int kc = K >> 6;
    for (int c = 0; c < kc; c++) {
        #pragma unroll
        for (int i = 0; i < 4; i++) {
            cp16(uBh + bdst[i], bsrc_h[i] + (c << 6));
            cp16(uBl + bdst[i], bsrc_l[i] + (c << 6));
        }
        #pragma unroll
        for (int i = 0; i < 8; i++) {
            float4 v = *(const float4*)(arow[i] + (c << 6));
            if (preRelu) {
                v.x = fmaxf(v.x, 0.f); v.y = fmaxf(v.y, 0.f);
                v.z = fmaxf(v.z, 0.f); v.w = fmaxf(v.w, 0.f);
            }
            __nv_bfloat16 h0 = __float2bfloat16_rn(v.x), h1 = __float2bfloat16_rn(v.y);
            __nv_bfloat16 h2 = __float2bfloat16_rn(v.z), h3 = __float2bfloat16_rn(v.w);
            float l0 = v.x - __bfloat162float(h0), l1 = v.y - __bfloat162float(h1);
            float l2 = v.z - __bfloat162float(h2), l3 = v.w - __bfloat162float(h3);
            unsigned hp0 = ((unsigned)__bfloat16_as_ushort(h0)) | ((unsigned)__bfloat16_as_ushort(h1) << 16);
            unsigned hp1 = ((unsigned)__bfloat16_as_ushort(h2)) | ((unsigned)__bfloat16_as_ushort(h3) << 16);
            *(uint2*)(sAh + amq[i]) = make_uint2(hp0, hp1);
            *(uint2*)(sAl + amq[i]) = make_uint2(bfpack(l0, l1), bfpack(l2, l3));
        }
        cp_waitall();
        __syncthreads();
        #pragma unroll
        for (int ks = 0; ks < 4; ks++) {
            const int kb = ks * 16;
            unsigned ah[4][4], al[4][4], bh[4][2], bl[4][2];
            #pragma unroll
            for (int mt = 0; mt < 4; mt++) {
                int off = ((warp_m + mt * 16 + a_row) * GSTRIDE + kb + a_half) * 2;
                ldsm4(ah[mt], uAh + off);
                ldsm4(al[mt], uAl + off);
            }
            #pragma unroll
            for (int nt = 0; nt < 4; nt++) {
                int off = ((warp_n + nt * 8 + b_row) * GSTRIDE + kb + b_half) * 2;
                ldsm2(bh[nt], uBh + off);
                ldsm2(bl[nt], uBl + off);
            }
            #pragma unroll
            for (int mt = 0; mt < 4; mt++)
                #pragma unroll
                for (int nt = 0; nt < 4; nt++) {
                    mma16816(d[mt][nt], ah[mt], bh[nt]);
                    mma16816(d[mt][nt], ah[mt], bl[nt]);
                    mma16816(d[mt][nt], al[mt], bh[nt]);
                }
        }
        __syncthreads();
    }

    const int r0 = lane >> 2;
    const int c0 = (lane & 3) * 2;
    #pragma unroll
    for (int mt = 0; mt < 4; mt++) {
        int gmA = m0 + warp_m + mt * 16 + r0;
        int gmB = gmA + 8;
        float dgA = 1.f, dgB = 1.f;
        if (C2) { dgA = degv[gmA]; dgB = degv[gmB]; }
        #pragma unroll
        for (int nt = 0; nt < 4; nt++) {
            int gn = col0 + warp_n + nt * 8 + c0;
            float2 vA = make_float2(d[mt][nt][0], d[mt][nt][1]);
            float2 vB = make_float2(d[mt][nt][2], d[mt][nt][3]);
            if (C2) {
                *(float2*)&C2[(long)gmA * ldc + gn] =
                    make_float2(vA.x / dgA + bias2[gn], vA.y / dgA + bias2[gn + 1]);
                *(float2*)&C2[(long)gmB * ldc + gn] =
                    make_float2(vB.x / dgB + bias2[gn], vB.y / dgB + bias2[gn + 1]);
            }
            if (bias) {
                float b0 = bias[gn], b1 = bias[gn + 1];
                vA.x += b0; vA.y += b1; vB.x += b0; vB.y += b1;
            }
            if (act == 1) {
                vA.x = fmaxf(vA.x, 0.f); vA.y = fmaxf(vA.y, 0.f);
                vB.x = fmaxf(vB.x, 0.f); vB.y = fmaxf(vB.y, 0.f);
            } else if (act == 2) {
                vA.x = tanhf(vA.x); vA.y = tanhf(vA.y);
                vB.x = tanhf(vB.x); vB.y = tanhf(vB.y);
            }
            if (C) {
                *(float2*)&C[(long)gmA * ldc + gn] = vA;
                *(float2*)&C[(long)gmB * ldc + gn] = vB;
            }
            if (Chi) {
                split_store2(vA, Chi, Clo, (long)gmA * ldc + gn);
                split_store2(vB, Chi, Clo, (long)gmB * ldc + gn);
            }
        }
    }
}

// =================================================================
// gemm_bfA: A pre-converted bf16 hi/lo; single-buffered, 2 CTAs/SM.
// =================================================================
__global__ __launch_bounds__(256, 2) void gemm_bfA(
    const __nv_bfloat16* __restrict__ Ahi, const __nv_bfloat16* __restrict__ Alo, int lda,
    const __nv_bfloat16* __restrict__ Bhi, const __nv_bfloat16* __restrict__ Blo,
    const float* __restrict__ bias,
    float* __restrict__ C, __nv_bfloat16* __restrict__ Chi, __nv_bfloat16* __restrict__ Clo,
    int ldc, const int* __restrict__ Mdyn, int K, int act)
{
    const int m0 = blockIdx.y * 128;
    if (Mdyn && m0 >= *Mdyn) return;
    const int col0 = blockIdx.x * 128;
    const int tid = threadIdx.x;
    const int wid = tid >> 5, lane = tid & 31;
    const int warp_m = (wid >> 2) * 64;
    const int warp_n = (wid & 3) * 32;

    extern __shared__ char smraw[];
    const unsigned uAh = su32(smraw);
    const unsigned uAl = uAh + GTILEB;
    const unsigned uBh = uAh + 2 * GTILEB;
    const unsigned uBl = uAh + 3 * GTILEB;

    const __nv_bfloat16 *ah_s[4], *al_s[4], *bh_s[4], *bl_s[4];
    unsigned doff[4];
    #pragma unroll
    for (int i = 0; i < 4; i++) {
        int idx = tid + i * 256;
        int r = idx >> 3;
        int k8 = (idx & 7) << 3;
        ah_s[i] = Ahi + (long)(m0 + r) * lda + k8;
        al_s[i] = Alo + (long)(m0 + r) * lda + k8;
        bh_s[i] = Bhi + (long)(col0 + r) * K + k8;
        bl_s[i] = Blo + (long)(col0 + r) * K + k8;
        doff[i] = (r * GSTRIDE + k8) * 2;
    }

    float d[4][4][4];
    #pragma unroll
    for (int i = 0; i < 4; i++)
        #pragma unroll
        for (int j = 0; j < 4; j++)
            #pragma unroll
            for (int r = 0; r < 4; r++) d[i][j][r] = 0.f;

    const int a_row = lane & 15, a_half = (lane >> 4) * 8;
    const int b_row = lane & 7,  b_half = ((lane >> 3) & 1) * 8;
    const int kc = K >> 6;

    for (int c = 0; c < kc; c++) {
        const int kof = c << 6;
        #pragma unroll
        for (int i = 0; i < 4; i++) {
            cp16(uAh + doff[i], ah_s[i] + kof);
            cp16(uAl + doff[i], al_s[i] + kof);
            cp16(uBh + doff[i], bh_s[i] + kof);
            cp16(uBl + doff[i], bl_s[i] + kof);
        }
        cp_commit();
        cp_waitall();
        __syncthreads();
        #pragma unroll
        for (int ks = 0; ks < 4; ks++) {
            const int kb = ks * 16;
            unsigned ah[4][4], al[4][4], bh[4][2], bl[4][2];
            #pragma unroll
            for (int mt = 0; mt < 4; mt++) {
                int off = ((warp_m + mt * 16 + a_row) * GSTRIDE + kb + a_half) * 2;
                ldsm4(ah[mt], uAh + off);
                ldsm4(al[mt], uAl + off);
            }
            #pragma unroll
            for (int nt = 0; nt < 4; nt++) {
                int off = ((warp_n + nt * 8 + b_row) * GSTRIDE + kb + b_half) * 2;
                ldsm2(bh[nt], uBh + off);
                ldsm2(bl[nt], uBl + off);
            }
            #pragma unroll
            for (int mt = 0; mt < 4; mt++)
                #pragma unroll
                for (int nt = 0; nt < 4; nt++) {
                    mma16816(d[mt][nt], ah[mt], bh[nt]);
                    mma16816(d[mt][nt], ah[mt], bl[nt]);
                    mma16816(d[mt][nt], al[mt], bh[nt]);
                }
        }
        __syncthreads();
    }

    const int r0 = lane >> 2;
    const int c0 = (lane & 3) * 2;
    #pragma unroll
    for (int mt = 0; mt < 4; mt++) {
        int gmA = m0 + warp_m + mt * 16 + r0;
        int gmB = gmA + 8;
        #pragma unroll
        for (int nt = 0; nt < 4; nt++) {
            int gn = col0 + warp_n + nt * 8 + c0;
            float2 vA = make_float2(d[mt][nt][0], d[mt][nt][1]);
            float2 vB = make_float2(d[mt][nt][2], d[mt][nt][3]);
            if (bias) {
                float b0 = bias[gn], b1 = bias[gn + 1];
                vA.x += b0; vA.y += b1; vB.x += b0; vB.y += b1;
            }
            if (act == 1) {
                vA.x = fmaxf(vA.x, 0.f); vA.y = fmaxf(vA.y, 0.f);
                vB.x = fmaxf(vB.x, 0.f); vB.y = fmaxf(vB.y, 0.f);
            } else if (act == 2) {
                vA.x = tanhf(vA.x); vA.y = tanhf(vA.y);
                vB.x = tanhf(vB.x); vB.y = tanhf(vB.y);
            }
            if (C) {
                *(float2*)&C[(long)gmA * ldc + gn] = vA;
                *(float2*)&C[(long)gmB * ldc + gn] = vB;
            }
            if (Chi) {
                split_store2(vA, Chi, Clo, (long)gmA * ldc + gn);
                split_store2(vB, Chi, Clo, (long)gmB * ldc + gn);
            }
        }
    }
}

// ---------------- generic SGEMM (GCN layer 1, K=78) ----------------
__global__ __launch_bounds__(256) void sgemm64(
    const float* __restrict__ A, int lda,
    const float* __restrict__ B, float* __restrict__ C,
    int M, int N, int K,
    float* __restrict__ C2, const float* __restrict__ degv,
    const float* __restrict__ bias2)
{
    __shared__ float As[16][64];
    __shared__ float Bs[16][68];
    const int tid = threadIdx.y * 16 + threadIdx.x;
    const int m0 = blockIdx.y * 64;
    const int n0 = blockIdx.x * 64;
    float acc[4][4] = {};
    for (int kt = 0; kt < K; kt += 16) {
        #pragma unroll
        for (int i = tid; i < 64 * 16; i += 256) {
            int m = i >> 4, kk = i & 15;
            int gm = m0 + m, gk = kt + kk;
            float v = 0.f;
            if (gm < M && gk < K) v = A[(long)gm * lda + gk];
            As[kk][m] = v;
        }
        #pragma unroll
        for (int i = tid; i < 16 * 64; i += 256) {
            int kk = i >> 6, n = i & 63;
            int gk = kt + kk, gn = n0 + n;
            Bs[kk][n] = (gk < K && gn < N) ? B[(long)gk * N + gn] : 0.f;
        }
        __syncthreads();
        #pragma unroll
        for (int kk = 0; kk < 16; kk++) {
            float a[4];
            #pragma unroll
            for (int i = 0; i < 4; i++) a[i] = As[kk][threadIdx.y * 4 + i];
            float4 b4 = *(const float4*)&Bs[kk][threadIdx.x * 4];
            float bv[4] = { b4.x, b4.y, b4.z, b4.w };
            #pragma unroll
            for (int i = 0; i < 4; i++)
                #pragma unroll
                for (int j = 0; j < 4; j++) acc[i][j] += a[i] * bv[j];
        }
        __syncthreads();
    }
    #pragma unroll
    for (int i = 0; i < 4; i++) {
        int gm = m0 + threadIdx.y * 4 + i;
        if (gm >= M) continue;
        #pragma unroll
        for (int j = 0; j < 4; j++) {
            int gn = n0 + threadIdx.x * 4 + j;
            if (gn >= N) continue;
            float v = acc[i][j];
            if (C2) C2[(long)gm * N + gn] = v / degv[gm] + bias2[gn];
            C[(long)gm * N + gn] = v;
        }
    }
}

// ---------------- prep_all ----------------
__global__ __launch_bounds__(1024) void prep_all(
    const int* __restrict__ tgt, const int* __restrict__ src,
    const int* __restrict__ dst, const int* __restrict__ batch,
    int n, int E,
    int* bslot, int* rowmap, int* Mdyn,
    float* deg, float* coef, int* counts, int* starts)
{
    __shared__ float sdeg[NNODES];
    __shared__ int flag[NPROT];
    __shared__ int slot[NPROT];
    __shared__ int uniq[BGR];
    __shared__ int cbin[BGR];
    __shared__ int nu_s;
    const int tid = threadIdx.x;

    for (int i = tid; i < n; i += 1024) sdeg[i] = 1.0f;
    if (tid < NPROT) flag[tid] = 0;
    if (tid < BGR) cbin[tid] = 0;
    __syncthreads();
    if (tid < BGR) flag[tgt[tid]] = 1;
    for (int e = tid; e < E; e += 1024) atomicAdd(&sdeg[dst[e]], 1.0f);
    for (int i = tid; i < n; i += 1024) atomicAdd(&cbin[batch[i]], 1);
    __syncthreads();
    if (tid == 0) {
        int s = 0;
        for (int p = 0; p < NPROT; p++) {
            if (flag[p]) { slot[p] = s; uniq[s] = p; s++; }
            else slot[p] = -1;
        }
        nu_s = s;
        Mdyn[0] = s * LPROT;
    } else if (tid == 32) {
        int s = 0;
        for (int b = 0; b < BGR; b++) { starts[b] = s; counts[b] = cbin[b]; s += cbin[b]; }
    }
    __syncthreads();
    if (tid < BGR) bslot[tid] = slot[tgt[tid]];
    for (int i = tid; i < n; i += 1024) deg[i] = sdeg[i];
    for (int e = tid; e < E; e += 1024)
        coef[e] = rsqrtf(sdeg[src[e]]) * rsqrtf(sdeg[dst[e]]);
    int nu = nu_s;
    for (int r = tid; r < TROWS; r += 1024) {
        int s = r >> 9;
        rowmap[r] = (s < nu) ? (uniq[s] * LPROT + (r & (LPROT - 1))) : 0;
    }
}

// ---------------- GCN scatter (float4) ----------------
__global__ void gcn_scatter4(const int* __restrict__ src, const int* __restrict__ dst,
                             const float* __restrict__ coef, const float* __restrict__ xw,
                             float* out, int E, int F4) {
    long i = (long)blockIdx.x * blockDim.x + threadIdx.x;
    if (i >= (long)E * F4) return;
    int e = (int)(i / F4);
    int f = (int)(i - (long)e * F4) * 4;
    float c = coef[e];
    int s = src[e], d = dst[e];
    const int F = F4 * 4;
    float4 v = *(const float4*)&xw[(long)s * F + f];
    float* o = &out[(long)d * F + f];
    atomicAdd(o + 0, v.x * c);
    atomicAdd(o + 1, v.y * c);
    atomicAdd(o + 2, v.z * c);
    atomicAdd(o + 3, v.w * c);
}

// ---------------- to_dense_batch gather -> bf16 hi/lo ----------------
__global__ void dense_build(const float* __restrict__ h3,
                            const int* __restrict__ counts,
                            const int* __restrict__ starts,
                            __nv_bfloat16* __restrict__ dh,
                            __nv_bfloat16* __restrict__ dl) {
    int i = blockIdx.x * blockDim.x + threadIdx.x;
    if (i >= MD * 64) return;
    int b = i / (MAXN * 64);
    int rem = i - b * (MAXN * 64);
    int pos = rem >> 6, f4 = rem & 63;
    float4 v = make_float4(0.f, 0.f, 0.f, 0.f);
    if (pos < counts[b]) {
        v = ((const float4*)(h3 + (long)(starts[b] + pos) * 256))[f4];
        v.x = fmaxf(v.x, 0.f); v.y = fmaxf(v.y, 0.f);
        v.z = fmaxf(v.z, 0.f); v.w = fmaxf(v.w, 0.f);
    }
    long off = (long)i * 4;
    split_store2(make_float2(v.x, v.y), dh, dl, off);
    split_store2(make_float2(v.z, v.w), dh, dl, off + 2);
}

// =================================================================
// FUSED CO-ATTENTION (WptT staged in smem)
// =================================================================
#define PHD 132
#define OFF_HD   0
#define OFF_WCX  (OFF_HD + 45*PHD)
#define OFF_C    (OFF_WCX + 32*48)
#define OFF_TB   (OFF_C + 64*48)
#define OFF_WPT  (OFF_TB + 64*PHD)
#define OFF_AP   (OFF_WPT + 64*32)
#define OFF_AC   (OFF_AP + 512)
#define OFF_RED  (OFF_AC + 48)
#define OFF_WC   (OFF_RED + 256)
#define OFF_WP   (OFF_WC + 32)
#define OFF_SCAL (OFF_WP + 32)
#define SM_FLOATS (OFF_SCAL + 4)

__global__ __launch_bounds__(256) void coattn_fused(
    const float* __restrict__ tbw, const float* __restrict__ t,
    const float* __restrict__ hd, const float* __restrict__ Wc_g,
    const float* __restrict__ whc, const float* __restrict__ whp,
    const int* __restrict__ bslot, float* __restrict__ cp)
{
    extern __shared__ float sm[];
    float* s_hd  = sm + OFF_HD;
    float* s_wcx = sm + OFF_WCX;
    float* s_C   = sm + OFF_C;
    float* s_tb  = sm + OFF_TB;
    float* s_wpt = sm + OFF_WPT;
    float* s_ap  = sm + OFF_AP;
    float* s_ac  = sm + OFF_AC;
    float* s_red = sm + OFF_RED;
    float* s_wc  = sm + OFF_WC;
    float* s_wp  = sm + OFF_WP;
    float* s_scal= sm + OFF_SCAL;

    const int b = blockIdx.x;
    const int tid = threadIdx.x;
    const long base = (long)bslot[b] * LPROT;
    const float* hd_b = hd + (long)b * MAXN * 128;

    for (int idx = tid; idx < MAXN * 32; idx += 256) {
        int s = idx >> 5, v4 = (idx & 31) * 4;
        *(float4*)&s_hd[s * PHD + v4] = *(const float4*)&hd_b[s * 128 + v4];
    }
    if (tid < 32) { s_wc[tid] = whc[tid]; s_wp[tid] = whp[tid]; }
    if (tid < 48) s_ac[tid] = 0.f;
    __syncthreads();

    for (int idx = tid; idx < 32 * MAXN; idx += 256) {
        int k = idx / MAXN, s = idx - k * MAXN;
        float acc = 0.f;
        #pragma unroll
        for (int kk = 0; kk < 32; kk++) {
            float4 a = *(const float4*)&Wc_g[k * 128 + kk * 4];
            float4 h4 = *(const float4*)&s_hd[s * PHD + kk * 4];
            acc += a.x * h4.x + a.y * h4.y + a.z * h4.z + a.w * h4.w;
        }
        s_wcx[k * 48 + s] = acc;
    }

    const int kt2 = (tid / 15) * 2;
    const int st3 = (tid % 15) * 3;
    float hc00 = 0.f, hc01 = 0.f, hc02 = 0.f, hc10 = 0.f, hc11 = 0.f, hc12 = 0.f;

    for (int cc = 0; cc < 8; cc++) {
        const int lbase = cc * 64;
        __syncthreads();
        for (int idx = tid; idx < 64 * 32; idx += 256) {
            int l = idx >> 5, v4 = (idx & 31) * 4;
            *(float4*)&s_tb[l * PHD + v4] =
                *(const float4*)&tbw[(base + lbase + l) * 256 + v4];
        }
        for (int idx = tid; idx < 64 * 8; idx += 256) {
            int l = idx >> 3, v4 = (idx & 7) * 4;
            *(float4*)&s_wpt[l * 32 + v4] =
                *(const float4*)&tbw[(base + lbase + l) * 256 + 128 + v4];
        }
        __syncthreads();
        if (tid < 240) {
            int lt = (tid / 15) * 4;
            float ca[4][3] = {};
            #pragma unroll 8
            for (int kk = 0; kk < 32; kk++) {
                float4 a0 = *(const float4*)&s_tb[(lt + 0) * PHD + kk * 4];
                float4 a1 = *(const float4*)&s_tb[(lt + 1) * PHD + kk * 4];
                float4 a2 = *(const float4*)&s_tb[(lt + 2) * PHD + kk * 4];
                float4 a3 = *(const float4*)&s_tb[(lt + 3) * PHD + kk * 4];
                float4 h0 = *(const float4*)&s_hd[(st3 + 0) * PHD + kk * 4];
                float4 h1 = *(const float4*)&s_hd[(st3 + 1) * PHD + kk * 4];
                float4 h2 = *(const float4*)&s_hd[(st3 + 2) * PHD + kk * 4];
                ca[0][0] += a0.x*h0.x + a0.y*h0.y + a0.z*h0.z + a0.w*h0.w;
                ca[0][1] += a0.x*h1.x + a0.y*h1.y + a0.z*h1.z + a0.w*h1.w;
                ca[0][2] += a0.x*h2.x + a0.y*h2.y + a0.z*h2.z + a0.w*h2.w;
                ca[1][0] += a1.x*h0.x + a1.y*h0.y + a1.z*h0.z + a1.w*h0.w;
                ca[1][1] += a1.x*h1.x + a1.y*h1.y + a1.z*h1.z + a1.w*h1.w;
                ca[1][2] += a1.x*h2.x + a1.y*h2.y + a1.z*h2.z + a1.w*h2.w;
                ca[2][0] += a2.x*h0.x + a2.y*h0.y + a2.z*h0.z + a2.w*h0.w;
                ca[2][1] += a2.x*h1.x + a2.y*h1.y + a2.z*h1.z + a2.w*h1.w;
                ca[2][2] += a2.x*h2.x + a2.y*h2.y + a2.z*h2.z + a2.w*h2.w;
                ca[3][0] += a3.x*h0.x + a3.y*h0.y + a3.z*h0.z + a3.w*h0.w;
                ca[3][1] += a3.x*h1.x + a3.y*h1.y + a3.z*h1.z + a3.w*h1.w;
                ca[3][2] += a3.x*h2.x + a3.y*h2.y + a3.z*h2.z + a3.w*h2.w;
            }
            #pragma unroll
            for (int i = 0; i < 4; i++)
                #pragma unroll
                for (int j = 0; j < 3; j++)
                    s_C[(lt + i) * 48 + st3 + j] = tanhf(ca[i][j]);
        }
        __syncthreads();
        if (tid < 240) {
            for (int l = 0; l < 64; l++) {
                float w0 = s_wpt[l * 32 + kt2], w1 = s_wpt[l * 32 + kt2 + 1];
                float c0 = s_C[l * 48 + st3];
                float c1 = s_C[l * 48 + st3 + 1];
                float c2 = s_C[l * 48 + st3 + 2];
                hc00 += w0 * c0; hc01 += w0 * c1; hc02 += w0 * c2;
                hc10 += w1 * c0; hc11 += w1 * c1; hc12 += w1 * c2;
            }
        }
        {
            int l = tid >> 2, q = tid & 3;
            float cl[45];
            #pragma unroll
            for (int s = 0; s < 45; s++) cl[s] = s_C[l * 48 + s];
            float part = 0.f;
            #pragma unroll
            for (int i = 0; i < 8; i++) {
                int k = q * 8 + i;
                float v = s_wpt[l * 32 + k];
                const float* wx = &s_wcx[k * 48];
                #pragma unroll
                for (int s = 0; s < 45; s++) v += wx[s] * cl[s];
                part += s_wp[k] * tanhf(v);
            }
            part += __shfl_down_sync(0xffffffffu, part, 2);
            part += __shfl_down_sync(0xffffffffu, part, 1);
            if (q == 0) s_ap[lbase + l] = part;
        }
    }
    __syncthreads();

    if (tid < 240) {
        float h;
        h = tanhf(s_wcx[kt2 * 48 + st3] + hc00);       atomicAdd(&s_ac[st3],     s_wc[kt2] * h);
        h = tanhf(s_wcx[kt2 * 48 + st3 + 1] + hc01);   atomicAdd(&s_ac[st3 + 1], s_wc[kt2] * h);
        h = tanhf(s_wcx[kt2 * 48 + st3 + 2] + hc02);   atomicAdd(&s_ac[st3 + 2], s_wc[kt2] * h);
        h = tanhf(s_wcx[(kt2+1) * 48 + st3] + hc10);     atomicAdd(&s_ac[st3],     s_wc[kt2+1] * h);
        h = tanhf(s_wcx[(kt2+1) * 48 + st3 + 1] + hc11); atomicAdd(&s_ac[st3 + 1], s_wc[kt2+1] * h);
        h = tanhf(s_wcx[(kt2+1) * 48 + st3 + 2] + hc12); atomicAdd(&s_ac[st3 + 2], s_wc[kt2+1] * h);
    }
    __syncthreads();

    float m1 = fmaxf(s_ap[tid], s_ap[tid + 256]);
    s_red[tid] = m1; __syncthreads();
    for (int o = 128; o > 0; o >>= 1) {
        if (tid < o) s_red[tid] = fmaxf(s_red[tid], s_red[tid + o]);
        __syncthreads();
    }
    float mx = s_red[0]; __syncthreads();
    float e1 = expf(s_ap[tid] - mx), e2 = expf(s_ap[tid + 256] - mx);
    s_ap[tid] = e1; s_ap[tid + 256] = e2;
    s_red[tid] = e1 + e2; __syncthreads();
    for (int o = 128; o > 0; o >>= 1) {
        if (tid < o) s_red[tid] += s_red[tid + o];
        __syncthreads();
    }
    if (tid == 0) s_scal[0] = 1.f / s_red[0];
    if (tid == 0) {
        float amx = -1e30f;
        for (int s = 0; s < MAXN; s++) amx = fmaxf(amx, s_ac[s]);
        float sum = 0.f;
        for (int s = 0; s < MAXN; s++) { float e = expf(s_ac[s] - amx); s_ac[s] = e; sum += e; }
        float inv = 1.f / sum;
        for (int s = 0; s < MAXN; s++) s_ac[s] *= inv;
    }
    __syncthreads();

    {
        int h = tid >> 7, m = tid & 127;
        float accp = 0.f;
        int l0 = h * 256;
        for (int l = 0; l < 256; l++)
            accp += s_ap[l0 + l] * t[(base + l0 + l) * 128 + m];
        s_red[tid] = accp;
        __syncthreads();
        if (h == 0) {
            float accc = 0.f;
            #pragma unroll
            for (int s = 0; s < MAXN; s++) accc += s_ac[s] * s_hd[s * PHD + m];
            cp[b * 256 + m] = accc;
            cp[b * 256 + 128 + m] = (s_red[m] + s_red[128 + m]) * s_scal[0];
        }
    }
}

// ---------------- final output ----------------
__global__ void out_kernel(const float* __restrict__ f2, const float* __restrict__ oW,
                           const float* __restrict__ ob, float* __restrict__ out) {
    int b = threadIdx.x;
    if (b < BGR) {
        float s = 0.f;
        for (int j = 0; j < 512; j += 4) {
            float4 a = *(const float4*)&f2[b * 512 + j];
            float4 w = *(const float4*)&oW[j];
            s += a.x * w.x + a.y * w.y + a.z * w.z + a.w * w.w;
        }
        out[b] = s + ob[0];
    }
}

// ---------------- host launcher ----------------
static float* sym_f(const void* s) { void* p = nullptr; cudaGetSymbolAddress(&p, s); return (float*)p; }
static int*   sym_i(const void* s) { void* p = nullptr; cudaGetSymbolAddress(&p, s); return (int*)p; }
static __nv_bfloat16* sym_b(const void* s) { void* p = nullptr; cudaGetSymbolAddress(&p, s); return (__nv_bfloat16*)p; }

extern "C" void kernel_launch(void* const* d_in, const int* in_sizes, int n_in,
                              void* d_out, int out_size)
{
    const float* x      = (const float*)d_in[0];
    const int*   ei     = (const int*)d_in[1];
    const int*   tgt    = (const int*)d_in[2];
    const int*   batch  = (const int*)d_in[3];
    const float* prot   = (const float*)d_in[4];
    const float* gW1 = (const float*)d_in[5],  *gb1 = (const float*)d_in[6];
    const float* gW2 = (const float*)d_in[7],  *gb2 = (const float*)d_in[8];
    const float* gW3 = (const float*)d_in[9],  *gb3 = (const float*)d_in[10];
    const float* fc1W = (const float*)d_in[11], *fc1b = (const float*)d_in[12];
    const float* fc2W = (const float*)d_in[13], *fc2b = (const float*)d_in[14];
    const float* b1W = (const float*)d_in[15],  *b1b = (const float*)d_in[16];
    const float* b2W = (const float*)d_in[17],  *b2b = (const float*)d_in[18];
    const float* W_b = (const float*)d_in[19];
    const float* W_c = (const float*)d_in[20];
    const float* W_p = (const float*)d_in[21];
    const float* w_hc = (const float*)d_in[22], *w_hp = (const float*)d_in[23];
    const float* c1W = (const float*)d_in[24], *c1b = (const float*)d_in[25];
    const float* c2W = (const float*)d_in[26], *c2b = (const float*)d_in[27];
    const float* oW  = (const float*)d_in[28], *ob  = (const float*)d_in[29];

    const int N = in_sizes[0] / 78;
    const int E = in_sizes[1] / 2;
    const int* src = ei;
    const int* dst = ei + E;

    float* deg   = sym_f(g_deg);
    float* coef  = sym_f(g_coef);
    float* xw    = sym_f(g_xw);
    float* hA    = sym_f(g_hA);
    float* hB    = sym_f(g_hB);
    float* h3    = sym_f(g_h3);
    int*   counts = sym_i(g_counts);
    int*   starts = sym_i(g_starts);
    float* hd    = sym_f(g_hd);
    int*   rowmap = sym_i(g_rowmap);
    float* t     = sym_f(g_t);
    float* tbw   = sym_f(g_tbw);
    float* cp    = sym_f(g_cp);
    float* f2    = sym_f(g_f2);
    int* Mdyn  = sym_i(g_Mdyn);
    int* bslot = sym_i(g_bslot);
    __nv_bfloat16* whi = sym_b(g_whi);
    __nv_bfloat16* wlo = sym_b(g_wlo);
    __nv_bfloat16* t1h = sym_b(g_t1h), *t1l = sym_b(g_t1l);
    __nv_bfloat16* th  = sym_b(g_th),  *tl  = sym_b(g_tl);
    __nv_bfloat16* dh  = sym_b(g_dh),  *dl  = sym_b(g_dl);
    __nv_bfloat16* fc1h = sym_b(g_fc1h), *fc1l = sym_b(g_fc1l);
    __nv_bfloat16* f1h = sym_b(g_f1h), *f1l = sym_b(g_f1l);

    static cudaStream_t sB = 0;
    static cudaEvent_t evF = 0, evJ = 0;
    static int tried = 0;
    if (!tried) {
        tried = 1;
        if (cudaStreamCreateWithFlags(&sB, cudaStreamNonBlocking) != cudaSuccess) sB = 0;
        if (sB) {
            if (cudaEventCreateWithFlags(&evF, cudaEventDisableTiming) != cudaSuccess ||
                cudaEventCreateWithFlags(&evJ, cudaEventDisableTiming) != cudaSuccess) {
                sB = 0;
            }
        }
        cudaFuncSetAttribute(coattn_fused, cudaFuncAttributeMaxDynamicSharedMemorySize,
                             SM_FLOATS * 4 + 1024);
        cudaFuncSetAttribute(gemm_f32A, cudaFuncAttributeMaxDynamicSharedMemorySize, GM_SMEM);
        cudaFuncSetAttribute(gemm_bfA, cudaFuncAttributeMaxDynamicSharedMemorySize, GM_SMEM);
    }
    const bool fork = (sB != 0);
    cudaStream_t PS = fork ? sB : (cudaStream_t)0;

    dim3 t16(16, 16);

    // ---- prep + weight conversion ----
    prep_all<<<1, 1024>>>(tgt, src, dst, batch, N, E,
                          bslot, rowmap, Mdyn, deg, coef, counts, starts);
    convert_w<<<(TOTALW + 255) / 256, 256>>>(b1W, b2W, W_b, W_p, gW2, gW3,
                                             fc1W, fc2W, c1W, c2W, whi, wlo);

    // ---- fork: protein branch ----
    if (fork) { cudaEventRecord(evF, 0); cudaStreamWaitEvent(sB, evF, 0); }
    gemm_f32A<<<dim3(1, TROWS / 128), 256, GM_SMEM, PS>>>(prot, DPROT, rowmap,
        whi + WOFF_B1, wlo + WOFF_B1, b1b, nullptr, t1h, t1l, 128, Mdyn, DPROT, 1, 0, nullptr, nullptr, nullptr);
    gemm_bfA<<<dim3(1, TROWS / 128), 256, GM_SMEM, PS>>>(t1h, t1l, 128,
        whi + WOFF_B2, wlo + WOFF_B2, b2b, t, th, tl, 128, Mdyn, 128, 1);
    gemm_bfA<<<dim3(2, TROWS / 128), 256, GM_SMEM, PS>>>(th, tl, 128,
        whi + WOFF_WC, wlo + WOFF_WC, nullptr, tbw, nullptr, nullptr, 256, Mdyn, 128, 0);
    if (fork) cudaEventRecord(evJ, sB);

    // ---- main branch: GCN stack ----
    sgemm64<<<dim3(2, (N + 63) / 64), t16>>>(x, 78, gW1, xw, N, 128, 78, hA, deg, gb1);
    gcn_scatter4<<<((long)E * 32 + 255) / 256, 256>>>(src, dst, coef, xw, hA, E, 32);

    gemm_f32A<<<dim3(1, N / 128), 256, GM_SMEM>>>(hA, 128, nullptr,
        whi + WOFF_G2, wlo + WOFF_G2, nullptr, xw, nullptr, nullptr, 128, nullptr, 128, 0, 1, hB, deg, gb2);
    gcn_scatter4<<<((long)E * 32 + 255) / 256, 256>>>(src, dst, coef, xw, hB, E, 32);

    gemm_f32A<<<dim3(2, N / 128), 256, GM_SMEM>>>(hB, 128, nullptr,
        whi + WOFF_G3, wlo + WOFF_G3, nullptr, xw, nullptr, nullptr, 256, nullptr, 128, 0, 1, h3, deg, gb3);
    gcn_scatter4<<<((long)E * 64 + 255) / 256, 256>>>(src, dst, coef, xw, h3, E, 64);

    dense_build<<<(MD * 64 + 255) / 256, 256>>>(h3, counts, starts, dh, dl);
    gemm_bfA<<<dim3(8, MD / 128), 256, GM_SMEM>>>(dh, dl, 256,
        whi + WOFF_F1, wlo + WOFF_F1, fc1b, nullptr, fc1h, fc1l, 1024, nullptr, 256, 1);
    gemm_bfA<<<dim3(1, MD / 128), 256, GM_SMEM>>>(fc1h, fc1l, 1024,
        whi + WOFF_F2, wlo + WOFF_F2, fc2b, hd, nullptr, nullptr, 128, nullptr, 1024, 1);

    // ---- join, fused co-attention ----
    if (fork) cudaStreamWaitEvent(0, evJ, 0);
    coattn_fused<<<BGR, 256, SM_FLOATS * 4 + 1024>>>(tbw, t, hd, W_c, w_hc, w_hp, bslot, cp);

    // ---- final MLP ----
    gemm_f32A<<<dim3(8, 1), 256, GM_SMEM>>>(cp, 256, nullptr,
        whi + WOFF_C1, wlo + WOFF_C1, c1b, nullptr, f1h, f1l, 1024, nullptr, 256, 1, 0, nullptr, nullptr, nullptr);
    gemm_bfA<<<dim3(4, 1), 256, GM_SMEM>>>(f1h, f1l, 1024,
        whi + WOFF_C2, wlo + WOFF_C2, c2b, f2, nullptr, nullptr, 512, nullptr, 1024, 1);
    out_kernel<<<1, 128>>>(f2, oW, ob, (float*)d_out);
}